// round 6
// baseline (speedup 1.0000x reference)
#include <cuda_runtime.h>
#include <cuda_bf16.h>
#include <math.h>
#include <stdint.h>

// ---------------- problem constants ----------------
#define L_SEQ   4096
#define IDIM    2048
#define NHEADS  8
#define NGROUPS 2
#define HDIM    256
#define ROPED   64
#define ODIM    (NHEADS*HDIM)     // 2048
#define NKV     (NGROUPS*HDIM)    // 512
#define QSCALE  0.0625f           // 256^-0.5

// ---------------- warp-MMA helpers (standard PTX, sm_80+) ----------------
__device__ __forceinline__ void ldsm_x4(uint32_t* r, uint32_t addr) {
    asm volatile("ldmatrix.sync.aligned.m8n8.x4.shared.b16 {%0,%1,%2,%3}, [%4];"
        : "=r"(r[0]), "=r"(r[1]), "=r"(r[2]), "=r"(r[3]) : "r"(addr));
}
__device__ __forceinline__ void ldsm_x4_trans(uint32_t* r, uint32_t addr) {
    asm volatile("ldmatrix.sync.aligned.m8n8.x4.trans.shared.b16 {%0,%1,%2,%3}, [%4];"
        : "=r"(r[0]), "=r"(r[1]), "=r"(r[2]), "=r"(r[3]) : "r"(addr));
}
__device__ __forceinline__ void mma16816(float* d, const uint32_t* a, uint32_t b0, uint32_t b1) {
    asm volatile("mma.sync.aligned.m16n8k16.row.col.f32.bf16.bf16.f32 "
        "{%0,%1,%2,%3}, {%4,%5,%6,%7}, {%8,%9}, {%0,%1,%2,%3};"
        : "+f"(d[0]), "+f"(d[1]), "+f"(d[2]), "+f"(d[3])
        : "r"(a[0]), "r"(a[1]), "r"(a[2]), "r"(a[3]), "r"(b0), "r"(b1));
}
__device__ __forceinline__ void cp_async16(uint32_t dst, const void* src) {
    asm volatile("cp.async.cg.shared.global [%0], [%1], 16;" :: "r"(dst), "l"(src));
}
#define CP_COMMIT() asm volatile("cp.async.commit_group;" ::: "memory")
#define CP_WAIT1()  asm volatile("cp.async.wait_group 1;" ::: "memory")
#define CP_WAIT0()  asm volatile("cp.async.wait_group 0;" ::: "memory")

__device__ __forceinline__ uint32_t smem_to_u32(const void* p) {
    uint32_t a;
    asm("{ .reg .u64 t; cvta.to.shared.u64 t, %1; cvt.u32.u64 %0, t; }" : "=r"(a) : "l"(p));
    return a;
}
__device__ __forceinline__ uint32_t pack_bf16x2(__nv_bfloat16 a, __nv_bfloat16 b) {
    __nv_bfloat162 t{a, b};
    return *reinterpret_cast<uint32_t*>(&t);
}

// ---------------- scratch (device globals) ----------------
__device__ float g_qraw [(size_t)L_SEQ * (ODIM*2)];
__device__ float g_gate [(size_t)L_SEQ * ODIM];
__device__ float g_kvraw[(size_t)L_SEQ * 1024];     // cols 0-511 = K, 512-1023 = V

// bf16 hi/lo operands
__device__ __nv_bfloat16 g_xh  [(size_t)L_SEQ * IDIM];
__device__ __nv_bfloat16 g_xl  [(size_t)L_SEQ * IDIM];
__device__ __nv_bfloat16 g_wqh [(size_t)(ODIM*2) * IDIM];
__device__ __nv_bfloat16 g_wql [(size_t)(ODIM*2) * IDIM];
__device__ __nv_bfloat16 g_wkvh[(size_t)1024 * IDIM];   // rows 0-511 wk^T, 512-1023 wv^T
__device__ __nv_bfloat16 g_wkvl[(size_t)1024 * IDIM];
__device__ __nv_bfloat16 g_woh [(size_t)IDIM * ODIM];
__device__ __nv_bfloat16 g_wol [(size_t)IDIM * ODIM];
__device__ __nv_bfloat16 g_ath [(size_t)L_SEQ * ODIM];
__device__ __nv_bfloat16 g_atl [(size_t)L_SEQ * ODIM];
// attention operands
__device__ __nv_bfloat16 g_qh [(size_t)L_SEQ * ODIM];
__device__ __nv_bfloat16 g_ql [(size_t)L_SEQ * ODIM];
__device__ __nv_bfloat16 g_kh [(size_t)L_SEQ * NKV];
__device__ __nv_bfloat16 g_kl [(size_t)L_SEQ * NKV];
__device__ __nv_bfloat16 g_vh [(size_t)L_SEQ * NKV];
__device__ __nv_bfloat16 g_vl [(size_t)L_SEQ * NKV];

// ---------------- split kernel: fp32 -> (hi, lo) bf16 ----------------
__global__ __launch_bounds__(256) void split_kernel(
    const float* __restrict__ in, __nv_bfloat16* __restrict__ hi,
    __nv_bfloat16* __restrict__ lo, size_t n4)
{
    size_t i = (size_t)blockIdx.x * blockDim.x + threadIdx.x;
    size_t stride = (size_t)gridDim.x * blockDim.x;
    for (; i < n4; i += stride) {
        float4 v = reinterpret_cast<const float4*>(in)[i];
        __nv_bfloat16 h0 = __float2bfloat16(v.x), h1 = __float2bfloat16(v.y);
        __nv_bfloat16 h2 = __float2bfloat16(v.z), h3 = __float2bfloat16(v.w);
        __nv_bfloat16 l0 = __float2bfloat16(v.x - __bfloat162float(h0));
        __nv_bfloat16 l1 = __float2bfloat16(v.y - __bfloat162float(h1));
        __nv_bfloat16 l2 = __float2bfloat16(v.z - __bfloat162float(h2));
        __nv_bfloat16 l3 = __float2bfloat16(v.w - __bfloat162float(h3));
        __nv_bfloat162 hp0{h0, h1}, hp1{h2, h3}, lp0{l0, l1}, lp1{l2, l3};
        reinterpret_cast<__nv_bfloat162*>(hi)[i*2]   = hp0;
        reinterpret_cast<__nv_bfloat162*>(hi)[i*2+1] = hp1;
        reinterpret_cast<__nv_bfloat162*>(lo)[i*2]   = lp0;
        reinterpret_cast<__nv_bfloat162*>(lo)[i*2+1] = lp1;
    }
}

// ---------------- transpose + split: W[K][N] fp32 -> Wt hi/lo [N][K] bf16 ----------------
__global__ __launch_bounds__(256) void transpose_split_kernel(
    const float* __restrict__ W, __nv_bfloat16* __restrict__ Th,
    __nv_bfloat16* __restrict__ Tl, int Kdim, int Ndim)
{
    __shared__ float tile[32][33];
    int n0 = blockIdx.x * 32;
    int k0 = blockIdx.y * 32;
    int tx = threadIdx.x & 31;
    int ty = threadIdx.x >> 5;
#pragma unroll
    for (int r = 0; r < 4; r++)
        tile[ty + 8*r][tx] = W[(size_t)(k0 + ty + 8*r) * Ndim + n0 + tx];
    __syncthreads();
#pragma unroll
    for (int r = 0; r < 4; r++) {
        float v = tile[tx][ty + 8*r];
        __nv_bfloat16 h = __float2bfloat16(v);
        __nv_bfloat16 l = __float2bfloat16(v - __bfloat162float(h));
        size_t o = (size_t)(n0 + ty + 8*r) * Kdim + k0 + tx;
        Th[o] = h; Tl[o] = l;
    }
}

// ---------------- warp-mma split-bf16 GEMM v2 ----------------
// C[M x N] fp32 = A[M x 2048] @ Bt[N x 2048]^T via Ah·Bh + Ah·Bl + Al·Bh
// block 256x128, 8 warps (4M x 2N), warp tile 64x64, BK=32, 3-stage cp.async.
#define GBK 32
#define NCHUNK (IDIM / GBK)            // 64
#define RS 80                          // padded row stride bytes for 32 bf16
#define G_AH 0
#define G_AL (256 * RS)                // 20480
#define G_BH (G_AL + 256 * RS)         // 40960
#define G_BL (G_BH + 128 * RS)         // 51200
#define G_STAGE (G_BL + 128 * RS)      // 61440
#define GEMM_SMEM (3 * G_STAGE)        // 184320

__global__ __launch_bounds__(256, 1) void mma_gemm(
    const __nv_bfloat16* __restrict__ Ah, const __nv_bfloat16* __restrict__ Al,
    const __nv_bfloat16* __restrict__ Bh, const __nv_bfloat16* __restrict__ Bl,
    float* __restrict__ C, int N)
{
    extern __shared__ char smem[];
    const uint32_t sb = smem_to_u32(smem);

    const int tid  = threadIdx.x;
    const int lane = tid & 31;
    const int wid  = tid >> 5;
    const int wm   = wid >> 1;         // 0..3
    const int wn   = wid & 1;          // 0..1
    const int m0   = blockIdx.y * 256;
    const int n0   = blockIdx.x * 128;

    const int lrow = tid >> 2;         // 0..63 row sub-index
    const int lcol = tid & 3;          // 16B column

    auto issue_stage = [&](int chunk) {
        const uint32_t s0 = sb + (chunk % 3) * G_STAGE;
        const int k0 = chunk * GBK;
#pragma unroll
        for (int j = 0; j < 12; j++) {
            int row, moff; const __nv_bfloat16* gp;
            if (j < 4)       { row = lrow + j * 64;       moff = G_AH; gp = Ah + (size_t)(m0 + row) * IDIM; }
            else if (j < 8)  { row = lrow + (j - 4) * 64; moff = G_AL; gp = Al + (size_t)(m0 + row) * IDIM; }
            else if (j < 10) { row = lrow + (j - 8) * 64; moff = G_BH; gp = Bh + (size_t)(n0 + row) * IDIM; }
            else             { row = lrow + (j - 10) * 64; moff = G_BL; gp = Bl + (size_t)(n0 + row) * IDIM; }
            cp_async16(s0 + moff + row * RS + lcol * 16, gp + k0 + lcol * 8);
        }
    };

    float acc[4][8][4];
#pragma unroll
    for (int mi = 0; mi < 4; mi++)
#pragma unroll
        for (int ni = 0; ni < 8; ni++)
#pragma unroll
            for (int r = 0; r < 4; r++) acc[mi][ni][r] = 0.0f;

    const uint32_t colb = (lane >> 4) * 16;
    const int l15 = lane & 15;

    issue_stage(0); CP_COMMIT();
    issue_stage(1); CP_COMMIT();

    for (int i = 0; i < NCHUNK; i++) {
        CP_WAIT1();
        __syncthreads();
        if (i + 2 < NCHUNK) issue_stage(i + 2);
        CP_COMMIT();                    // commit every iter (possibly empty) -> uniform wait

        const uint32_t s0  = sb + (i % 3) * G_STAGE;
        const uint32_t sAh = s0 + G_AH;
        const uint32_t sAl = s0 + G_AL;
        const uint32_t sBh = s0 + G_BH;
        const uint32_t sBl = s0 + G_BL;

#pragma unroll
        for (int ks = 0; ks < 2; ks++) {
            const uint32_t kb = ks * 32 + colb;
            uint32_t bh[4][4], bl[4][4];
#pragma unroll
            for (int nt = 0; nt < 4; nt++) {
                uint32_t ro = (wn * 64 + nt * 16 + l15) * RS + kb;
                ldsm_x4(bh[nt], sBh + ro);
                ldsm_x4(bl[nt], sBl + ro);
            }
#pragma unroll
            for (int mi = 0; mi < 4; mi++) {
                uint32_t ah[4], al[4];
                uint32_t ao = (wm * 64 + mi * 16 + l15) * RS + kb;
                ldsm_x4(ah, sAh + ao);
                ldsm_x4(al, sAl + ao);
#pragma unroll
                for (int ni = 0; ni < 8; ni++) {
                    const int nt = ni >> 1, sub = ni & 1;
                    float* d = acc[mi][ni];
                    mma16816(d, ah, bh[nt][sub], bh[nt][2 + sub]);
                    mma16816(d, ah, bl[nt][sub], bl[nt][2 + sub]);
                    mma16816(d, al, bh[nt][sub], bh[nt][2 + sub]);
                }
            }
        }
        __syncthreads();
    }

    const int er = lane >> 2;
    const int ec = (lane & 3) * 2;
#pragma unroll
    for (int mi = 0; mi < 4; mi++) {
#pragma unroll
        for (int ni = 0; ni < 8; ni++) {
            int row = m0 + wm * 64 + mi * 16 + er;
            int col = n0 + wn * 64 + ni * 8 + ec;
            *reinterpret_cast<float2*>(&C[(size_t)row * N + col]) =
                make_float2(acc[mi][ni][0], acc[mi][ni][1]);
            *reinterpret_cast<float2*>(&C[(size_t)(row + 8) * N + col]) =
                make_float2(acc[mi][ni][2], acc[mi][ni][3]);
        }
    }
}

// ---------------- RMSNorm + RoPE for Q -> bf16 hi/lo (pre-scaled) + gate ----------------
__global__ __launch_bounds__(256) void qnorm_rope_kernel(
    const float* __restrict__ cosb, const float* __restrict__ sinb,
    const float* __restrict__ gamma)
{
    const int l = blockIdx.x;
    const int h = blockIdx.y;
    const int d = threadIdx.x;
    const float* row = g_qraw + (size_t)l * (ODIM * 2) + h * 512;
    float v  = row[d];
    float gv = row[256 + d];

    float s = v * v;
#pragma unroll
    for (int o = 16; o > 0; o >>= 1) s += __shfl_xor_sync(0xffffffffu, s, o);
    __shared__ float wsum[8];
    __shared__ float sh[256];
    if ((d & 31) == 0) wsum[d >> 5] = s;
    __syncthreads();
    float tot = 0.0f;
#pragma unroll
    for (int w = 0; w < 8; w++) tot += wsum[w];
    float rstd = rsqrtf(tot * (1.0f / 256.0f) + 1e-6f);
    float y = v * rstd * gamma[d];
    sh[d] = y;
    __syncthreads();
    float out = y;
    if (d < ROPED) {
        float rot = (d < ROPED / 2) ? -sh[d + ROPED / 2] : sh[d - ROPED / 2];
        out = y * cosb[(size_t)l * ROPED + d] + rot * sinb[(size_t)l * ROPED + d];
    }
    float q = out * QSCALE;
    __nv_bfloat16 qh = __float2bfloat16(q);
    __nv_bfloat16 ql = __float2bfloat16(q - __bfloat162float(qh));
    size_t o = (size_t)l * ODIM + h * HDIM + d;
    g_qh[o] = qh; g_ql[o] = ql;
    g_gate[o] = gv;
}

// ---------------- RMSNorm + RoPE for K -> bf16 hi/lo (reads fused KV buffer) ----------------
__global__ __launch_bounds__(256) void knorm_rope_kernel(
    const float* __restrict__ cosb, const float* __restrict__ sinb,
    const float* __restrict__ gamma)
{
    const int l = blockIdx.x;
    const int g = blockIdx.y;
    const int d = threadIdx.x;
    float v = g_kvraw[(size_t)l * 1024 + g * HDIM + d];

    float s = v * v;
#pragma unroll
    for (int o = 16; o > 0; o >>= 1) s += __shfl_xor_sync(0xffffffffu, s, o);
    __shared__ float wsum[8];
    __shared__ float sh[256];
    if ((d & 31) == 0) wsum[d >> 5] = s;
    __syncthreads();
    float tot = 0.0f;
#pragma unroll
    for (int w = 0; w < 8; w++) tot += wsum[w];
    float rstd = rsqrtf(tot * (1.0f / 256.0f) + 1e-6f);
    float y = v * rstd * gamma[d];
    sh[d] = y;
    __syncthreads();
    float out = y;
    if (d < ROPED) {
        float rot = (d < ROPED / 2) ? -sh[d + ROPED / 2] : sh[d - ROPED / 2];
        out = y * cosb[(size_t)l * ROPED + d] + rot * sinb[(size_t)l * ROPED + d];
    }
    __nv_bfloat16 kh = __float2bfloat16(out);
    __nv_bfloat16 kl = __float2bfloat16(out - __bfloat162float(kh));
    size_t o = (size_t)l * NKV + g * HDIM + d;
    g_kh[o] = kh; g_kl[o] = kl;
}

// ---------------- V split from fused KV buffer ----------------
__global__ __launch_bounds__(256) void vsplit_kernel()
{
    const int l = blockIdx.x;
    const int g = blockIdx.y;
    const int d = threadIdx.x;
    float v = g_kvraw[(size_t)l * 1024 + 512 + g * HDIM + d];
    __nv_bfloat16 vh = __float2bfloat16(v);
    __nv_bfloat16 vl = __float2bfloat16(v - __bfloat162float(vh));
    size_t o = (size_t)l * NKV + g * HDIM + d;
    g_vh[o] = vh; g_vl[o] = vl;
}

// ---------------- MMA flash attention (split-bf16), BR=BC=64, D=256 ----------------
#define AQH 0
#define AQL 32768
#define AKH 65536
#define AKL 98304
#define AVH 131072
#define AVL 163840
#define ASS 196608
#define SSS 68
#define APH (ASS + 64*SSS*4)
#define APL (APH + 8192)
#define AMR (APL + 8192)
#define ALR (AMR + 256)
#define ACR (ALR + 256)
#define ATT_SMEM (ACR + 256)

__device__ __forceinline__ uint32_t sw512(int row, int g) {
    return (uint32_t)(row * 512 + ((g ^ (row & 7)) << 4));
}
__device__ __forceinline__ uint32_t sw128(int row, int g) {
    return (uint32_t)(row * 128 + ((g ^ (row & 7)) << 4));
}

__global__ __launch_bounds__(256, 1) void attn_mma_kernel()
{
    extern __shared__ char sm[];
    const uint32_t sb = smem_to_u32(sm);
    const int tid  = threadIdx.x;
    const int lane = tid & 31;
    const int wid  = tid >> 5;
    const int qt   = gridDim.x - 1 - blockIdx.x;
    const int h    = blockIdx.y;
    const int g    = h >> 2;
    const int i0   = qt * 64;

    float* Ss   = reinterpret_cast<float*>(sm + ASS);
    float* mrow = reinterpret_cast<float*>(sm + AMR);
    float* lrow = reinterpret_cast<float*>(sm + ALR);
    float* crow = reinterpret_cast<float*>(sm + ACR);

    {
        const char* qh = (const char*)(g_qh + ((size_t)i0 * NHEADS + h) * HDIM);
        const char* ql = (const char*)(g_ql + ((size_t)i0 * NHEADS + h) * HDIM);
        const size_t rstr = (size_t)NHEADS * HDIM * 2;
#pragma unroll
        for (int i = 0; i < 8; i++) {
            int idx = tid + 256 * i;
            int row = idx >> 5, gr = idx & 31;
            uint32_t so = sw512(row, gr);
            cp_async16(sb + AQH + so, qh + (size_t)row * rstr + gr * 16);
            cp_async16(sb + AQL + so, ql + (size_t)row * rstr + gr * 16);
        }
    }
    CP_COMMIT();
    if (tid < 64) { mrow[tid] = -INFINITY; lrow[tid] = 0.0f; }

    const int wm = wid & 3;
    const int wn = wid >> 2;
    const int er = lane >> 2;
    const int ec = (lane & 3) * 2;
    const int kgl = lane >> 4;

    float oacc[16][4];
#pragma unroll
    for (int t = 0; t < 16; t++)
#pragma unroll
        for (int r = 0; r < 4; r++) oacc[t][r] = 0.0f;

    CP_WAIT0();
    __syncthreads();

    for (int j0 = 0; j0 <= i0; j0 += 64) {
        {
            const size_t rbase = ((size_t)j0 * NGROUPS + g) * HDIM;
            const size_t rstr  = (size_t)NGROUPS * HDIM;
#pragma unroll
            for (int i = 0; i < 8; i++) {
                int idx = tid + 256 * i;
                int row = idx >> 5, gr = idx & 31;
                size_t go = (rbase + (size_t)row * rstr) * 2 + gr * 16;
                uint32_t so = sw512(row, gr);
                cp_async16(sb + AKH + so, (const char*)g_kh + go);
                cp_async16(sb + AKL + so, (const char*)g_kl + go);
                cp_async16(sb + AVH + so, (const char*)g_vh + go);
                cp_async16(sb + AVL + so, (const char*)g_vl + go);
            }
        }
        CP_COMMIT(); CP_WAIT0();
        __syncthreads();

        float sacc[4][4];
#pragma unroll
        for (int t = 0; t < 4; t++)
#pragma unroll
            for (int r = 0; r < 4; r++) sacc[t][r] = 0.0f;

        const int arow  = wm * 16 + (lane & 15);
        const int brow0 = wn * 32 + (lane & 15);
#pragma unroll 4
        for (int ks = 0; ks < 16; ks++) {
            int kg = ks * 2 + kgl;
            uint32_t ah[4], al[4], bh[2][4], bl[2][4];
            uint32_t ao = sw512(arow, kg);
            ldsm_x4(ah, sb + AQH + ao);
            ldsm_x4(al, sb + AQL + ao);
            uint32_t bo0 = sw512(brow0, kg);
            uint32_t bo1 = sw512(brow0 + 16, kg);
            ldsm_x4(bh[0], sb + AKH + bo0);
            ldsm_x4(bh[1], sb + AKH + bo1);
            ldsm_x4(bl[0], sb + AKL + bo0);
            ldsm_x4(bl[1], sb + AKL + bo1);
#pragma unroll
            for (int nt = 0; nt < 2; nt++)
#pragma unroll
                for (int sub = 0; sub < 2; sub++) {
                    float* d = sacc[nt * 2 + sub];
                    mma16816(d, ah, bh[nt][sub], bh[nt][2 + sub]);
                    mma16816(d, ah, bl[nt][sub], bl[nt][2 + sub]);
                    mma16816(d, al, bh[nt][sub], bh[nt][2 + sub]);
                }
        }
#pragma unroll
        for (int t = 0; t < 4; t++) {
            int col = wn * 32 + (t >> 1) * 16 + (t & 1) * 8 + ec;
            int r0 = wm * 16 + er;
            Ss[r0 * SSS + col]           = sacc[t][0];
            Ss[r0 * SSS + col + 1]       = sacc[t][1];
            Ss[(r0 + 8) * SSS + col]     = sacc[t][2];
            Ss[(r0 + 8) * SSS + col + 1] = sacc[t][3];
        }
        __syncthreads();

        {
            const int row  = tid >> 2;
            const int part = tid & 3;
            int vlim = i0 + row - j0 + 1; if (vlim > 64) vlim = 64;
            float sv[16];
            float mx = -INFINITY;
            const float* srow = &Ss[row * SSS + part * 16];
#pragma unroll
            for (int c = 0; c < 16; c++) {
                int cc = part * 16 + c;
                float v = (cc < vlim) ? srow[c] : -INFINITY;
                sv[c] = v; mx = fmaxf(mx, v);
            }
            mx = fmaxf(mx, __shfl_xor_sync(0xffffffffu, mx, 1));
            mx = fmaxf(mx, __shfl_xor_sync(0xffffffffu, mx, 2));
            float mold = mrow[row];
            float mnew = fmaxf(mold, mx);
            float ls = 0.0f;
#pragma unroll
            for (int c = 0; c < 16; c++) {
                float p = __expf(sv[c] - mnew);
                sv[c] = p; ls += p;
            }
            ls += __shfl_xor_sync(0xffffffffu, ls, 1);
            ls += __shfl_xor_sync(0xffffffffu, ls, 2);
            float corr = __expf(mold - mnew);
            if (part == 0) {
                mrow[row] = mnew;
                lrow[row] = lrow[row] * corr + ls;
                crow[row] = corr;
            }
#pragma unroll
            for (int gs = 0; gs < 2; gs++) {
                uint32_t hw[4], lw[4];
#pragma unroll
                for (int q = 0; q < 4; q++) {
                    float p0 = sv[gs * 8 + q * 2], p1 = sv[gs * 8 + q * 2 + 1];
                    __nv_bfloat16 h0 = __float2bfloat16(p0);
                    __nv_bfloat16 h1 = __float2bfloat16(p1);
                    __nv_bfloat16 l0 = __float2bfloat16(p0 - __bfloat162float(h0));
                    __nv_bfloat16 l1 = __float2bfloat16(p1 - __bfloat162float(h1));
                    hw[q] = pack_bf16x2(h0, h1);
                    lw[q] = pack_bf16x2(l0, l1);
                }
                uint32_t off = sw128(row, part * 2 + gs);
                *reinterpret_cast<uint4*>(sm + APH + off) = make_uint4(hw[0], hw[1], hw[2], hw[3]);
                *reinterpret_cast<uint4*>(sm + APL + off) = make_uint4(lw[0], lw[1], lw[2], lw[3]);
            }
        }
        __syncthreads();

        {
            float c0 = crow[wm * 16 + er];
            float c1 = crow[wm * 16 + er + 8];
#pragma unroll
            for (int t = 0; t < 16; t++) {
                oacc[t][0] *= c0; oacc[t][1] *= c0;
                oacc[t][2] *= c1; oacc[t][3] *= c1;
            }
        }
        const int prow = wm * 16 + (lane & 15);
        const int vk   = lane & 15;
        const int vng  = lane >> 4;
#pragma unroll
        for (int ks = 0; ks < 4; ks++) {
            uint32_t ah[4], al[4];
            uint32_t po = sw128(prow, ks * 2 + kgl);
            ldsm_x4(ah, sb + APH + po);
            ldsm_x4(al, sb + APL + po);
            int krow = ks * 16 + vk;
#pragma unroll
            for (int ng = 0; ng < 8; ng++) {
                uint32_t vh[4], vl[4];
                int gv = wn * 16 + ng * 2 + vng;
                uint32_t vo = sw512(krow, gv);
                ldsm_x4_trans(vh, sb + AVH + vo);
                ldsm_x4_trans(vl, sb + AVL + vo);
#pragma unroll
                for (int sub = 0; sub < 2; sub++) {
                    float* d = oacc[ng * 2 + sub];
                    mma16816(d, ah, vh[2 * sub], vh[2 * sub + 1]);
                    mma16816(d, ah, vl[2 * sub], vl[2 * sub + 1]);
                    mma16816(d, al, vh[2 * sub], vh[2 * sub + 1]);
                }
            }
        }
        __syncthreads();
    }

    {
        const int r0 = wm * 16 + er;
        const float li0 = 1.0f / lrow[r0];
        const float li1 = 1.0f / lrow[r0 + 8];
        const size_t base0 = (size_t)(i0 + r0) * ODIM + h * HDIM;
        const size_t base1 = (size_t)(i0 + r0 + 8) * ODIM + h * HDIM;
#pragma unroll
        for (int t = 0; t < 16; t++) {
            int col = wn * 128 + (t >> 1) * 16 + (t & 1) * 8 + ec;
            float2 gt0 = *reinterpret_cast<const float2*>(&g_gate[base0 + col]);
            float2 gt1 = *reinterpret_cast<const float2*>(&g_gate[base1 + col]);
            float v00 = oacc[t][0] * li0 * (1.0f / (1.0f + __expf(-gt0.x)));
            float v01 = oacc[t][1] * li0 * (1.0f / (1.0f + __expf(-gt0.y)));
            float v10 = oacc[t][2] * li1 * (1.0f / (1.0f + __expf(-gt1.x)));
            float v11 = oacc[t][3] * li1 * (1.0f / (1.0f + __expf(-gt1.y)));
            __nv_bfloat16 h00 = __float2bfloat16(v00), h01 = __float2bfloat16(v01);
            __nv_bfloat16 h10 = __float2bfloat16(v10), h11 = __float2bfloat16(v11);
            __nv_bfloat16 l00 = __float2bfloat16(v00 - __bfloat162float(h00));
            __nv_bfloat16 l01 = __float2bfloat16(v01 - __bfloat162float(h01));
            __nv_bfloat16 l10 = __float2bfloat16(v10 - __bfloat162float(h10));
            __nv_bfloat16 l11 = __float2bfloat16(v11 - __bfloat162float(h11));
            *reinterpret_cast<uint32_t*>(&g_ath[base0 + col]) = pack_bf16x2(h00, h01);
            *reinterpret_cast<uint32_t*>(&g_atl[base0 + col]) = pack_bf16x2(l00, l01);
            *reinterpret_cast<uint32_t*>(&g_ath[base1 + col]) = pack_bf16x2(h10, h11);
            *reinterpret_cast<uint32_t*>(&g_atl[base1 + col]) = pack_bf16x2(l10, l11);
        }
    }
}

// ---------------- launch ----------------
extern "C" void kernel_launch(void* const* d_in, const int* in_sizes, int n_in,
                              void* d_out, int out_size)
{
    const float* x    = (const float*)d_in[0];
    const float* cosb = (const float*)d_in[1];
    const float* sinb = (const float*)d_in[2];
    const float* wq   = (const float*)d_in[4];
    const float* wk   = (const float*)d_in[5];
    const float* wv   = (const float*)d_in[6];
    const float* wo   = (const float*)d_in[7];
    const float* qg   = (const float*)d_in[8];
    const float* kg   = (const float*)d_in[9];
    float* out        = (float*)d_out;

    float *p_qraw, *p_kvraw;
    cudaGetSymbolAddress((void**)&p_qraw,  g_qraw);
    cudaGetSymbolAddress((void**)&p_kvraw, g_kvraw);

    __nv_bfloat16 *p_xh, *p_xl, *p_wqh, *p_wql, *p_wkvh, *p_wkvl,
                  *p_woh, *p_wol, *p_ath, *p_atl;
    cudaGetSymbolAddress((void**)&p_xh,   g_xh);
    cudaGetSymbolAddress((void**)&p_xl,   g_xl);
    cudaGetSymbolAddress((void**)&p_wqh,  g_wqh);
    cudaGetSymbolAddress((void**)&p_wql,  g_wql);
    cudaGetSymbolAddress((void**)&p_wkvh, g_wkvh);
    cudaGetSymbolAddress((void**)&p_wkvl, g_wkvl);
    cudaGetSymbolAddress((void**)&p_woh,  g_woh);
    cudaGetSymbolAddress((void**)&p_wol,  g_wol);
    cudaGetSymbolAddress((void**)&p_ath,  g_ath);
    cudaGetSymbolAddress((void**)&p_atl,  g_atl);

    cudaFuncSetAttribute(mma_gemm, cudaFuncAttributeMaxDynamicSharedMemorySize, GEMM_SMEM);
    cudaFuncSetAttribute(attn_mma_kernel, cudaFuncAttributeMaxDynamicSharedMemorySize, ATT_SMEM);

    // 0) operand prep
    split_kernel<<<1024, 256>>>(x, p_xh, p_xl, (size_t)L_SEQ * IDIM / 4);
    transpose_split_kernel<<<dim3((ODIM*2)/32, IDIM/32), 256>>>(wq, p_wqh, p_wql, IDIM, ODIM*2);
    transpose_split_kernel<<<dim3(NKV/32, IDIM/32), 256>>>(wk, p_wkvh, p_wkvl, IDIM, NKV);
    transpose_split_kernel<<<dim3(NKV/32, IDIM/32), 256>>>(
        wv, p_wkvh + (size_t)512 * IDIM, p_wkvl + (size_t)512 * IDIM, IDIM, NKV);
    transpose_split_kernel<<<dim3(IDIM/32, ODIM/32), 256>>>(wo, p_woh, p_wol, ODIM, IDIM);

    // 1) projections: Q (N=4096) and fused KV (N=1024)
    mma_gemm<<<dim3((ODIM*2)/128, L_SEQ/256), 256, GEMM_SMEM>>>(p_xh, p_xl, p_wqh, p_wql, p_qraw, ODIM*2);
    mma_gemm<<<dim3(1024/128,     L_SEQ/256), 256, GEMM_SMEM>>>(p_xh, p_xl, p_wkvh, p_wkvl, p_kvraw, 1024);

    // 2) norms + RoPE -> bf16 hi/lo; V split
    qnorm_rope_kernel<<<dim3(L_SEQ, NHEADS),  256>>>(cosb, sinb, qg);
    knorm_rope_kernel<<<dim3(L_SEQ, NGROUPS), 256>>>(cosb, sinb, kg);
    vsplit_kernel<<<dim3(L_SEQ, NGROUPS), 256>>>();

    // 3) MMA flash attention + gating -> hi/lo bf16
    attn_mma_kernel<<<dim3(L_SEQ / 64, NHEADS), 256, ATT_SMEM>>>();

    // 4) output projection
    mma_gemm<<<dim3(IDIM/128, L_SEQ/256), 256, GEMM_SMEM>>>(p_ath, p_atl, p_woh, p_wol, out, IDIM);
}

// round 7
// speedup vs baseline: 1.0662x; 1.0662x over previous
#include <cuda_runtime.h>
#include <cuda_bf16.h>
#include <math.h>
#include <stdint.h>

// ---------------- problem constants ----------------
#define L_SEQ   4096
#define IDIM    2048
#define NHEADS  8
#define NGROUPS 2
#define HDIM    256
#define ROPED   64
#define ODIM    (NHEADS*HDIM)     // 2048
#define NKV     (NGROUPS*HDIM)    // 512
#define QSCALE  0.0625f           // 256^-0.5

// ---------------- warp-MMA helpers (standard PTX, sm_80+) ----------------
__device__ __forceinline__ void ldsm_x4(uint32_t* r, uint32_t addr) {
    asm volatile("ldmatrix.sync.aligned.m8n8.x4.shared.b16 {%0,%1,%2,%3}, [%4];"
        : "=r"(r[0]), "=r"(r[1]), "=r"(r[2]), "=r"(r[3]) : "r"(addr));
}
__device__ __forceinline__ void ldsm_x4_trans(uint32_t* r, uint32_t addr) {
    asm volatile("ldmatrix.sync.aligned.m8n8.x4.trans.shared.b16 {%0,%1,%2,%3}, [%4];"
        : "=r"(r[0]), "=r"(r[1]), "=r"(r[2]), "=r"(r[3]) : "r"(addr));
}
__device__ __forceinline__ void mma16816(float* d, const uint32_t* a, uint32_t b0, uint32_t b1) {
    asm volatile("mma.sync.aligned.m16n8k16.row.col.f32.bf16.bf16.f32 "
        "{%0,%1,%2,%3}, {%4,%5,%6,%7}, {%8,%9}, {%0,%1,%2,%3};"
        : "+f"(d[0]), "+f"(d[1]), "+f"(d[2]), "+f"(d[3])
        : "r"(a[0]), "r"(a[1]), "r"(a[2]), "r"(a[3]), "r"(b0), "r"(b1));
}
__device__ __forceinline__ void cp_async16(uint32_t dst, const void* src) {
    asm volatile("cp.async.cg.shared.global [%0], [%1], 16;" :: "r"(dst), "l"(src));
}
#define CP_COMMIT() asm volatile("cp.async.commit_group;" ::: "memory")
#define CP_WAIT1()  asm volatile("cp.async.wait_group 1;" ::: "memory")
#define CP_WAIT0()  asm volatile("cp.async.wait_group 0;" ::: "memory")

__device__ __forceinline__ uint32_t smem_to_u32(const void* p) {
    uint32_t a;
    asm("{ .reg .u64 t; cvta.to.shared.u64 t, %1; cvt.u32.u64 %0, t; }" : "=r"(a) : "l"(p));
    return a;
}
__device__ __forceinline__ uint32_t pack_bf16x2(__nv_bfloat16 a, __nv_bfloat16 b) {
    __nv_bfloat162 t{a, b};
    return *reinterpret_cast<uint32_t*>(&t);
}

// ---------------- scratch (device globals) ----------------
__device__ float g_qraw [(size_t)L_SEQ * (ODIM*2)];
__device__ float g_gate [(size_t)L_SEQ * ODIM];
__device__ float g_kvraw[(size_t)L_SEQ * 1024];     // cols 0-511 = K, 512-1023 = V

// bf16 hi/lo operands
__device__ __nv_bfloat16 g_xh  [(size_t)L_SEQ * IDIM];
__device__ __nv_bfloat16 g_xl  [(size_t)L_SEQ * IDIM];
__device__ __nv_bfloat16 g_wqh [(size_t)(ODIM*2) * IDIM];
__device__ __nv_bfloat16 g_wql [(size_t)(ODIM*2) * IDIM];
__device__ __nv_bfloat16 g_wkvh[(size_t)1024 * IDIM];   // rows 0-511 wk^T, 512-1023 wv^T
__device__ __nv_bfloat16 g_wkvl[(size_t)1024 * IDIM];
__device__ __nv_bfloat16 g_woh [(size_t)IDIM * ODIM];
__device__ __nv_bfloat16 g_wol [(size_t)IDIM * ODIM];
__device__ __nv_bfloat16 g_ath [(size_t)L_SEQ * ODIM];
__device__ __nv_bfloat16 g_atl [(size_t)L_SEQ * ODIM];
// attention operands
__device__ __nv_bfloat16 g_qh [(size_t)L_SEQ * ODIM];
__device__ __nv_bfloat16 g_ql [(size_t)L_SEQ * ODIM];
__device__ __nv_bfloat16 g_kh [(size_t)L_SEQ * NKV];
__device__ __nv_bfloat16 g_kl [(size_t)L_SEQ * NKV];
__device__ __nv_bfloat16 g_vh [(size_t)L_SEQ * NKV];
__device__ __nv_bfloat16 g_vl [(size_t)L_SEQ * NKV];

// ---------------- split kernel: fp32 -> (hi, lo) bf16 ----------------
__global__ __launch_bounds__(256) void split_kernel(
    const float* __restrict__ in, __nv_bfloat16* __restrict__ hi,
    __nv_bfloat16* __restrict__ lo, size_t n4)
{
    size_t i = (size_t)blockIdx.x * blockDim.x + threadIdx.x;
    size_t stride = (size_t)gridDim.x * blockDim.x;
    for (; i < n4; i += stride) {
        float4 v = reinterpret_cast<const float4*>(in)[i];
        __nv_bfloat16 h0 = __float2bfloat16(v.x), h1 = __float2bfloat16(v.y);
        __nv_bfloat16 h2 = __float2bfloat16(v.z), h3 = __float2bfloat16(v.w);
        __nv_bfloat16 l0 = __float2bfloat16(v.x - __bfloat162float(h0));
        __nv_bfloat16 l1 = __float2bfloat16(v.y - __bfloat162float(h1));
        __nv_bfloat16 l2 = __float2bfloat16(v.z - __bfloat162float(h2));
        __nv_bfloat16 l3 = __float2bfloat16(v.w - __bfloat162float(h3));
        __nv_bfloat162 hp0{h0, h1}, hp1{h2, h3}, lp0{l0, l1}, lp1{l2, l3};
        reinterpret_cast<__nv_bfloat162*>(hi)[i*2]   = hp0;
        reinterpret_cast<__nv_bfloat162*>(hi)[i*2+1] = hp1;
        reinterpret_cast<__nv_bfloat162*>(lo)[i*2]   = lp0;
        reinterpret_cast<__nv_bfloat162*>(lo)[i*2+1] = lp1;
    }
}

// ---------------- transpose + split: W[K][N] fp32 -> Wt hi/lo [N][K] bf16 ----------------
__global__ __launch_bounds__(256) void transpose_split_kernel(
    const float* __restrict__ W, __nv_bfloat16* __restrict__ Th,
    __nv_bfloat16* __restrict__ Tl, int Kdim, int Ndim)
{
    __shared__ float tile[32][33];
    int n0 = blockIdx.x * 32;
    int k0 = blockIdx.y * 32;
    int tx = threadIdx.x & 31;
    int ty = threadIdx.x >> 5;
#pragma unroll
    for (int r = 0; r < 4; r++)
        tile[ty + 8*r][tx] = W[(size_t)(k0 + ty + 8*r) * Ndim + n0 + tx];
    __syncthreads();
#pragma unroll
    for (int r = 0; r < 4; r++) {
        float v = tile[tx][ty + 8*r];
        __nv_bfloat16 h = __float2bfloat16(v);
        __nv_bfloat16 l = __float2bfloat16(v - __bfloat162float(h));
        size_t o = (size_t)(n0 + ty + 8*r) * Kdim + k0 + tx;
        Th[o] = h; Tl[o] = l;
    }
}

// ---------------- warp-mma split-bf16 GEMM (v1, proven: 128x128, 2-stage) ----------------
#define GBK 32
#define NCHUNK (IDIM / GBK)            // 64
#define RS 80                          // smem row stride bytes (conflict-free ldsm)
#define MAT_BYTES (128 * RS)           // 10240
#define STAGE_BYTES (4 * MAT_BYTES)    // 40960 (Ah, Al, Bh, Bl)
#define GEMM_SMEM (2 * STAGE_BYTES)    // 81920 -> 2 CTAs/SM

__global__ __launch_bounds__(256) void mma_gemm(
    const __nv_bfloat16* __restrict__ Ah, const __nv_bfloat16* __restrict__ Al,
    const __nv_bfloat16* __restrict__ Bh, const __nv_bfloat16* __restrict__ Bl,
    float* __restrict__ C, int N)
{
    extern __shared__ char smem[];
    const uint32_t sb = smem_to_u32(smem);

    const int tid  = threadIdx.x;
    const int lane = tid & 31;
    const int wid  = tid >> 5;
    const int wm   = wid & 1;
    const int wn   = wid >> 1;
    const int m0   = blockIdx.y * 128;
    const int n0   = blockIdx.x * 128;

    const int mat  = tid >> 6;
    const int lidx = tid & 63;
    const __nv_bfloat16* gbase = (mat == 0) ? Ah : (mat == 1) ? Al : (mat == 2) ? Bh : Bl;
    const int grow0 = (mat < 2) ? m0 : n0;
    const uint32_t smat = sb + mat * MAT_BYTES;

    auto issue_loads = [&](int chunk) {
        const int stage = chunk & 1;
        const uint32_t sdst0 = smat + stage * STAGE_BYTES;
        const __nv_bfloat16* src0 = gbase + (size_t)grow0 * IDIM + chunk * GBK;
#pragma unroll
        for (int j = 0; j < 8; j++) {
            int idx = lidx + 64 * j;
            int row = idx >> 2;
            int c   = idx & 3;
            cp_async16(sdst0 + row * RS + c * 16,
                       src0 + (size_t)row * IDIM + c * 8);
        }
    };

    float acc[4][4][4];
#pragma unroll
    for (int mi = 0; mi < 4; mi++)
#pragma unroll
        for (int ni = 0; ni < 4; ni++)
#pragma unroll
            for (int r = 0; r < 4; r++) acc[mi][ni][r] = 0.0f;

    const uint32_t a_row = wm * 64 + (lane & 15);
    const uint32_t b_row = wn * 32 + (lane & 15);
    const uint32_t colb  = (lane >> 4) * 16;

    issue_loads(0); CP_COMMIT();

    for (int i = 0; i < NCHUNK; i++) {
        const int stage = i & 1;
        if (i + 1 < NCHUNK) { issue_loads(i + 1); CP_COMMIT(); CP_WAIT1(); }
        else                { CP_WAIT0(); }
        __syncthreads();

        const uint32_t sAh = sb + stage * STAGE_BYTES;
        const uint32_t sAl = sAh + MAT_BYTES;
        const uint32_t sBh = sAh + 2 * MAT_BYTES;
        const uint32_t sBl = sAh + 3 * MAT_BYTES;

#pragma unroll
        for (int ks = 0; ks < 2; ks++) {
            const uint32_t kb = ks * 32 + colb;
            uint32_t ah[4][4], al[4][4], bh[2][4], bl[2][4];
#pragma unroll
            for (int mi = 0; mi < 4; mi++) {
                uint32_t ro = (a_row + mi * 16) * RS + kb;
                ldsm_x4(ah[mi], sAh + ro);
                ldsm_x4(al[mi], sAl + ro);
            }
#pragma unroll
            for (int nt = 0; nt < 2; nt++) {
                uint32_t ro = (b_row + nt * 16) * RS + kb;
                ldsm_x4(bh[nt], sBh + ro);
                ldsm_x4(bl[nt], sBl + ro);
            }
#pragma unroll
            for (int mi = 0; mi < 4; mi++) {
#pragma unroll
                for (int ni = 0; ni < 4; ni++) {
                    const int nt = ni >> 1, sub = ni & 1;
                    mma16816(acc[mi][ni], ah[mi], bh[nt][sub], bh[nt][2 + sub]);
                    mma16816(acc[mi][ni], ah[mi], bl[nt][sub], bl[nt][2 + sub]);
                    mma16816(acc[mi][ni], al[mi], bh[nt][sub], bh[nt][2 + sub]);
                }
            }
        }
        __syncthreads();
    }

    const int er = lane >> 2;
    const int ec = (lane & 3) * 2;
#pragma unroll
    for (int mi = 0; mi < 4; mi++) {
#pragma unroll
        for (int ni = 0; ni < 4; ni++) {
            int row = m0 + wm * 64 + mi * 16 + er;
            int col = n0 + wn * 32 + ni * 8 + ec;
            *reinterpret_cast<float2*>(&C[(size_t)row * N + col]) =
                make_float2(acc[mi][ni][0], acc[mi][ni][1]);
            *reinterpret_cast<float2*>(&C[(size_t)(row + 8) * N + col]) =
                make_float2(acc[mi][ni][2], acc[mi][ni][3]);
        }
    }
}

// ---------------- RMSNorm + RoPE for Q -> bf16 hi/lo (pre-scaled) + gate ----------------
__global__ __launch_bounds__(256) void qnorm_rope_kernel(
    const float* __restrict__ cosb, const float* __restrict__ sinb,
    const float* __restrict__ gamma)
{
    const int l = blockIdx.x;
    const int h = blockIdx.y;
    const int d = threadIdx.x;
    const float* row = g_qraw + (size_t)l * (ODIM * 2) + h * 512;
    float v  = row[d];
    float gv = row[256 + d];

    float s = v * v;
#pragma unroll
    for (int o = 16; o > 0; o >>= 1) s += __shfl_xor_sync(0xffffffffu, s, o);
    __shared__ float wsum[8];
    __shared__ float sh[256];
    if ((d & 31) == 0) wsum[d >> 5] = s;
    __syncthreads();
    float tot = 0.0f;
#pragma unroll
    for (int w = 0; w < 8; w++) tot += wsum[w];
    float rstd = rsqrtf(tot * (1.0f / 256.0f) + 1e-6f);
    float y = v * rstd * gamma[d];
    sh[d] = y;
    __syncthreads();
    float out = y;
    if (d < ROPED) {
        float rot = (d < ROPED / 2) ? -sh[d + ROPED / 2] : sh[d - ROPED / 2];
        out = y * cosb[(size_t)l * ROPED + d] + rot * sinb[(size_t)l * ROPED + d];
    }
    float q = out * QSCALE;
    __nv_bfloat16 qh = __float2bfloat16(q);
    __nv_bfloat16 ql = __float2bfloat16(q - __bfloat162float(qh));
    size_t o = (size_t)l * ODIM + h * HDIM + d;
    g_qh[o] = qh; g_ql[o] = ql;
    g_gate[o] = gv;
}

// ---------------- RMSNorm + RoPE for K -> bf16 hi/lo (reads fused KV buffer) ----------------
__global__ __launch_bounds__(256) void knorm_rope_kernel(
    const float* __restrict__ cosb, const float* __restrict__ sinb,
    const float* __restrict__ gamma)
{
    const int l = blockIdx.x;
    const int g = blockIdx.y;
    const int d = threadIdx.x;
    float v = g_kvraw[(size_t)l * 1024 + g * HDIM + d];

    float s = v * v;
#pragma unroll
    for (int o = 16; o > 0; o >>= 1) s += __shfl_xor_sync(0xffffffffu, s, o);
    __shared__ float wsum[8];
    __shared__ float sh[256];
    if ((d & 31) == 0) wsum[d >> 5] = s;
    __syncthreads();
    float tot = 0.0f;
#pragma unroll
    for (int w = 0; w < 8; w++) tot += wsum[w];
    float rstd = rsqrtf(tot * (1.0f / 256.0f) + 1e-6f);
    float y = v * rstd * gamma[d];
    sh[d] = y;
    __syncthreads();
    float out = y;
    if (d < ROPED) {
        float rot = (d < ROPED / 2) ? -sh[d + ROPED / 2] : sh[d - ROPED / 2];
        out = y * cosb[(size_t)l * ROPED + d] + rot * sinb[(size_t)l * ROPED + d];
    }
    __nv_bfloat16 kh = __float2bfloat16(out);
    __nv_bfloat16 kl = __float2bfloat16(out - __bfloat162float(kh));
    size_t o = (size_t)l * NKV + g * HDIM + d;
    g_kh[o] = kh; g_kl[o] = kl;
}

// ---------------- V split from fused KV buffer ----------------
__global__ __launch_bounds__(256) void vsplit_kernel()
{
    const int l = blockIdx.x;
    const int g = blockIdx.y;
    const int d = threadIdx.x;
    float v = g_kvraw[(size_t)l * 1024 + 512 + g * HDIM + d];
    __nv_bfloat16 vh = __float2bfloat16(v);
    __nv_bfloat16 vl = __float2bfloat16(v - __bfloat162float(vh));
    size_t o = (size_t)l * NKV + g * HDIM + d;
    g_vh[o] = vh; g_vl[o] = vl;
}

// ---------------- MMA flash attention (split-bf16), BR=BC=64, D=256 ----------------
// Pipelined loads: V(i) overlaps S(i)+softmax; K(i+1) overlaps P·V(i).
#define AQH 0
#define AQL 32768
#define AKH 65536
#define AKL 98304
#define AVH 131072
#define AVL 163840
#define ASS 196608
#define SSS 68
#define APH (ASS + 64*SSS*4)
#define APL (APH + 8192)
#define AMR (APL + 8192)
#define ALR (AMR + 256)
#define ACR (ALR + 256)
#define ATT_SMEM (ACR + 256)

__device__ __forceinline__ uint32_t sw512(int row, int g) {
    return (uint32_t)(row * 512 + ((g ^ (row & 7)) << 4));
}
__device__ __forceinline__ uint32_t sw128(int row, int g) {
    return (uint32_t)(row * 128 + ((g ^ (row & 7)) << 4));
}

__global__ __launch_bounds__(256, 1) void attn_mma_kernel()
{
    extern __shared__ char sm[];
    const uint32_t sb = smem_to_u32(sm);
    const int tid  = threadIdx.x;
    const int lane = tid & 31;
    const int wid  = tid >> 5;
    const int qt   = gridDim.x - 1 - blockIdx.x;   // big tiles first
    const int h    = blockIdx.y;
    const int g    = h >> 2;
    const int i0   = qt * 64;

    float* Ss   = reinterpret_cast<float*>(sm + ASS);
    float* mrow = reinterpret_cast<float*>(sm + AMR);
    float* lrow = reinterpret_cast<float*>(sm + ALR);
    float* crow = reinterpret_cast<float*>(sm + ACR);

    // split K / V loaders (8x2 cp.async each)
    auto load_k = [&](int j0) {
        const size_t rbase = ((size_t)j0 * NGROUPS + g) * HDIM;
        const size_t rstr  = (size_t)NGROUPS * HDIM;
#pragma unroll
        for (int i = 0; i < 8; i++) {
            int idx = tid + 256 * i;
            int row = idx >> 5, gr = idx & 31;
            size_t go = (rbase + (size_t)row * rstr) * 2 + gr * 16;
            uint32_t so = sw512(row, gr);
            cp_async16(sb + AKH + so, (const char*)g_kh + go);
            cp_async16(sb + AKL + so, (const char*)g_kl + go);
        }
    };
    auto load_v = [&](int j0) {
        const size_t rbase = ((size_t)j0 * NGROUPS + g) * HDIM;
        const size_t rstr  = (size_t)NGROUPS * HDIM;
#pragma unroll
        for (int i = 0; i < 8; i++) {
            int idx = tid + 256 * i;
            int row = idx >> 5, gr = idx & 31;
            size_t go = (rbase + (size_t)row * rstr) * 2 + gr * 16;
            uint32_t so = sw512(row, gr);
            cp_async16(sb + AVH + so, (const char*)g_vh + go);
            cp_async16(sb + AVL + so, (const char*)g_vl + go);
        }
    };

    // ---- prolog: Q tile, then K(0), then V(0) (3 commit groups) ----
    {
        const char* qh = (const char*)(g_qh + ((size_t)i0 * NHEADS + h) * HDIM);
        const char* ql = (const char*)(g_ql + ((size_t)i0 * NHEADS + h) * HDIM);
        const size_t rstr = (size_t)NHEADS * HDIM * 2;
#pragma unroll
        for (int i = 0; i < 8; i++) {
            int idx = tid + 256 * i;
            int row = idx >> 5, gr = idx & 31;
            uint32_t so = sw512(row, gr);
            cp_async16(sb + AQH + so, qh + (size_t)row * rstr + gr * 16);
            cp_async16(sb + AQL + so, ql + (size_t)row * rstr + gr * 16);
        }
    }
    CP_COMMIT();
    load_k(0); CP_COMMIT();
    if (tid < 64) { mrow[tid] = -INFINITY; lrow[tid] = 0.0f; }
    load_v(0); CP_COMMIT();

    const int wm = wid & 3;
    const int wn = wid >> 2;
    const int er = lane >> 2;
    const int ec = (lane & 3) * 2;
    const int kgl = lane >> 4;

    float oacc[16][4];
#pragma unroll
    for (int t = 0; t < 16; t++)
#pragma unroll
        for (int r = 0; r < 4; r++) oacc[t][r] = 0.0f;

    for (int j0 = 0; j0 <= i0; j0 += 64) {
        // K(j0) (and Q on first iter) ready; V(j0) may still be in flight
        CP_WAIT1();
        __syncthreads();

        // ---- S = Q K^T (3-term split) ----
        float sacc[4][4];
#pragma unroll
        for (int t = 0; t < 4; t++)
#pragma unroll
            for (int r = 0; r < 4; r++) sacc[t][r] = 0.0f;

        const int arow  = wm * 16 + (lane & 15);
        const int brow0 = wn * 32 + (lane & 15);
#pragma unroll 4
        for (int ks = 0; ks < 16; ks++) {
            int kg = ks * 2 + kgl;
            uint32_t ah[4], al[4], bh[2][4], bl[2][4];
            uint32_t ao = sw512(arow, kg);
            ldsm_x4(ah, sb + AQH + ao);
            ldsm_x4(al, sb + AQL + ao);
            uint32_t bo0 = sw512(brow0, kg);
            uint32_t bo1 = sw512(brow0 + 16, kg);
            ldsm_x4(bh[0], sb + AKH + bo0);
            ldsm_x4(bh[1], sb + AKH + bo1);
            ldsm_x4(bl[0], sb + AKL + bo0);
            ldsm_x4(bl[1], sb + AKL + bo1);
#pragma unroll
            for (int nt = 0; nt < 2; nt++)
#pragma unroll
                for (int sub = 0; sub < 2; sub++) {
                    float* d = sacc[nt * 2 + sub];
                    mma16816(d, ah, bh[nt][sub], bh[nt][2 + sub]);
                    mma16816(d, ah, bl[nt][sub], bl[nt][2 + sub]);
                    mma16816(d, al, bh[nt][sub], bh[nt][2 + sub]);
                }
        }
#pragma unroll
        for (int t = 0; t < 4; t++) {
            int col = wn * 32 + (t >> 1) * 16 + (t & 1) * 8 + ec;
            int r0 = wm * 16 + er;
            Ss[r0 * SSS + col]           = sacc[t][0];
            Ss[r0 * SSS + col + 1]       = sacc[t][1];
            Ss[(r0 + 8) * SSS + col]     = sacc[t][2];
            Ss[(r0 + 8) * SSS + col + 1] = sacc[t][3];
        }
        __syncthreads();

        // ---- online softmax + P hi/lo conversion (4 threads / row) ----
        {
            const int row  = tid >> 2;
            const int part = tid & 3;
            int vlim = i0 + row - j0 + 1; if (vlim > 64) vlim = 64;
            float sv[16];
            float mx = -INFINITY;
            const float* srow = &Ss[row * SSS + part * 16];
#pragma unroll
            for (int c = 0; c < 16; c++) {
                int cc = part * 16 + c;
                float v = (cc < vlim) ? srow[c] : -INFINITY;
                sv[c] = v; mx = fmaxf(mx, v);
            }
            mx = fmaxf(mx, __shfl_xor_sync(0xffffffffu, mx, 1));
            mx = fmaxf(mx, __shfl_xor_sync(0xffffffffu, mx, 2));
            float mold = mrow[row];
            float mnew = fmaxf(mold, mx);
            float ls = 0.0f;
#pragma unroll
            for (int c = 0; c < 16; c++) {
                float p = __expf(sv[c] - mnew);
                sv[c] = p; ls += p;
            }
            ls += __shfl_xor_sync(0xffffffffu, ls, 1);
            ls += __shfl_xor_sync(0xffffffffu, ls, 2);
            float corr = __expf(mold - mnew);
            if (part == 0) {
                mrow[row] = mnew;
                lrow[row] = lrow[row] * corr + ls;
                crow[row] = corr;
            }
#pragma unroll
            for (int gs = 0; gs < 2; gs++) {
                uint32_t hw[4], lw[4];
#pragma unroll
                for (int q = 0; q < 4; q++) {
                    float p0 = sv[gs * 8 + q * 2], p1 = sv[gs * 8 + q * 2 + 1];
                    __nv_bfloat16 h0 = __float2bfloat16(p0);
                    __nv_bfloat16 h1 = __float2bfloat16(p1);
                    __nv_bfloat16 l0 = __float2bfloat16(p0 - __bfloat162float(h0));
                    __nv_bfloat16 l1 = __float2bfloat16(p1 - __bfloat162float(h1));
                    hw[q] = pack_bf16x2(h0, h1);
                    lw[q] = pack_bf16x2(l0, l1);
                }
                uint32_t off = sw128(row, part * 2 + gs);
                *reinterpret_cast<uint4*>(sm + APH + off) = make_uint4(hw[0], hw[1], hw[2], hw[3]);
                *reinterpret_cast<uint4*>(sm + APL + off) = make_uint4(lw[0], lw[1], lw[2], lw[3]);
            }
        }
        __syncthreads();          // K buffer now dead; P ready

        // prefetch K(j0+64) during P·V
        if (j0 + 64 <= i0) load_k(j0 + 64);
        CP_COMMIT();
        CP_WAIT1();               // V(j0) ready (K(j0+64) still in flight)
        __syncthreads();

        // ---- rescale O, then O += P V (3-term split) ----
        {
            float c0 = crow[wm * 16 + er];
            float c1 = crow[wm * 16 + er + 8];
#pragma unroll
            for (int t = 0; t < 16; t++) {
                oacc[t][0] *= c0; oacc[t][1] *= c0;
                oacc[t][2] *= c1; oacc[t][3] *= c1;
            }
        }
        const int prow = wm * 16 + (lane & 15);
        const int vk   = lane & 15;
        const int vng  = lane >> 4;
#pragma unroll
        for (int ks = 0; ks < 4; ks++) {
            uint32_t ah[4], al[4];
            uint32_t po = sw128(prow, ks * 2 + kgl);
            ldsm_x4(ah, sb + APH + po);
            ldsm_x4(al, sb + APL + po);
            int krow = ks * 16 + vk;
#pragma unroll
            for (int ng = 0; ng < 8; ng++) {
                uint32_t vh[4], vl[4];
                int gv = wn * 16 + ng * 2 + vng;
                uint32_t vo = sw512(krow, gv);
                ldsm_x4_trans(vh, sb + AVH + vo);
                ldsm_x4_trans(vl, sb + AVL + vo);
#pragma unroll
                for (int sub = 0; sub < 2; sub++) {
                    float* d = oacc[ng * 2 + sub];
                    mma16816(d, ah, vh[2 * sub], vh[2 * sub + 1]);
                    mma16816(d, ah, vl[2 * sub], vl[2 * sub + 1]);
                    mma16816(d, al, vh[2 * sub], vh[2 * sub + 1]);
                }
            }
        }
        __syncthreads();          // V buffer now dead

        // prefetch V(j0+64) during next iteration's S compute
        if (j0 + 64 <= i0) load_v(j0 + 64);
        CP_COMMIT();
    }

    // ---- epilogue: 1/l, sigmoid gate, write hi/lo bf16 ----
    {
        const int r0 = wm * 16 + er;
        const float li0 = 1.0f / lrow[r0];
        const float li1 = 1.0f / lrow[r0 + 8];
        const size_t base0 = (size_t)(i0 + r0) * ODIM + h * HDIM;
        const size_t base1 = (size_t)(i0 + r0 + 8) * ODIM + h * HDIM;
#pragma unroll
        for (int t = 0; t < 16; t++) {
            int col = wn * 128 + (t >> 1) * 16 + (t & 1) * 8 + ec;
            float2 gt0 = *reinterpret_cast<const float2*>(&g_gate[base0 + col]);
            float2 gt1 = *reinterpret_cast<const float2*>(&g_gate[base1 + col]);
            float v00 = oacc[t][0] * li0 * (1.0f / (1.0f + __expf(-gt0.x)));
            float v01 = oacc[t][1] * li0 * (1.0f / (1.0f + __expf(-gt0.y)));
            float v10 = oacc[t][2] * li1 * (1.0f / (1.0f + __expf(-gt1.x)));
            float v11 = oacc[t][3] * li1 * (1.0f / (1.0f + __expf(-gt1.y)));
            __nv_bfloat16 h00 = __float2bfloat16(v00), h01 = __float2bfloat16(v01);
            __nv_bfloat16 h10 = __float2bfloat16(v10), h11 = __float2bfloat16(v11);
            __nv_bfloat16 l00 = __float2bfloat16(v00 - __bfloat162float(h00));
            __nv_bfloat16 l01 = __float2bfloat16(v01 - __bfloat162float(h01));
            __nv_bfloat16 l10 = __float2bfloat16(v10 - __bfloat162float(h10));
            __nv_bfloat16 l11 = __float2bfloat16(v11 - __bfloat162float(h11));
            *reinterpret_cast<uint32_t*>(&g_ath[base0 + col]) = pack_bf16x2(h00, h01);
            *reinterpret_cast<uint32_t*>(&g_atl[base0 + col]) = pack_bf16x2(l00, l01);
            *reinterpret_cast<uint32_t*>(&g_ath[base1 + col]) = pack_bf16x2(h10, h11);
            *reinterpret_cast<uint32_t*>(&g_atl[base1 + col]) = pack_bf16x2(l10, l11);
        }
    }
}

// ---------------- launch ----------------
extern "C" void kernel_launch(void* const* d_in, const int* in_sizes, int n_in,
                              void* d_out, int out_size)
{
    const float* x    = (const float*)d_in[0];
    const float* cosb = (const float*)d_in[1];
    const float* sinb = (const float*)d_in[2];
    const float* wq   = (const float*)d_in[4];
    const float* wk   = (const float*)d_in[5];
    const float* wv   = (const float*)d_in[6];
    const float* wo   = (const float*)d_in[7];
    const float* qg   = (const float*)d_in[8];
    const float* kg   = (const float*)d_in[9];
    float* out        = (float*)d_out;

    float *p_qraw, *p_kvraw;
    cudaGetSymbolAddress((void**)&p_qraw,  g_qraw);
    cudaGetSymbolAddress((void**)&p_kvraw, g_kvraw);

    __nv_bfloat16 *p_xh, *p_xl, *p_wqh, *p_wql, *p_wkvh, *p_wkvl,
                  *p_woh, *p_wol, *p_ath, *p_atl;
    cudaGetSymbolAddress((void**)&p_xh,   g_xh);
    cudaGetSymbolAddress((void**)&p_xl,   g_xl);
    cudaGetSymbolAddress((void**)&p_wqh,  g_wqh);
    cudaGetSymbolAddress((void**)&p_wql,  g_wql);
    cudaGetSymbolAddress((void**)&p_wkvh, g_wkvh);
    cudaGetSymbolAddress((void**)&p_wkvl, g_wkvl);
    cudaGetSymbolAddress((void**)&p_woh,  g_woh);
    cudaGetSymbolAddress((void**)&p_wol,  g_wol);
    cudaGetSymbolAddress((void**)&p_ath,  g_ath);
    cudaGetSymbolAddress((void**)&p_atl,  g_atl);

    cudaFuncSetAttribute(mma_gemm, cudaFuncAttributeMaxDynamicSharedMemorySize, GEMM_SMEM);
    cudaFuncSetAttribute(attn_mma_kernel, cudaFuncAttributeMaxDynamicSharedMemorySize, ATT_SMEM);

    // 0) operand prep
    split_kernel<<<1024, 256>>>(x, p_xh, p_xl, (size_t)L_SEQ * IDIM / 4);
    transpose_split_kernel<<<dim3((ODIM*2)/32, IDIM/32), 256>>>(wq, p_wqh, p_wql, IDIM, ODIM*2);
    transpose_split_kernel<<<dim3(NKV/32, IDIM/32), 256>>>(wk, p_wkvh, p_wkvl, IDIM, NKV);
    transpose_split_kernel<<<dim3(NKV/32, IDIM/32), 256>>>(
        wv, p_wkvh + (size_t)512 * IDIM, p_wkvl + (size_t)512 * IDIM, IDIM, NKV);
    transpose_split_kernel<<<dim3(IDIM/32, ODIM/32), 256>>>(wo, p_woh, p_wol, ODIM, IDIM);

    // 1) projections: Q (N=4096) and fused KV (N=1024)
    mma_gemm<<<dim3((ODIM*2)/128, L_SEQ/128), 256, GEMM_SMEM>>>(p_xh, p_xl, p_wqh, p_wql, p_qraw, ODIM*2);
    mma_gemm<<<dim3(1024/128,     L_SEQ/128), 256, GEMM_SMEM>>>(p_xh, p_xl, p_wkvh, p_wkvl, p_kvraw, 1024);

    // 2) norms + RoPE -> bf16 hi/lo; V split
    qnorm_rope_kernel<<<dim3(L_SEQ, NHEADS),  256>>>(cosb, sinb, qg);
    knorm_rope_kernel<<<dim3(L_SEQ, NGROUPS), 256>>>(cosb, sinb, kg);
    vsplit_kernel<<<dim3(L_SEQ, NGROUPS), 256>>>();

    // 3) MMA flash attention + gating -> hi/lo bf16 (pipelined K/V loads)
    attn_mma_kernel<<<dim3(L_SEQ / 64, NHEADS), 256, ATT_SMEM>>>();

    // 4) output projection
    mma_gemm<<<dim3(IDIM/128, L_SEQ/128), 256, GEMM_SMEM>>>(p_ath, p_atl, p_woh, p_wol, out, IDIM);
}

// round 8
// speedup vs baseline: 1.1347x; 1.0643x over previous
#include <cuda_runtime.h>
#include <cuda_bf16.h>
#include <cuda_fp16.h>
#include <math.h>
#include <stdint.h>

// ---------------- problem constants ----------------
#define L_SEQ   4096
#define IDIM    2048
#define NHEADS  8
#define NGROUPS 2
#define HDIM    256
#define ROPED   64
#define ODIM    (NHEADS*HDIM)     // 2048
#define NKV     (NGROUPS*HDIM)    // 512
#define QSCALE  0.0625f           // 256^-0.5

// ---------------- warp-MMA helpers (standard PTX, sm_80+) ----------------
__device__ __forceinline__ void ldsm_x4(uint32_t* r, uint32_t addr) {
    asm volatile("ldmatrix.sync.aligned.m8n8.x4.shared.b16 {%0,%1,%2,%3}, [%4];"
        : "=r"(r[0]), "=r"(r[1]), "=r"(r[2]), "=r"(r[3]) : "r"(addr));
}
__device__ __forceinline__ void ldsm_x4_trans(uint32_t* r, uint32_t addr) {
    asm volatile("ldmatrix.sync.aligned.m8n8.x4.trans.shared.b16 {%0,%1,%2,%3}, [%4];"
        : "=r"(r[0]), "=r"(r[1]), "=r"(r[2]), "=r"(r[3]) : "r"(addr));
}
__device__ __forceinline__ void mma16816(float* d, const uint32_t* a, uint32_t b0, uint32_t b1) {
    asm volatile("mma.sync.aligned.m16n8k16.row.col.f32.bf16.bf16.f32 "
        "{%0,%1,%2,%3}, {%4,%5,%6,%7}, {%8,%9}, {%0,%1,%2,%3};"
        : "+f"(d[0]), "+f"(d[1]), "+f"(d[2]), "+f"(d[3])
        : "r"(a[0]), "r"(a[1]), "r"(a[2]), "r"(a[3]), "r"(b0), "r"(b1));
}
__device__ __forceinline__ void mma16816h(float* d, const uint32_t* a, uint32_t b0, uint32_t b1) {
    asm volatile("mma.sync.aligned.m16n8k16.row.col.f32.f16.f16.f32 "
        "{%0,%1,%2,%3}, {%4,%5,%6,%7}, {%8,%9}, {%0,%1,%2,%3};"
        : "+f"(d[0]), "+f"(d[1]), "+f"(d[2]), "+f"(d[3])
        : "r"(a[0]), "r"(a[1]), "r"(a[2]), "r"(a[3]), "r"(b0), "r"(b1));
}
__device__ __forceinline__ void cp_async16(uint32_t dst, const void* src) {
    asm volatile("cp.async.cg.shared.global [%0], [%1], 16;" :: "r"(dst), "l"(src));
}
#define CP_COMMIT() asm volatile("cp.async.commit_group;" ::: "memory")
#define CP_WAIT1()  asm volatile("cp.async.wait_group 1;" ::: "memory")
#define CP_WAIT0()  asm volatile("cp.async.wait_group 0;" ::: "memory")

__device__ __forceinline__ uint32_t smem_to_u32(const void* p) {
    uint32_t a;
    asm("{ .reg .u64 t; cvta.to.shared.u64 t, %1; cvt.u32.u64 %0, t; }" : "=r"(a) : "l"(p));
    return a;
}
__device__ __forceinline__ uint32_t pack_bf16x2(__nv_bfloat16 a, __nv_bfloat16 b) {
    __nv_bfloat162 t{a, b};
    return *reinterpret_cast<uint32_t*>(&t);
}

// ---------------- scratch (device globals) ----------------
__device__ float g_qraw [(size_t)L_SEQ * (ODIM*2)];
__device__ float g_gate [(size_t)L_SEQ * ODIM];
__device__ float g_kvraw[(size_t)L_SEQ * 1024];     // cols 0-511 = K, 512-1023 = V

// bf16 hi/lo operands (projections Q/KV keep 3-term bf16)
__device__ __nv_bfloat16 g_xh  [(size_t)L_SEQ * IDIM];
__device__ __nv_bfloat16 g_xl  [(size_t)L_SEQ * IDIM];
__device__ __nv_bfloat16 g_wqh [(size_t)(ODIM*2) * IDIM];
__device__ __nv_bfloat16 g_wql [(size_t)(ODIM*2) * IDIM];
__device__ __nv_bfloat16 g_wkvh[(size_t)1024 * IDIM];   // rows 0-511 wk^T, 512-1023 wv^T
__device__ __nv_bfloat16 g_wkvl[(size_t)1024 * IDIM];
// wo projection: 2-term fp16 (y single, wo hi/lo)
__device__ __half g_y    [(size_t)L_SEQ * ODIM];
__device__ __half g_woh16[(size_t)IDIM * ODIM];
__device__ __half g_wol16[(size_t)IDIM * ODIM];
// attention operands (bf16 hi/lo, 3-term)
__device__ __nv_bfloat16 g_qh [(size_t)L_SEQ * ODIM];
__device__ __nv_bfloat16 g_ql [(size_t)L_SEQ * ODIM];
__device__ __nv_bfloat16 g_kh [(size_t)L_SEQ * NKV];
__device__ __nv_bfloat16 g_kl [(size_t)L_SEQ * NKV];
__device__ __nv_bfloat16 g_vh [(size_t)L_SEQ * NKV];
__device__ __nv_bfloat16 g_vl [(size_t)L_SEQ * NKV];

// ---------------- split kernel: fp32 -> (hi, lo) bf16 ----------------
__global__ __launch_bounds__(256) void split_kernel(
    const float* __restrict__ in, __nv_bfloat16* __restrict__ hi,
    __nv_bfloat16* __restrict__ lo, size_t n4)
{
    size_t i = (size_t)blockIdx.x * blockDim.x + threadIdx.x;
    size_t stride = (size_t)gridDim.x * blockDim.x;
    for (; i < n4; i += stride) {
        float4 v = reinterpret_cast<const float4*>(in)[i];
        __nv_bfloat16 h0 = __float2bfloat16(v.x), h1 = __float2bfloat16(v.y);
        __nv_bfloat16 h2 = __float2bfloat16(v.z), h3 = __float2bfloat16(v.w);
        __nv_bfloat16 l0 = __float2bfloat16(v.x - __bfloat162float(h0));
        __nv_bfloat16 l1 = __float2bfloat16(v.y - __bfloat162float(h1));
        __nv_bfloat16 l2 = __float2bfloat16(v.z - __bfloat162float(h2));
        __nv_bfloat16 l3 = __float2bfloat16(v.w - __bfloat162float(h3));
        __nv_bfloat162 hp0{h0, h1}, hp1{h2, h3}, lp0{l0, l1}, lp1{l2, l3};
        reinterpret_cast<__nv_bfloat162*>(hi)[i*2]   = hp0;
        reinterpret_cast<__nv_bfloat162*>(hi)[i*2+1] = hp1;
        reinterpret_cast<__nv_bfloat162*>(lo)[i*2]   = lp0;
        reinterpret_cast<__nv_bfloat162*>(lo)[i*2+1] = lp1;
    }
}

// ---------------- transpose + split: W[K][N] fp32 -> Wt hi/lo [N][K] bf16 ----------------
__global__ __launch_bounds__(256) void transpose_split_kernel(
    const float* __restrict__ W, __nv_bfloat16* __restrict__ Th,
    __nv_bfloat16* __restrict__ Tl, int Kdim, int Ndim)
{
    __shared__ float tile[32][33];
    int n0 = blockIdx.x * 32;
    int k0 = blockIdx.y * 32;
    int tx = threadIdx.x & 31;
    int ty = threadIdx.x >> 5;
#pragma unroll
    for (int r = 0; r < 4; r++)
        tile[ty + 8*r][tx] = W[(size_t)(k0 + ty + 8*r) * Ndim + n0 + tx];
    __syncthreads();
#pragma unroll
    for (int r = 0; r < 4; r++) {
        float v = tile[tx][ty + 8*r];
        __nv_bfloat16 h = __float2bfloat16(v);
        __nv_bfloat16 l = __float2bfloat16(v - __bfloat162float(h));
        size_t o = (size_t)(n0 + ty + 8*r) * Kdim + k0 + tx;
        Th[o] = h; Tl[o] = l;
    }
}

// ---------------- transpose + split: W[K][N] fp32 -> Wt hi/lo [N][K] fp16 ----------------
__global__ __launch_bounds__(256) void transpose_split_h_kernel(
    const float* __restrict__ W, __half* __restrict__ Th,
    __half* __restrict__ Tl, int Kdim, int Ndim)
{
    __shared__ float tile[32][33];
    int n0 = blockIdx.x * 32;
    int k0 = blockIdx.y * 32;
    int tx = threadIdx.x & 31;
    int ty = threadIdx.x >> 5;
#pragma unroll
    for (int r = 0; r < 4; r++)
        tile[ty + 8*r][tx] = W[(size_t)(k0 + ty + 8*r) * Ndim + n0 + tx];
    __syncthreads();
#pragma unroll
    for (int r = 0; r < 4; r++) {
        float v = tile[tx][ty + 8*r];
        __half h = __float2half_rn(v);
        __half l = __float2half_rn(v - __half2float(h));
        size_t o = (size_t)(n0 + ty + 8*r) * Kdim + k0 + tx;
        Th[o] = h; Tl[o] = l;
    }
}

// ---------------- warp-mma split-bf16 GEMM (v1, proven: 128x128, 2-stage) ----------------
#define GBK 32
#define NCHUNK (IDIM / GBK)            // 64
#define RS 80                          // smem row stride bytes (conflict-free ldsm)
#define MAT_BYTES (128 * RS)           // 10240
#define STAGE_BYTES (4 * MAT_BYTES)    // 40960 (Ah, Al, Bh, Bl)
#define GEMM_SMEM (2 * STAGE_BYTES)    // 81920 -> 2 CTAs/SM

__global__ __launch_bounds__(256) void mma_gemm(
    const __nv_bfloat16* __restrict__ Ah, const __nv_bfloat16* __restrict__ Al,
    const __nv_bfloat16* __restrict__ Bh, const __nv_bfloat16* __restrict__ Bl,
    float* __restrict__ C, int N)
{
    extern __shared__ char smem[];
    const uint32_t sb = smem_to_u32(smem);

    const int tid  = threadIdx.x;
    const int lane = tid & 31;
    const int wid  = tid >> 5;
    const int wm   = wid & 1;
    const int wn   = wid >> 1;
    const int m0   = blockIdx.y * 128;
    const int n0   = blockIdx.x * 128;

    const int mat  = tid >> 6;
    const int lidx = tid & 63;
    const __nv_bfloat16* gbase = (mat == 0) ? Ah : (mat == 1) ? Al : (mat == 2) ? Bh : Bl;
    const int grow0 = (mat < 2) ? m0 : n0;
    const uint32_t smat = sb + mat * MAT_BYTES;

    auto issue_loads = [&](int chunk) {
        const int stage = chunk & 1;
        const uint32_t sdst0 = smat + stage * STAGE_BYTES;
        const __nv_bfloat16* src0 = gbase + (size_t)grow0 * IDIM + chunk * GBK;
#pragma unroll
        for (int j = 0; j < 8; j++) {
            int idx = lidx + 64 * j;
            int row = idx >> 2;
            int c   = idx & 3;
            cp_async16(sdst0 + row * RS + c * 16,
                       src0 + (size_t)row * IDIM + c * 8);
        }
    };

    float acc[4][4][4];
#pragma unroll
    for (int mi = 0; mi < 4; mi++)
#pragma unroll
        for (int ni = 0; ni < 4; ni++)
#pragma unroll
            for (int r = 0; r < 4; r++) acc[mi][ni][r] = 0.0f;

    const uint32_t a_row = wm * 64 + (lane & 15);
    const uint32_t b_row = wn * 32 + (lane & 15);
    const uint32_t colb  = (lane >> 4) * 16;

    issue_loads(0); CP_COMMIT();

    for (int i = 0; i < NCHUNK; i++) {
        const int stage = i & 1;
        if (i + 1 < NCHUNK) { issue_loads(i + 1); CP_COMMIT(); CP_WAIT1(); }
        else                { CP_WAIT0(); }
        __syncthreads();

        const uint32_t sAh = sb + stage * STAGE_BYTES;
        const uint32_t sAl = sAh + MAT_BYTES;
        const uint32_t sBh = sAh + 2 * MAT_BYTES;
        const uint32_t sBl = sAh + 3 * MAT_BYTES;

#pragma unroll
        for (int ks = 0; ks < 2; ks++) {
            const uint32_t kb = ks * 32 + colb;
            uint32_t ah[4][4], al[4][4], bh[2][4], bl[2][4];
#pragma unroll
            for (int mi = 0; mi < 4; mi++) {
                uint32_t ro = (a_row + mi * 16) * RS + kb;
                ldsm_x4(ah[mi], sAh + ro);
                ldsm_x4(al[mi], sAl + ro);
            }
#pragma unroll
            for (int nt = 0; nt < 2; nt++) {
                uint32_t ro = (b_row + nt * 16) * RS + kb;
                ldsm_x4(bh[nt], sBh + ro);
                ldsm_x4(bl[nt], sBl + ro);
            }
#pragma unroll
            for (int mi = 0; mi < 4; mi++) {
#pragma unroll
                for (int ni = 0; ni < 4; ni++) {
                    const int nt = ni >> 1, sub = ni & 1;
                    mma16816(acc[mi][ni], ah[mi], bh[nt][sub], bh[nt][2 + sub]);
                    mma16816(acc[mi][ni], ah[mi], bl[nt][sub], bl[nt][2 + sub]);
                    mma16816(acc[mi][ni], al[mi], bh[nt][sub], bh[nt][2 + sub]);
                }
            }
        }
        __syncthreads();
    }

    const int er = lane >> 2;
    const int ec = (lane & 3) * 2;
#pragma unroll
    for (int mi = 0; mi < 4; mi++) {
#pragma unroll
        for (int ni = 0; ni < 4; ni++) {
            int row = m0 + wm * 64 + mi * 16 + er;
            int col = n0 + wn * 32 + ni * 8 + ec;
            *reinterpret_cast<float2*>(&C[(size_t)row * N + col]) =
                make_float2(acc[mi][ni][0], acc[mi][ni][1]);
            *reinterpret_cast<float2*>(&C[(size_t)(row + 8) * N + col]) =
                make_float2(acc[mi][ni][2], acc[mi][ni][3]);
        }
    }
}

// ---------------- 2-term fp16 GEMM: C = A(fp16) @ (Bh+Bl)(fp16)^T ----------------
// block 128x128, same structure; 3 smem matrices per stage.
#define MAT3_STAGE (3 * MAT_BYTES)     // 30720
#define GEMM2_SMEM (2 * MAT3_STAGE)    // 61440 -> 2 CTAs/SM

__global__ __launch_bounds__(256) void mma_gemm2h(
    const __half* __restrict__ A,
    const __half* __restrict__ Bh, const __half* __restrict__ Bl,
    float* __restrict__ C, int N)
{
    extern __shared__ char smem[];
    const uint32_t sb = smem_to_u32(smem);

    const int tid  = threadIdx.x;
    const int lane = tid & 31;
    const int wid  = tid >> 5;
    const int wm   = wid & 1;
    const int wn   = wid >> 1;
    const int m0   = blockIdx.y * 128;
    const int n0   = blockIdx.x * 128;

    auto issue_loads = [&](int chunk) {
        const int stage = chunk & 1;
        const uint32_t s0 = sb + stage * MAT3_STAGE;
#pragma unroll
        for (int j = 0; j < 6; j++) {
            int idx = tid + 256 * j;          // 0..1535
            int mat = idx >> 9;               // 0=A,1=Bh,2=Bl
            int wi  = idx & 511;
            int row = wi >> 2;
            int c   = wi & 3;
            const __half* gp = (mat == 0) ? A + (size_t)(m0 + row) * IDIM
                              : (mat == 1) ? Bh + (size_t)(n0 + row) * IDIM
                                           : Bl + (size_t)(n0 + row) * IDIM;
            cp_async16(s0 + mat * MAT_BYTES + row * RS + c * 16,
                       gp + chunk * GBK + c * 8);
        }
    };

    float acc[4][4][4];
#pragma unroll
    for (int mi = 0; mi < 4; mi++)
#pragma unroll
        for (int ni = 0; ni < 4; ni++)
#pragma unroll
            for (int r = 0; r < 4; r++) acc[mi][ni][r] = 0.0f;

    const uint32_t a_row = wm * 64 + (lane & 15);
    const uint32_t b_row = wn * 32 + (lane & 15);
    const uint32_t colb  = (lane >> 4) * 16;

    issue_loads(0); CP_COMMIT();

    for (int i = 0; i < NCHUNK; i++) {
        const int stage = i & 1;
        if (i + 1 < NCHUNK) { issue_loads(i + 1); CP_COMMIT(); CP_WAIT1(); }
        else                { CP_WAIT0(); }
        __syncthreads();

        const uint32_t sA  = sb + stage * MAT3_STAGE;
        const uint32_t sBh = sA + MAT_BYTES;
        const uint32_t sBl = sA + 2 * MAT_BYTES;

#pragma unroll
        for (int ks = 0; ks < 2; ks++) {
            const uint32_t kb = ks * 32 + colb;
            uint32_t a[4][4], bh[2][4], bl[2][4];
#pragma unroll
            for (int mi = 0; mi < 4; mi++)
                ldsm_x4(a[mi], sA + (a_row + mi * 16) * RS + kb);
#pragma unroll
            for (int nt = 0; nt < 2; nt++) {
                uint32_t ro = (b_row + nt * 16) * RS + kb;
                ldsm_x4(bh[nt], sBh + ro);
                ldsm_x4(bl[nt], sBl + ro);
            }
#pragma unroll
            for (int mi = 0; mi < 4; mi++) {
#pragma unroll
                for (int ni = 0; ni < 4; ni++) {
                    const int nt = ni >> 1, sub = ni & 1;
                    mma16816h(acc[mi][ni], a[mi], bh[nt][sub], bh[nt][2 + sub]);
                    mma16816h(acc[mi][ni], a[mi], bl[nt][sub], bl[nt][2 + sub]);
                }
            }
        }
        __syncthreads();
    }

    const int er = lane >> 2;
    const int ec = (lane & 3) * 2;
#pragma unroll
    for (int mi = 0; mi < 4; mi++) {
#pragma unroll
        for (int ni = 0; ni < 4; ni++) {
            int row = m0 + wm * 64 + mi * 16 + er;
            int col = n0 + wn * 32 + ni * 8 + ec;
            *reinterpret_cast<float2*>(&C[(size_t)row * N + col]) =
                make_float2(acc[mi][ni][0], acc[mi][ni][1]);
            *reinterpret_cast<float2*>(&C[(size_t)(row + 8) * N + col]) =
                make_float2(acc[mi][ni][2], acc[mi][ni][3]);
        }
    }
}

// ---------------- RMSNorm + RoPE for Q -> bf16 hi/lo (pre-scaled) + gate ----------------
__global__ __launch_bounds__(256) void qnorm_rope_kernel(
    const float* __restrict__ cosb, const float* __restrict__ sinb,
    const float* __restrict__ gamma)
{
    const int l = blockIdx.x;
    const int h = blockIdx.y;
    const int d = threadIdx.x;
    const float* row = g_qraw + (size_t)l * (ODIM * 2) + h * 512;
    float v  = row[d];
    float gv = row[256 + d];

    float s = v * v;
#pragma unroll
    for (int o = 16; o > 0; o >>= 1) s += __shfl_xor_sync(0xffffffffu, s, o);
    __shared__ float wsum[8];
    __shared__ float sh[256];
    if ((d & 31) == 0) wsum[d >> 5] = s;
    __syncthreads();
    float tot = 0.0f;
#pragma unroll
    for (int w = 0; w < 8; w++) tot += wsum[w];
    float rstd = rsqrtf(tot * (1.0f / 256.0f) + 1e-6f);
    float y = v * rstd * gamma[d];
    sh[d] = y;
    __syncthreads();
    float out = y;
    if (d < ROPED) {
        float rot = (d < ROPED / 2) ? -sh[d + ROPED / 2] : sh[d - ROPED / 2];
        out = y * cosb[(size_t)l * ROPED + d] + rot * sinb[(size_t)l * ROPED + d];
    }
    float q = out * QSCALE;
    __nv_bfloat16 qh = __float2bfloat16(q);
    __nv_bfloat16 ql = __float2bfloat16(q - __bfloat162float(qh));
    size_t o = (size_t)l * ODIM + h * HDIM + d;
    g_qh[o] = qh; g_ql[o] = ql;
    g_gate[o] = gv;
}

// ---------------- RMSNorm + RoPE for K + V split (fused, reads fused KV buffer) ----------------
__global__ __launch_bounds__(256) void knorm_rope_vsplit_kernel(
    const float* __restrict__ cosb, const float* __restrict__ sinb,
    const float* __restrict__ gamma)
{
    const int l = blockIdx.x;
    const int g = blockIdx.y;
    const int d = threadIdx.x;
    float v  = g_kvraw[(size_t)l * 1024 + g * HDIM + d];
    float vv = g_kvraw[(size_t)l * 1024 + 512 + g * HDIM + d];

    float s = v * v;
#pragma unroll
    for (int o = 16; o > 0; o >>= 1) s += __shfl_xor_sync(0xffffffffu, s, o);
    __shared__ float wsum[8];
    __shared__ float sh[256];
    if ((d & 31) == 0) wsum[d >> 5] = s;
    __syncthreads();
    float tot = 0.0f;
#pragma unroll
    for (int w = 0; w < 8; w++) tot += wsum[w];
    float rstd = rsqrtf(tot * (1.0f / 256.0f) + 1e-6f);
    float y = v * rstd * gamma[d];
    sh[d] = y;
    __syncthreads();
    float out = y;
    if (d < ROPED) {
        float rot = (d < ROPED / 2) ? -sh[d + ROPED / 2] : sh[d - ROPED / 2];
        out = y * cosb[(size_t)l * ROPED + d] + rot * sinb[(size_t)l * ROPED + d];
    }
    size_t o = (size_t)l * NKV + g * HDIM + d;
    __nv_bfloat16 kh = __float2bfloat16(out);
    __nv_bfloat16 kl = __float2bfloat16(out - __bfloat162float(kh));
    g_kh[o] = kh; g_kl[o] = kl;
    // fused V split
    __nv_bfloat16 vh = __float2bfloat16(vv);
    __nv_bfloat16 vl = __float2bfloat16(vv - __bfloat162float(vh));
    g_vh[o] = vh; g_vl[o] = vl;
}

// ---------------- MMA flash attention (split-bf16), BR=BC=64, D=256 ----------------
// Pipelined loads: V(i) overlaps S(i)+softmax; K(i+1) overlaps P·V(i).
#define AQH 0
#define AQL 32768
#define AKH 65536
#define AKL 98304
#define AVH 131072
#define AVL 163840
#define ASS 196608
#define SSS 68
#define APH (ASS + 64*SSS*4)
#define APL (APH + 8192)
#define AMR (APL + 8192)
#define ALR (AMR + 256)
#define ACR (ALR + 256)
#define ATT_SMEM (ACR + 256)

__device__ __forceinline__ uint32_t sw512(int row, int g) {
    return (uint32_t)(row * 512 + ((g ^ (row & 7)) << 4));
}
__device__ __forceinline__ uint32_t sw128(int row, int g) {
    return (uint32_t)(row * 128 + ((g ^ (row & 7)) << 4));
}

__global__ __launch_bounds__(256, 1) void attn_mma_kernel()
{
    extern __shared__ char sm[];
    const uint32_t sb = smem_to_u32(sm);
    const int tid  = threadIdx.x;
    const int lane = tid & 31;
    const int wid  = tid >> 5;
    const int qt   = gridDim.x - 1 - blockIdx.x;   // big tiles first
    const int h    = blockIdx.y;
    const int g    = h >> 2;
    const int i0   = qt * 64;

    float* Ss   = reinterpret_cast<float*>(sm + ASS);
    float* mrow = reinterpret_cast<float*>(sm + AMR);
    float* lrow = reinterpret_cast<float*>(sm + ALR);
    float* crow = reinterpret_cast<float*>(sm + ACR);

    auto load_k = [&](int j0) {
        const size_t rbase = ((size_t)j0 * NGROUPS + g) * HDIM;
        const size_t rstr  = (size_t)NGROUPS * HDIM;
#pragma unroll
        for (int i = 0; i < 8; i++) {
            int idx = tid + 256 * i;
            int row = idx >> 5, gr = idx & 31;
            size_t go = (rbase + (size_t)row * rstr) * 2 + gr * 16;
            uint32_t so = sw512(row, gr);
            cp_async16(sb + AKH + so, (const char*)g_kh + go);
            cp_async16(sb + AKL + so, (const char*)g_kl + go);
        }
    };
    auto load_v = [&](int j0) {
        const size_t rbase = ((size_t)j0 * NGROUPS + g) * HDIM;
        const size_t rstr  = (size_t)NGROUPS * HDIM;
#pragma unroll
        for (int i = 0; i < 8; i++) {
            int idx = tid + 256 * i;
            int row = idx >> 5, gr = idx & 31;
            size_t go = (rbase + (size_t)row * rstr) * 2 + gr * 16;
            uint32_t so = sw512(row, gr);
            cp_async16(sb + AVH + so, (const char*)g_vh + go);
            cp_async16(sb + AVL + so, (const char*)g_vl + go);
        }
    };

    {
        const char* qh = (const char*)(g_qh + ((size_t)i0 * NHEADS + h) * HDIM);
        const char* ql = (const char*)(g_ql + ((size_t)i0 * NHEADS + h) * HDIM);
        const size_t rstr = (size_t)NHEADS * HDIM * 2;
#pragma unroll
        for (int i = 0; i < 8; i++) {
            int idx = tid + 256 * i;
            int row = idx >> 5, gr = idx & 31;
            uint32_t so = sw512(row, gr);
            cp_async16(sb + AQH + so, qh + (size_t)row * rstr + gr * 16);
            cp_async16(sb + AQL + so, ql + (size_t)row * rstr + gr * 16);
        }
    }
    CP_COMMIT();
    load_k(0); CP_COMMIT();
    if (tid < 64) { mrow[tid] = -INFINITY; lrow[tid] = 0.0f; }
    load_v(0); CP_COMMIT();

    const int wm = wid & 3;
    const int wn = wid >> 2;
    const int er = lane >> 2;
    const int ec = (lane & 3) * 2;
    const int kgl = lane >> 4;

    float oacc[16][4];
#pragma unroll
    for (int t = 0; t < 16; t++)
#pragma unroll
        for (int r = 0; r < 4; r++) oacc[t][r] = 0.0f;

    for (int j0 = 0; j0 <= i0; j0 += 64) {
        CP_WAIT1();
        __syncthreads();

        float sacc[4][4];
#pragma unroll
        for (int t = 0; t < 4; t++)
#pragma unroll
            for (int r = 0; r < 4; r++) sacc[t][r] = 0.0f;

        const int arow  = wm * 16 + (lane & 15);
        const int brow0 = wn * 32 + (lane & 15);
#pragma unroll 4
        for (int ks = 0; ks < 16; ks++) {
            int kg = ks * 2 + kgl;
            uint32_t ah[4], al[4], bh[2][4], bl[2][4];
            uint32_t ao = sw512(arow, kg);
            ldsm_x4(ah, sb + AQH + ao);
            ldsm_x4(al, sb + AQL + ao);
            uint32_t bo0 = sw512(brow0, kg);
            uint32_t bo1 = sw512(brow0 + 16, kg);
            ldsm_x4(bh[0], sb + AKH + bo0);
            ldsm_x4(bh[1], sb + AKH + bo1);
            ldsm_x4(bl[0], sb + AKL + bo0);
            ldsm_x4(bl[1], sb + AKL + bo1);
#pragma unroll
            for (int nt = 0; nt < 2; nt++)
#pragma unroll
                for (int sub = 0; sub < 2; sub++) {
                    float* d = sacc[nt * 2 + sub];
                    mma16816(d, ah, bh[nt][sub], bh[nt][2 + sub]);
                    mma16816(d, ah, bl[nt][sub], bl[nt][2 + sub]);
                    mma16816(d, al, bh[nt][sub], bh[nt][2 + sub]);
                }
        }
#pragma unroll
        for (int t = 0; t < 4; t++) {
            int col = wn * 32 + (t >> 1) * 16 + (t & 1) * 8 + ec;
            int r0 = wm * 16 + er;
            Ss[r0 * SSS + col]           = sacc[t][0];
            Ss[r0 * SSS + col + 1]       = sacc[t][1];
            Ss[(r0 + 8) * SSS + col]     = sacc[t][2];
            Ss[(r0 + 8) * SSS + col + 1] = sacc[t][3];
        }
        __syncthreads();

        {
            const int row  = tid >> 2;
            const int part = tid & 3;
            int vlim = i0 + row - j0 + 1; if (vlim > 64) vlim = 64;
            float sv[16];
            float mx = -INFINITY;
            const float* srow = &Ss[row * SSS + part * 16];
#pragma unroll
            for (int c = 0; c < 16; c++) {
                int cc = part * 16 + c;
                float v = (cc < vlim) ? srow[c] : -INFINITY;
                sv[c] = v; mx = fmaxf(mx, v);
            }
            mx = fmaxf(mx, __shfl_xor_sync(0xffffffffu, mx, 1));
            mx = fmaxf(mx, __shfl_xor_sync(0xffffffffu, mx, 2));
            float mold = mrow[row];
            float mnew = fmaxf(mold, mx);
            float ls = 0.0f;
#pragma unroll
            for (int c = 0; c < 16; c++) {
                float p = __expf(sv[c] - mnew);
                sv[c] = p; ls += p;
            }
            ls += __shfl_xor_sync(0xffffffffu, ls, 1);
            ls += __shfl_xor_sync(0xffffffffu, ls, 2);
            float corr = __expf(mold - mnew);
            if (part == 0) {
                mrow[row] = mnew;
                lrow[row] = lrow[row] * corr + ls;
                crow[row] = corr;
            }
#pragma unroll
            for (int gs = 0; gs < 2; gs++) {
                uint32_t hw[4], lw[4];
#pragma unroll
                for (int q = 0; q < 4; q++) {
                    float p0 = sv[gs * 8 + q * 2], p1 = sv[gs * 8 + q * 2 + 1];
                    __nv_bfloat16 h0 = __float2bfloat16(p0);
                    __nv_bfloat16 h1 = __float2bfloat16(p1);
                    __nv_bfloat16 l0 = __float2bfloat16(p0 - __bfloat162float(h0));
                    __nv_bfloat16 l1 = __float2bfloat16(p1 - __bfloat162float(h1));
                    hw[q] = pack_bf16x2(h0, h1);
                    lw[q] = pack_bf16x2(l0, l1);
                }
                uint32_t off = sw128(row, part * 2 + gs);
                *reinterpret_cast<uint4*>(sm + APH + off) = make_uint4(hw[0], hw[1], hw[2], hw[3]);
                *reinterpret_cast<uint4*>(sm + APL + off) = make_uint4(lw[0], lw[1], lw[2], lw[3]);
            }
        }
        __syncthreads();          // K buffer now dead; P ready

        if (j0 + 64 <= i0) load_k(j0 + 64);
        CP_COMMIT();
        CP_WAIT1();               // V(j0) ready
        __syncthreads();

        {
            float c0 = crow[wm * 16 + er];
            float c1 = crow[wm * 16 + er + 8];
#pragma unroll
            for (int t = 0; t < 16; t++) {
                oacc[t][0] *= c0; oacc[t][1] *= c0;
                oacc[t][2] *= c1; oacc[t][3] *= c1;
            }
        }
        const int prow = wm * 16 + (lane & 15);
        const int vk   = lane & 15;
        const int vng  = lane >> 4;
#pragma unroll
        for (int ks = 0; ks < 4; ks++) {
            uint32_t ah[4], al[4];
            uint32_t po = sw128(prow, ks * 2 + kgl);
            ldsm_x4(ah, sb + APH + po);
            ldsm_x4(al, sb + APL + po);
            int krow = ks * 16 + vk;
#pragma unroll
            for (int ng = 0; ng < 8; ng++) {
                uint32_t vh[4], vl[4];
                int gv = wn * 16 + ng * 2 + vng;
                uint32_t vo = sw512(krow, gv);
                ldsm_x4_trans(vh, sb + AVH + vo);
                ldsm_x4_trans(vl, sb + AVL + vo);
#pragma unroll
                for (int sub = 0; sub < 2; sub++) {
                    float* d = oacc[ng * 2 + sub];
                    mma16816(d, ah, vh[2 * sub], vh[2 * sub + 1]);
                    mma16816(d, ah, vl[2 * sub], vl[2 * sub + 1]);
                    mma16816(d, al, vh[2 * sub], vh[2 * sub + 1]);
                }
            }
        }
        __syncthreads();

        if (j0 + 64 <= i0) load_v(j0 + 64);
        CP_COMMIT();
    }

    // ---- epilogue: 1/l, sigmoid gate, write single fp16 y ----
    {
        const int r0 = wm * 16 + er;
        const float li0 = 1.0f / lrow[r0];
        const float li1 = 1.0f / lrow[r0 + 8];
        const size_t base0 = (size_t)(i0 + r0) * ODIM + h * HDIM;
        const size_t base1 = (size_t)(i0 + r0 + 8) * ODIM + h * HDIM;
#pragma unroll
        for (int t = 0; t < 16; t++) {
            int col = wn * 128 + (t >> 1) * 16 + (t & 1) * 8 + ec;
            float2 gt0 = *reinterpret_cast<const float2*>(&g_gate[base0 + col]);
            float2 gt1 = *reinterpret_cast<const float2*>(&g_gate[base1 + col]);
            float v00 = oacc[t][0] * li0 * (1.0f / (1.0f + __expf(-gt0.x)));
            float v01 = oacc[t][1] * li0 * (1.0f / (1.0f + __expf(-gt0.y)));
            float v10 = oacc[t][2] * li1 * (1.0f / (1.0f + __expf(-gt1.x)));
            float v11 = oacc[t][3] * li1 * (1.0f / (1.0f + __expf(-gt1.y)));
            *reinterpret_cast<__half2*>(&g_y[base0 + col]) =
                __halves2half2(__float2half_rn(v00), __float2half_rn(v01));
            *reinterpret_cast<__half2*>(&g_y[base1 + col]) =
                __halves2half2(__float2half_rn(v10), __float2half_rn(v11));
        }
    }
}

// ---------------- launch ----------------
extern "C" void kernel_launch(void* const* d_in, const int* in_sizes, int n_in,
                              void* d_out, int out_size)
{
    const float* x    = (const float*)d_in[0];
    const float* cosb = (const float*)d_in[1];
    const float* sinb = (const float*)d_in[2];
    const float* wq   = (const float*)d_in[4];
    const float* wk   = (const float*)d_in[5];
    const float* wv   = (const float*)d_in[6];
    const float* wo   = (const float*)d_in[7];
    const float* qg   = (const float*)d_in[8];
    const float* kg   = (const float*)d_in[9];
    float* out        = (float*)d_out;

    float *p_qraw, *p_kvraw;
    cudaGetSymbolAddress((void**)&p_qraw,  g_qraw);
    cudaGetSymbolAddress((void**)&p_kvraw, g_kvraw);

    __nv_bfloat16 *p_xh, *p_xl, *p_wqh, *p_wql, *p_wkvh, *p_wkvl;
    __half *p_y, *p_woh16, *p_wol16;
    cudaGetSymbolAddress((void**)&p_xh,    g_xh);
    cudaGetSymbolAddress((void**)&p_xl,    g_xl);
    cudaGetSymbolAddress((void**)&p_wqh,   g_wqh);
    cudaGetSymbolAddress((void**)&p_wql,   g_wql);
    cudaGetSymbolAddress((void**)&p_wkvh,  g_wkvh);
    cudaGetSymbolAddress((void**)&p_wkvl,  g_wkvl);
    cudaGetSymbolAddress((void**)&p_y,     g_y);
    cudaGetSymbolAddress((void**)&p_woh16, g_woh16);
    cudaGetSymbolAddress((void**)&p_wol16, g_wol16);

    cudaFuncSetAttribute(mma_gemm, cudaFuncAttributeMaxDynamicSharedMemorySize, GEMM_SMEM);
    cudaFuncSetAttribute(mma_gemm2h, cudaFuncAttributeMaxDynamicSharedMemorySize, GEMM2_SMEM);
    cudaFuncSetAttribute(attn_mma_kernel, cudaFuncAttributeMaxDynamicSharedMemorySize, ATT_SMEM);

    // 0) operand prep
    split_kernel<<<1024, 256>>>(x, p_xh, p_xl, (size_t)L_SEQ * IDIM / 4);
    transpose_split_kernel<<<dim3((ODIM*2)/32, IDIM/32), 256>>>(wq, p_wqh, p_wql, IDIM, ODIM*2);
    transpose_split_kernel<<<dim3(NKV/32, IDIM/32), 256>>>(wk, p_wkvh, p_wkvl, IDIM, NKV);
    transpose_split_kernel<<<dim3(NKV/32, IDIM/32), 256>>>(
        wv, p_wkvh + (size_t)512 * IDIM, p_wkvl + (size_t)512 * IDIM, IDIM, NKV);
    transpose_split_h_kernel<<<dim3(IDIM/32, ODIM/32), 256>>>(wo, p_woh16, p_wol16, ODIM, IDIM);

    // 1) projections: Q (N=4096) and fused KV (N=1024), 3-term bf16
    mma_gemm<<<dim3((ODIM*2)/128, L_SEQ/128), 256, GEMM_SMEM>>>(p_xh, p_xl, p_wqh, p_wql, p_qraw, ODIM*2);
    mma_gemm<<<dim3(1024/128,     L_SEQ/128), 256, GEMM_SMEM>>>(p_xh, p_xl, p_wkvh, p_wkvl, p_kvraw, 1024);

    // 2) norms + RoPE -> bf16 hi/lo; V split fused into knorm
    qnorm_rope_kernel<<<dim3(L_SEQ, NHEADS),  256>>>(cosb, sinb, qg);
    knorm_rope_vsplit_kernel<<<dim3(L_SEQ, NGROUPS), 256>>>(cosb, sinb, kg);

    // 3) MMA flash attention + gating -> single fp16 y (pipelined K/V loads)
    attn_mma_kernel<<<dim3(L_SEQ / 64, NHEADS), 256, ATT_SMEM>>>();

    // 4) output projection: 2-term fp16 (y single, wo hi/lo)
    mma_gemm2h<<<dim3(IDIM/128, L_SEQ/128), 256, GEMM2_SMEM>>>(p_y, p_woh16, p_wol16, out, IDIM);
}

// round 9
// speedup vs baseline: 1.4381x; 1.2673x over previous
#include <cuda_runtime.h>
#include <cuda_bf16.h>
#include <cuda_fp16.h>
#include <math.h>
#include <stdint.h>

// ---------------- problem constants ----------------
#define L_SEQ   4096
#define IDIM    2048
#define NHEADS  8
#define NGROUPS 2
#define HDIM    256
#define ROPED   64
#define ODIM    (NHEADS*HDIM)     // 2048
#define NKV     (NGROUPS*HDIM)    // 512
#define QSCALE  0.0625f           // 256^-0.5

// ---------------- warp-MMA helpers (standard PTX, sm_80+) ----------------
__device__ __forceinline__ void ldsm_x4(uint32_t* r, uint32_t addr) {
    asm volatile("ldmatrix.sync.aligned.m8n8.x4.shared.b16 {%0,%1,%2,%3}, [%4];"
        : "=r"(r[0]), "=r"(r[1]), "=r"(r[2]), "=r"(r[3]) : "r"(addr));
}
__device__ __forceinline__ void ldsm_x4_trans(uint32_t* r, uint32_t addr) {
    asm volatile("ldmatrix.sync.aligned.m8n8.x4.trans.shared.b16 {%0,%1,%2,%3}, [%4];"
        : "=r"(r[0]), "=r"(r[1]), "=r"(r[2]), "=r"(r[3]) : "r"(addr));
}
__device__ __forceinline__ void mma16816h(float* d, const uint32_t* a, uint32_t b0, uint32_t b1) {
    asm volatile("mma.sync.aligned.m16n8k16.row.col.f32.f16.f16.f32 "
        "{%0,%1,%2,%3}, {%4,%5,%6,%7}, {%8,%9}, {%0,%1,%2,%3};"
        : "+f"(d[0]), "+f"(d[1]), "+f"(d[2]), "+f"(d[3])
        : "r"(a[0]), "r"(a[1]), "r"(a[2]), "r"(a[3]), "r"(b0), "r"(b1));
}
__device__ __forceinline__ void cp_async16(uint32_t dst, const void* src) {
    asm volatile("cp.async.cg.shared.global [%0], [%1], 16;" :: "r"(dst), "l"(src));
}
#define CP_COMMIT() asm volatile("cp.async.commit_group;" ::: "memory")
#define CP_WAIT1()  asm volatile("cp.async.wait_group 1;" ::: "memory")
#define CP_WAIT0()  asm volatile("cp.async.wait_group 0;" ::: "memory")

__device__ __forceinline__ uint32_t smem_to_u32(const void* p) {
    uint32_t a;
    asm("{ .reg .u64 t; cvta.to.shared.u64 t, %1; cvt.u32.u64 %0, t; }" : "=r"(a) : "l"(p));
    return a;
}
__device__ __forceinline__ uint32_t pack_h2(__half a, __half b) {
    __half2 t = __halves2half2(a, b);
    return *reinterpret_cast<uint32_t*>(&t);
}

// ---------------- scratch (device globals) ----------------
__device__ float g_qraw [(size_t)L_SEQ * (ODIM*2)];
__device__ float g_gate [(size_t)L_SEQ * ODIM];
__device__ float g_kvraw[(size_t)L_SEQ * 1024];     // cols 0-511 = K, 512-1023 = V

// fp16 operands (all GEMMs 2-term fp16: A single, B hi/lo)
__device__ __half g_x16   [(size_t)L_SEQ * IDIM];
__device__ __half g_wqh16 [(size_t)(ODIM*2) * IDIM];
__device__ __half g_wql16 [(size_t)(ODIM*2) * IDIM];
__device__ __half g_wkvh16[(size_t)1024 * IDIM];    // rows 0-511 wk^T, 512-1023 wv^T
__device__ __half g_wkvl16[(size_t)1024 * IDIM];
__device__ __half g_woh16 [(size_t)IDIM * ODIM];
__device__ __half g_wol16 [(size_t)IDIM * ODIM];
__device__ __half g_y     [(size_t)L_SEQ * ODIM];
// attention operands
__device__ __half g_q16 [(size_t)L_SEQ * ODIM];     // single fp16, pre-scaled
__device__ __half g_kh16[(size_t)L_SEQ * NKV];
__device__ __half g_kl16[(size_t)L_SEQ * NKV];
__device__ __half g_vh16[(size_t)L_SEQ * NKV];
__device__ __half g_vl16[(size_t)L_SEQ * NKV];

// ---------------- cast kernel: fp32 -> fp16 ----------------
__global__ __launch_bounds__(256) void cast_h_kernel(
    const float* __restrict__ in, __half* __restrict__ out, size_t n4)
{
    size_t i = (size_t)blockIdx.x * blockDim.x + threadIdx.x;
    size_t stride = (size_t)gridDim.x * blockDim.x;
    for (; i < n4; i += stride) {
        float4 v = reinterpret_cast<const float4*>(in)[i];
        __half2 a = __halves2half2(__float2half_rn(v.x), __float2half_rn(v.y));
        __half2 b = __halves2half2(__float2half_rn(v.z), __float2half_rn(v.w));
        reinterpret_cast<__half2*>(out)[i*2]   = a;
        reinterpret_cast<__half2*>(out)[i*2+1] = b;
    }
}

// ---------------- transpose + split: W[K][N] fp32 -> Wt hi/lo [N][K] fp16 ----------------
__global__ __launch_bounds__(256) void transpose_split_h_kernel(
    const float* __restrict__ W, __half* __restrict__ Th,
    __half* __restrict__ Tl, int Kdim, int Ndim)
{
    __shared__ float tile[32][33];
    int n0 = blockIdx.x * 32;
    int k0 = blockIdx.y * 32;
    int tx = threadIdx.x & 31;
    int ty = threadIdx.x >> 5;
#pragma unroll
    for (int r = 0; r < 4; r++)
        tile[ty + 8*r][tx] = W[(size_t)(k0 + ty + 8*r) * Ndim + n0 + tx];
    __syncthreads();
#pragma unroll
    for (int r = 0; r < 4; r++) {
        float v = tile[tx][ty + 8*r];
        __half h = __float2half_rn(v);
        __half l = __float2half_rn(v - __half2float(h));
        size_t o = (size_t)(n0 + ty + 8*r) * Kdim + k0 + tx;
        Th[o] = h; Tl[o] = l;
    }
}

// ---------------- 2-term fp16 GEMM: C = A(fp16) @ (Bh+Bl)(fp16)^T ----------------
// block 128x128, 8 warps (2M x 4N), warp 64x32, BK=32, 2-stage cp.async, 2 CTAs/SM.
#define GBK 32
#define NCHUNK (IDIM / GBK)            // 64
#define RS 80                          // smem row stride bytes
#define MAT_BYTES (128 * RS)           // 10240
#define MAT3_STAGE (3 * MAT_BYTES)     // 30720
#define GEMM2_SMEM (2 * MAT3_STAGE)    // 61440

__global__ __launch_bounds__(256) void mma_gemm2h(
    const __half* __restrict__ A,
    const __half* __restrict__ Bh, const __half* __restrict__ Bl,
    float* __restrict__ C, int N)
{
    extern __shared__ char smem[];
    const uint32_t sb = smem_to_u32(smem);

    const int tid  = threadIdx.x;
    const int lane = tid & 31;
    const int wid  = tid >> 5;
    const int wm   = wid & 1;
    const int wn   = wid >> 1;
    const int m0   = blockIdx.y * 128;
    const int n0   = blockIdx.x * 128;

    auto issue_loads = [&](int chunk) {
        const int stage = chunk & 1;
        const uint32_t s0 = sb + stage * MAT3_STAGE;
#pragma unroll
        for (int j = 0; j < 6; j++) {
            int idx = tid + 256 * j;          // 0..1535
            int mat = idx >> 9;               // 0=A,1=Bh,2=Bl
            int wi  = idx & 511;
            int row = wi >> 2;
            int c   = wi & 3;
            const __half* gp = (mat == 0) ? A + (size_t)(m0 + row) * IDIM
                              : (mat == 1) ? Bh + (size_t)(n0 + row) * IDIM
                                           : Bl + (size_t)(n0 + row) * IDIM;
            cp_async16(s0 + mat * MAT_BYTES + row * RS + c * 16,
                       gp + chunk * GBK + c * 8);
        }
    };

    float acc[4][4][4];
#pragma unroll
    for (int mi = 0; mi < 4; mi++)
#pragma unroll
        for (int ni = 0; ni < 4; ni++)
#pragma unroll
            for (int r = 0; r < 4; r++) acc[mi][ni][r] = 0.0f;

    const uint32_t a_row = wm * 64 + (lane & 15);
    const uint32_t b_row = wn * 32 + (lane & 15);
    const uint32_t colb  = (lane >> 4) * 16;

    issue_loads(0); CP_COMMIT();

    for (int i = 0; i < NCHUNK; i++) {
        const int stage = i & 1;
        if (i + 1 < NCHUNK) { issue_loads(i + 1); CP_COMMIT(); CP_WAIT1(); }
        else                { CP_WAIT0(); }
        __syncthreads();

        const uint32_t sA  = sb + stage * MAT3_STAGE;
        const uint32_t sBh = sA + MAT_BYTES;
        const uint32_t sBl = sA + 2 * MAT_BYTES;

#pragma unroll
        for (int ks = 0; ks < 2; ks++) {
            const uint32_t kb = ks * 32 + colb;
            uint32_t a[4][4], bh[2][4], bl[2][4];
#pragma unroll
            for (int mi = 0; mi < 4; mi++)
                ldsm_x4(a[mi], sA + (a_row + mi * 16) * RS + kb);
#pragma unroll
            for (int nt = 0; nt < 2; nt++) {
                uint32_t ro = (b_row + nt * 16) * RS + kb;
                ldsm_x4(bh[nt], sBh + ro);
                ldsm_x4(bl[nt], sBl + ro);
            }
#pragma unroll
            for (int mi = 0; mi < 4; mi++) {
#pragma unroll
                for (int ni = 0; ni < 4; ni++) {
                    const int nt = ni >> 1, sub = ni & 1;
                    mma16816h(acc[mi][ni], a[mi], bh[nt][sub], bh[nt][2 + sub]);
                    mma16816h(acc[mi][ni], a[mi], bl[nt][sub], bl[nt][2 + sub]);
                }
            }
        }
        __syncthreads();
    }

    const int er = lane >> 2;
    const int ec = (lane & 3) * 2;
#pragma unroll
    for (int mi = 0; mi < 4; mi++) {
#pragma unroll
        for (int ni = 0; ni < 4; ni++) {
            int row = m0 + wm * 64 + mi * 16 + er;
            int col = n0 + wn * 32 + ni * 8 + ec;
            *reinterpret_cast<float2*>(&C[(size_t)row * N + col]) =
                make_float2(acc[mi][ni][0], acc[mi][ni][1]);
            *reinterpret_cast<float2*>(&C[(size_t)(row + 8) * N + col]) =
                make_float2(acc[mi][ni][2], acc[mi][ni][3]);
        }
    }
}

// ---------------- RMSNorm + RoPE for Q -> single fp16 (pre-scaled) + gate ----------------
__global__ __launch_bounds__(256) void qnorm_rope_kernel(
    const float* __restrict__ cosb, const float* __restrict__ sinb,
    const float* __restrict__ gamma)
{
    const int l = blockIdx.x;
    const int h = blockIdx.y;
    const int d = threadIdx.x;
    const float* row = g_qraw + (size_t)l * (ODIM * 2) + h * 512;
    float v  = row[d];
    float gv = row[256 + d];

    float s = v * v;
#pragma unroll
    for (int o = 16; o > 0; o >>= 1) s += __shfl_xor_sync(0xffffffffu, s, o);
    __shared__ float wsum[8];
    __shared__ float sh[256];
    if ((d & 31) == 0) wsum[d >> 5] = s;
    __syncthreads();
    float tot = 0.0f;
#pragma unroll
    for (int w = 0; w < 8; w++) tot += wsum[w];
    float rstd = rsqrtf(tot * (1.0f / 256.0f) + 1e-6f);
    float y = v * rstd * gamma[d];
    sh[d] = y;
    __syncthreads();
    float out = y;
    if (d < ROPED) {
        float rot = (d < ROPED / 2) ? -sh[d + ROPED / 2] : sh[d - ROPED / 2];
        out = y * cosb[(size_t)l * ROPED + d] + rot * sinb[(size_t)l * ROPED + d];
    }
    size_t o = (size_t)l * ODIM + h * HDIM + d;
    g_q16[o]  = __float2half_rn(out * QSCALE);
    g_gate[o] = gv;
}

// ---------------- RMSNorm + RoPE for K + V split -> fp16 hi/lo ----------------
__global__ __launch_bounds__(256) void knorm_rope_vsplit_kernel(
    const float* __restrict__ cosb, const float* __restrict__ sinb,
    const float* __restrict__ gamma)
{
    const int l = blockIdx.x;
    const int g = blockIdx.y;
    const int d = threadIdx.x;
    float v  = g_kvraw[(size_t)l * 1024 + g * HDIM + d];
    float vv = g_kvraw[(size_t)l * 1024 + 512 + g * HDIM + d];

    float s = v * v;
#pragma unroll
    for (int o = 16; o > 0; o >>= 1) s += __shfl_xor_sync(0xffffffffu, s, o);
    __shared__ float wsum[8];
    __shared__ float sh[256];
    if ((d & 31) == 0) wsum[d >> 5] = s;
    __syncthreads();
    float tot = 0.0f;
#pragma unroll
    for (int w = 0; w < 8; w++) tot += wsum[w];
    float rstd = rsqrtf(tot * (1.0f / 256.0f) + 1e-6f);
    float y = v * rstd * gamma[d];
    sh[d] = y;
    __syncthreads();
    float out = y;
    if (d < ROPED) {
        float rot = (d < ROPED / 2) ? -sh[d + ROPED / 2] : sh[d - ROPED / 2];
        out = y * cosb[(size_t)l * ROPED + d] + rot * sinb[(size_t)l * ROPED + d];
    }
    size_t o = (size_t)l * NKV + g * HDIM + d;
    __half kh = __float2half_rn(out);
    __half kl = __float2half_rn(out - __half2float(kh));
    g_kh16[o] = kh; g_kl16[o] = kl;
    __half vh = __float2half_rn(vv);
    __half vl = __float2half_rn(vv - __half2float(vh));
    g_vh16[o] = vh; g_vl16[o] = vl;
}

// ---------------- MMA flash attention (2-term fp16), BR=BC=64, D=256 ----------------
// Q single fp16, K hi/lo; P single fp16, V hi/lo. Pipelined loads.
#define AQ  0
#define AKH 32768
#define AKL 65536
#define AVH 98304
#define AVL 131072
#define ASS 163840
#define SSS 68
#define AP  (ASS + 64*SSS*4)      // 181248
#define AMR (AP + 8192)            // 189440
#define ALR (AMR + 256)
#define ACR (ALR + 256)
#define ATT_SMEM (ACR + 256)       // 190208

__device__ __forceinline__ uint32_t sw512(int row, int g) {
    return (uint32_t)(row * 512 + ((g ^ (row & 7)) << 4));
}
__device__ __forceinline__ uint32_t sw128(int row, int g) {
    return (uint32_t)(row * 128 + ((g ^ (row & 7)) << 4));
}

__global__ __launch_bounds__(256, 1) void attn_mma_kernel()
{
    extern __shared__ char sm[];
    const uint32_t sb = smem_to_u32(sm);
    const int tid  = threadIdx.x;
    const int lane = tid & 31;
    const int wid  = tid >> 5;
    const int qt   = gridDim.x - 1 - blockIdx.x;   // big tiles first
    const int h    = blockIdx.y;
    const int g    = h >> 2;
    const int i0   = qt * 64;

    float* Ss   = reinterpret_cast<float*>(sm + ASS);
    float* mrow = reinterpret_cast<float*>(sm + AMR);
    float* lrow = reinterpret_cast<float*>(sm + ALR);
    float* crow = reinterpret_cast<float*>(sm + ACR);

    auto load_k = [&](int j0) {
        const size_t rbase = ((size_t)j0 * NGROUPS + g) * HDIM;
        const size_t rstr  = (size_t)NGROUPS * HDIM;
#pragma unroll
        for (int i = 0; i < 8; i++) {
            int idx = tid + 256 * i;
            int row = idx >> 5, gr = idx & 31;
            size_t go = (rbase + (size_t)row * rstr) * 2 + gr * 16;
            uint32_t so = sw512(row, gr);
            cp_async16(sb + AKH + so, (const char*)g_kh16 + go);
            cp_async16(sb + AKL + so, (const char*)g_kl16 + go);
        }
    };
    auto load_v = [&](int j0) {
        const size_t rbase = ((size_t)j0 * NGROUPS + g) * HDIM;
        const size_t rstr  = (size_t)NGROUPS * HDIM;
#pragma unroll
        for (int i = 0; i < 8; i++) {
            int idx = tid + 256 * i;
            int row = idx >> 5, gr = idx & 31;
            size_t go = (rbase + (size_t)row * rstr) * 2 + gr * 16;
            uint32_t so = sw512(row, gr);
            cp_async16(sb + AVH + so, (const char*)g_vh16 + go);
            cp_async16(sb + AVL + so, (const char*)g_vl16 + go);
        }
    };

    // ---- prolog: Q (single), K(0), V(0) ----
    {
        const char* q16 = (const char*)(g_q16 + ((size_t)i0 * NHEADS + h) * HDIM);
        const size_t rstr = (size_t)NHEADS * HDIM * 2;
#pragma unroll
        for (int i = 0; i < 8; i++) {
            int idx = tid + 256 * i;
            int row = idx >> 5, gr = idx & 31;
            cp_async16(sb + AQ + sw512(row, gr), q16 + (size_t)row * rstr + gr * 16);
        }
    }
    CP_COMMIT();
    load_k(0); CP_COMMIT();
    if (tid < 64) { mrow[tid] = -INFINITY; lrow[tid] = 0.0f; }
    load_v(0); CP_COMMIT();

    const int wm = wid & 3;
    const int wn = wid >> 2;
    const int er = lane >> 2;
    const int ec = (lane & 3) * 2;
    const int kgl = lane >> 4;

    float oacc[16][4];
#pragma unroll
    for (int t = 0; t < 16; t++)
#pragma unroll
        for (int r = 0; r < 4; r++) oacc[t][r] = 0.0f;

    for (int j0 = 0; j0 <= i0; j0 += 64) {
        CP_WAIT1();                // Q (+K) ready
        __syncthreads();

        // ---- S = Q K^T (2-term) ----
        float sacc[4][4];
#pragma unroll
        for (int t = 0; t < 4; t++)
#pragma unroll
            for (int r = 0; r < 4; r++) sacc[t][r] = 0.0f;

        const int arow  = wm * 16 + (lane & 15);
        const int brow0 = wn * 32 + (lane & 15);
#pragma unroll 4
        for (int ks = 0; ks < 16; ks++) {
            int kg = ks * 2 + kgl;
            uint32_t a[4], bh[2][4], bl[2][4];
            ldsm_x4(a, sb + AQ + sw512(arow, kg));
            uint32_t bo0 = sw512(brow0, kg);
            uint32_t bo1 = sw512(brow0 + 16, kg);
            ldsm_x4(bh[0], sb + AKH + bo0);
            ldsm_x4(bh[1], sb + AKH + bo1);
            ldsm_x4(bl[0], sb + AKL + bo0);
            ldsm_x4(bl[1], sb + AKL + bo1);
#pragma unroll
            for (int nt = 0; nt < 2; nt++)
#pragma unroll
                for (int sub = 0; sub < 2; sub++) {
                    float* d = sacc[nt * 2 + sub];
                    mma16816h(d, a, bh[nt][sub], bh[nt][2 + sub]);
                    mma16816h(d, a, bl[nt][sub], bl[nt][2 + sub]);
                }
        }
#pragma unroll
        for (int t = 0; t < 4; t++) {
            int col = wn * 32 + (t >> 1) * 16 + (t & 1) * 8 + ec;
            int r0 = wm * 16 + er;
            Ss[r0 * SSS + col]           = sacc[t][0];
            Ss[r0 * SSS + col + 1]       = sacc[t][1];
            Ss[(r0 + 8) * SSS + col]     = sacc[t][2];
            Ss[(r0 + 8) * SSS + col + 1] = sacc[t][3];
        }
        __syncthreads();

        // ---- online softmax + P fp16 (4 threads / row) ----
        {
            const int row  = tid >> 2;
            const int part = tid & 3;
            int vlim = i0 + row - j0 + 1; if (vlim > 64) vlim = 64;
            float sv[16];
            float mx = -INFINITY;
            const float* srow = &Ss[row * SSS + part * 16];
#pragma unroll
            for (int c = 0; c < 16; c++) {
                int cc = part * 16 + c;
                float v = (cc < vlim) ? srow[c] : -INFINITY;
                sv[c] = v; mx = fmaxf(mx, v);
            }
            mx = fmaxf(mx, __shfl_xor_sync(0xffffffffu, mx, 1));
            mx = fmaxf(mx, __shfl_xor_sync(0xffffffffu, mx, 2));
            float mold = mrow[row];
            float mnew = fmaxf(mold, mx);
            float ls = 0.0f;
#pragma unroll
            for (int c = 0; c < 16; c++) {
                float p = __expf(sv[c] - mnew);
                sv[c] = p; ls += p;
            }
            ls += __shfl_xor_sync(0xffffffffu, ls, 1);
            ls += __shfl_xor_sync(0xffffffffu, ls, 2);
            float corr = __expf(mold - mnew);
            if (part == 0) {
                mrow[row] = mnew;
                lrow[row] = lrow[row] * corr + ls;
                crow[row] = corr;
            }
#pragma unroll
            for (int gs = 0; gs < 2; gs++) {
                uint32_t hw[4];
#pragma unroll
                for (int q = 0; q < 4; q++)
                    hw[q] = pack_h2(__float2half_rn(sv[gs * 8 + q * 2]),
                                    __float2half_rn(sv[gs * 8 + q * 2 + 1]));
                *reinterpret_cast<uint4*>(sm + AP + sw128(row, part * 2 + gs)) =
                    make_uint4(hw[0], hw[1], hw[2], hw[3]);
            }
        }
        __syncthreads();          // K buffer dead; P ready

        if (j0 + 64 <= i0) load_k(j0 + 64);
        CP_COMMIT();
        CP_WAIT1();               // V(j0) ready
        __syncthreads();

        // ---- rescale O, then O += P V (2-term) ----
        {
            float c0 = crow[wm * 16 + er];
            float c1 = crow[wm * 16 + er + 8];
#pragma unroll
            for (int t = 0; t < 16; t++) {
                oacc[t][0] *= c0; oacc[t][1] *= c0;
                oacc[t][2] *= c1; oacc[t][3] *= c1;
            }
        }
        const int prow = wm * 16 + (lane & 15);
        const int vk   = lane & 15;
        const int vng  = lane >> 4;
#pragma unroll
        for (int ks = 0; ks < 4; ks++) {
            uint32_t a[4];
            ldsm_x4(a, sb + AP + sw128(prow, ks * 2 + kgl));
            int krow = ks * 16 + vk;
#pragma unroll
            for (int ng = 0; ng < 8; ng++) {
                uint32_t vh[4], vl[4];
                int gv = wn * 16 + ng * 2 + vng;
                uint32_t vo = sw512(krow, gv);
                ldsm_x4_trans(vh, sb + AVH + vo);
                ldsm_x4_trans(vl, sb + AVL + vo);
#pragma unroll
                for (int sub = 0; sub < 2; sub++) {
                    float* d = oacc[ng * 2 + sub];
                    mma16816h(d, a, vh[2 * sub], vh[2 * sub + 1]);
                    mma16816h(d, a, vl[2 * sub], vl[2 * sub + 1]);
                }
            }
        }
        __syncthreads();          // V buffer dead

        if (j0 + 64 <= i0) load_v(j0 + 64);
        CP_COMMIT();
    }

    // ---- epilogue: 1/l, sigmoid gate, write single fp16 y ----
    {
        const int r0 = wm * 16 + er;
        const float li0 = 1.0f / lrow[r0];
        const float li1 = 1.0f / lrow[r0 + 8];
        const size_t base0 = (size_t)(i0 + r0) * ODIM + h * HDIM;
        const size_t base1 = (size_t)(i0 + r0 + 8) * ODIM + h * HDIM;
#pragma unroll
        for (int t = 0; t < 16; t++) {
            int col = wn * 128 + (t >> 1) * 16 + (t & 1) * 8 + ec;
            float2 gt0 = *reinterpret_cast<const float2*>(&g_gate[base0 + col]);
            float2 gt1 = *reinterpret_cast<const float2*>(&g_gate[base1 + col]);
            float v00 = oacc[t][0] * li0 * (1.0f / (1.0f + __expf(-gt0.x)));
            float v01 = oacc[t][1] * li0 * (1.0f / (1.0f + __expf(-gt0.y)));
            float v10 = oacc[t][2] * li1 * (1.0f / (1.0f + __expf(-gt1.x)));
            float v11 = oacc[t][3] * li1 * (1.0f / (1.0f + __expf(-gt1.y)));
            *reinterpret_cast<__half2*>(&g_y[base0 + col]) =
                __halves2half2(__float2half_rn(v00), __float2half_rn(v01));
            *reinterpret_cast<__half2*>(&g_y[base1 + col]) =
                __halves2half2(__float2half_rn(v10), __float2half_rn(v11));
        }
    }
}

// ---------------- launch ----------------
extern "C" void kernel_launch(void* const* d_in, const int* in_sizes, int n_in,
                              void* d_out, int out_size)
{
    const float* x    = (const float*)d_in[0];
    const float* cosb = (const float*)d_in[1];
    const float* sinb = (const float*)d_in[2];
    const float* wq   = (const float*)d_in[4];
    const float* wk   = (const float*)d_in[5];
    const float* wv   = (const float*)d_in[6];
    const float* wo   = (const float*)d_in[7];
    const float* qg   = (const float*)d_in[8];
    const float* kg   = (const float*)d_in[9];
    float* out        = (float*)d_out;

    float *p_qraw, *p_kvraw;
    cudaGetSymbolAddress((void**)&p_qraw,  g_qraw);
    cudaGetSymbolAddress((void**)&p_kvraw, g_kvraw);

    __half *p_x16, *p_wqh16, *p_wql16, *p_wkvh16, *p_wkvl16, *p_woh16, *p_wol16, *p_y;
    cudaGetSymbolAddress((void**)&p_x16,    g_x16);
    cudaGetSymbolAddress((void**)&p_wqh16,  g_wqh16);
    cudaGetSymbolAddress((void**)&p_wql16,  g_wql16);
    cudaGetSymbolAddress((void**)&p_wkvh16, g_wkvh16);
    cudaGetSymbolAddress((void**)&p_wkvl16, g_wkvl16);
    cudaGetSymbolAddress((void**)&p_woh16,  g_woh16);
    cudaGetSymbolAddress((void**)&p_wol16,  g_wol16);
    cudaGetSymbolAddress((void**)&p_y,      g_y);

    cudaFuncSetAttribute(mma_gemm2h, cudaFuncAttributeMaxDynamicSharedMemorySize, GEMM2_SMEM);
    cudaFuncSetAttribute(attn_mma_kernel, cudaFuncAttributeMaxDynamicSharedMemorySize, ATT_SMEM);

    // 0) operand prep (all fp16)
    cast_h_kernel<<<1024, 256>>>(x, p_x16, (size_t)L_SEQ * IDIM / 4);
    transpose_split_h_kernel<<<dim3((ODIM*2)/32, IDIM/32), 256>>>(wq, p_wqh16, p_wql16, IDIM, ODIM*2);
    transpose_split_h_kernel<<<dim3(NKV/32, IDIM/32), 256>>>(wk, p_wkvh16, p_wkvl16, IDIM, NKV);
    transpose_split_h_kernel<<<dim3(NKV/32, IDIM/32), 256>>>(
        wv, p_wkvh16 + (size_t)512 * IDIM, p_wkvl16 + (size_t)512 * IDIM, IDIM, NKV);
    transpose_split_h_kernel<<<dim3(IDIM/32, ODIM/32), 256>>>(wo, p_woh16, p_wol16, ODIM, IDIM);

    // 1) projections: Q (N=4096) and fused KV (N=1024), 2-term fp16
    mma_gemm2h<<<dim3((ODIM*2)/128, L_SEQ/128), 256, GEMM2_SMEM>>>(p_x16, p_wqh16, p_wql16, p_qraw, ODIM*2);
    mma_gemm2h<<<dim3(1024/128,     L_SEQ/128), 256, GEMM2_SMEM>>>(p_x16, p_wkvh16, p_wkvl16, p_kvraw, 1024);

    // 2) norms + RoPE -> fp16; V split fused
    qnorm_rope_kernel<<<dim3(L_SEQ, NHEADS),  256>>>(cosb, sinb, qg);
    knorm_rope_vsplit_kernel<<<dim3(L_SEQ, NGROUPS), 256>>>(cosb, sinb, kg);

    // 3) MMA flash attention (2-term fp16) + gating -> fp16 y
    attn_mma_kernel<<<dim3(L_SEQ / 64, NHEADS), 256, ATT_SMEM>>>();

    // 4) output projection: 2-term fp16
    mma_gemm2h<<<dim3(IDIM/128, L_SEQ/128), 256, GEMM2_SMEM>>>(p_y, p_woh16, p_wol16, out, IDIM);
}

// round 10
// speedup vs baseline: 1.6667x; 1.1589x over previous
#include <cuda_runtime.h>
#include <cuda_bf16.h>
#include <cuda_fp16.h>
#include <math.h>
#include <stdint.h>

// ---------------- problem constants ----------------
#define L_SEQ   4096
#define IDIM    2048
#define NHEADS  8
#define NGROUPS 2
#define HDIM    256
#define ROPED   64
#define ODIM    (NHEADS*HDIM)     // 2048
#define NKV     (NGROUPS*HDIM)    // 512
#define QSCALE  0.0625f           // 256^-0.5

// ---------------- warp-MMA helpers (standard PTX, sm_80+) ----------------
__device__ __forceinline__ void ldsm_x4(uint32_t* r, uint32_t addr) {
    asm volatile("ldmatrix.sync.aligned.m8n8.x4.shared.b16 {%0,%1,%2,%3}, [%4];"
        : "=r"(r[0]), "=r"(r[1]), "=r"(r[2]), "=r"(r[3]) : "r"(addr));
}
__device__ __forceinline__ void ldsm_x4_trans(uint32_t* r, uint32_t addr) {
    asm volatile("ldmatrix.sync.aligned.m8n8.x4.trans.shared.b16 {%0,%1,%2,%3}, [%4];"
        : "=r"(r[0]), "=r"(r[1]), "=r"(r[2]), "=r"(r[3]) : "r"(addr));
}
__device__ __forceinline__ void mma16816h(float* d, const uint32_t* a, uint32_t b0, uint32_t b1) {
    asm volatile("mma.sync.aligned.m16n8k16.row.col.f32.f16.f16.f32 "
        "{%0,%1,%2,%3}, {%4,%5,%6,%7}, {%8,%9}, {%0,%1,%2,%3};"
        : "+f"(d[0]), "+f"(d[1]), "+f"(d[2]), "+f"(d[3])
        : "r"(a[0]), "r"(a[1]), "r"(a[2]), "r"(a[3]), "r"(b0), "r"(b1));
}
__device__ __forceinline__ void cp_async16(uint32_t dst, const void* src) {
    asm volatile("cp.async.cg.shared.global [%0], [%1], 16;" :: "r"(dst), "l"(src));
}
#define CP_COMMIT() asm volatile("cp.async.commit_group;" ::: "memory")
#define CP_WAIT1()  asm volatile("cp.async.wait_group 1;" ::: "memory")
#define CP_WAIT0()  asm volatile("cp.async.wait_group 0;" ::: "memory")

__device__ __forceinline__ uint32_t smem_to_u32(const void* p) {
    uint32_t a;
    asm("{ .reg .u64 t; cvta.to.shared.u64 t, %1; cvt.u32.u64 %0, t; }" : "=r"(a) : "l"(p));
    return a;
}
__device__ __forceinline__ uint32_t pack_h2(__half a, __half b) {
    __half2 t = __halves2half2(a, b);
    return *reinterpret_cast<uint32_t*>(&t);
}

// ---------------- scratch (device globals) ----------------
__device__ float g_qraw [(size_t)L_SEQ * (ODIM*2)];
__device__ float g_gate [(size_t)L_SEQ * ODIM];
__device__ float g_kvraw[(size_t)L_SEQ * 1024];     // cols 0-511 = K, 512-1023 = V

// fp16 operands (GEMMs 2-term fp16: A single, B hi/lo)
__device__ __half g_x16   [(size_t)L_SEQ * IDIM];
__device__ __half g_wqh16 [(size_t)(ODIM*2) * IDIM];
__device__ __half g_wql16 [(size_t)(ODIM*2) * IDIM];
__device__ __half g_wkvh16[(size_t)1024 * IDIM];    // rows 0-511 wk^T, 512-1023 wv^T
__device__ __half g_wkvl16[(size_t)1024 * IDIM];
__device__ __half g_woh16 [(size_t)IDIM * ODIM];
__device__ __half g_wol16 [(size_t)IDIM * ODIM];
__device__ __half g_y     [(size_t)L_SEQ * ODIM];
// attention operands (all single fp16 now)
__device__ __half g_q16 [(size_t)L_SEQ * ODIM];     // pre-scaled
__device__ __half g_k16 [(size_t)L_SEQ * NKV];
__device__ __half g_v16 [(size_t)L_SEQ * NKV];

// ---------------- cast kernel: fp32 -> fp16 ----------------
__global__ __launch_bounds__(256) void cast_h_kernel(
    const float* __restrict__ in, __half* __restrict__ out, size_t n4)
{
    size_t i = (size_t)blockIdx.x * blockDim.x + threadIdx.x;
    size_t stride = (size_t)gridDim.x * blockDim.x;
    for (; i < n4; i += stride) {
        float4 v = reinterpret_cast<const float4*>(in)[i];
        __half2 a = __halves2half2(__float2half_rn(v.x), __float2half_rn(v.y));
        __half2 b = __halves2half2(__float2half_rn(v.z), __float2half_rn(v.w));
        reinterpret_cast<__half2*>(out)[i*2]   = a;
        reinterpret_cast<__half2*>(out)[i*2+1] = b;
    }
}

// ---------------- transpose + split: W[K][N] fp32 -> Wt hi/lo [N][K] fp16 ----------------
__global__ __launch_bounds__(256) void transpose_split_h_kernel(
    const float* __restrict__ W, __half* __restrict__ Th,
    __half* __restrict__ Tl, int Kdim, int Ndim)
{
    __shared__ float tile[32][33];
    int n0 = blockIdx.x * 32;
    int k0 = blockIdx.y * 32;
    int tx = threadIdx.x & 31;
    int ty = threadIdx.x >> 5;
#pragma unroll
    for (int r = 0; r < 4; r++)
        tile[ty + 8*r][tx] = W[(size_t)(k0 + ty + 8*r) * Ndim + n0 + tx];
    __syncthreads();
#pragma unroll
    for (int r = 0; r < 4; r++) {
        float v = tile[tx][ty + 8*r];
        __half h = __float2half_rn(v);
        __half l = __float2half_rn(v - __half2float(h));
        size_t o = (size_t)(n0 + ty + 8*r) * Kdim + k0 + tx;
        Th[o] = h; Tl[o] = l;
    }
}

// ---------------- 2-term fp16 GEMM: C = A(fp16) @ (Bh+Bl)(fp16)^T ----------------
#define GBK 32
#define NCHUNK (IDIM / GBK)            // 64
#define RS 80                          // smem row stride bytes
#define MAT_BYTES (128 * RS)           // 10240
#define MAT3_STAGE (3 * MAT_BYTES)     // 30720
#define GEMM2_SMEM (2 * MAT3_STAGE)    // 61440

__global__ __launch_bounds__(256) void mma_gemm2h(
    const __half* __restrict__ A,
    const __half* __restrict__ Bh, const __half* __restrict__ Bl,
    float* __restrict__ C, int N)
{
    extern __shared__ char smem[];
    const uint32_t sb = smem_to_u32(smem);

    const int tid  = threadIdx.x;
    const int lane = tid & 31;
    const int wid  = tid >> 5;
    const int wm   = wid & 1;
    const int wn   = wid >> 1;
    const int m0   = blockIdx.y * 128;
    const int n0   = blockIdx.x * 128;

    auto issue_loads = [&](int chunk) {
        const int stage = chunk & 1;
        const uint32_t s0 = sb + stage * MAT3_STAGE;
#pragma unroll
        for (int j = 0; j < 6; j++) {
            int idx = tid + 256 * j;          // 0..1535
            int mat = idx >> 9;               // 0=A,1=Bh,2=Bl
            int wi  = idx & 511;
            int row = wi >> 2;
            int c   = wi & 3;
            const __half* gp = (mat == 0) ? A + (size_t)(m0 + row) * IDIM
                              : (mat == 1) ? Bh + (size_t)(n0 + row) * IDIM
                                           : Bl + (size_t)(n0 + row) * IDIM;
            cp_async16(s0 + mat * MAT_BYTES + row * RS + c * 16,
                       gp + chunk * GBK + c * 8);
        }
    };

    float acc[4][4][4];
#pragma unroll
    for (int mi = 0; mi < 4; mi++)
#pragma unroll
        for (int ni = 0; ni < 4; ni++)
#pragma unroll
            for (int r = 0; r < 4; r++) acc[mi][ni][r] = 0.0f;

    const uint32_t a_row = wm * 64 + (lane & 15);
    const uint32_t b_row = wn * 32 + (lane & 15);
    const uint32_t colb  = (lane >> 4) * 16;

    issue_loads(0); CP_COMMIT();

    for (int i = 0; i < NCHUNK; i++) {
        const int stage = i & 1;
        if (i + 1 < NCHUNK) { issue_loads(i + 1); CP_COMMIT(); CP_WAIT1(); }
        else                { CP_WAIT0(); }
        __syncthreads();

        const uint32_t sA  = sb + stage * MAT3_STAGE;
        const uint32_t sBh = sA + MAT_BYTES;
        const uint32_t sBl = sA + 2 * MAT_BYTES;

#pragma unroll
        for (int ks = 0; ks < 2; ks++) {
            const uint32_t kb = ks * 32 + colb;
            uint32_t a[4][4], bh[2][4], bl[2][4];
#pragma unroll
            for (int mi = 0; mi < 4; mi++)
                ldsm_x4(a[mi], sA + (a_row + mi * 16) * RS + kb);
#pragma unroll
            for (int nt = 0; nt < 2; nt++) {
                uint32_t ro = (b_row + nt * 16) * RS + kb;
                ldsm_x4(bh[nt], sBh + ro);
                ldsm_x4(bl[nt], sBl + ro);
            }
#pragma unroll
            for (int mi = 0; mi < 4; mi++) {
#pragma unroll
                for (int ni = 0; ni < 4; ni++) {
                    const int nt = ni >> 1, sub = ni & 1;
                    mma16816h(acc[mi][ni], a[mi], bh[nt][sub], bh[nt][2 + sub]);
                    mma16816h(acc[mi][ni], a[mi], bl[nt][sub], bl[nt][2 + sub]);
                }
            }
        }
        __syncthreads();
    }

    const int er = lane >> 2;
    const int ec = (lane & 3) * 2;
#pragma unroll
    for (int mi = 0; mi < 4; mi++) {
#pragma unroll
        for (int ni = 0; ni < 4; ni++) {
            int row = m0 + wm * 64 + mi * 16 + er;
            int col = n0 + wn * 32 + ni * 8 + ec;
            *reinterpret_cast<float2*>(&C[(size_t)row * N + col]) =
                make_float2(acc[mi][ni][0], acc[mi][ni][1]);
            *reinterpret_cast<float2*>(&C[(size_t)(row + 8) * N + col]) =
                make_float2(acc[mi][ni][2], acc[mi][ni][3]);
        }
    }
}

// ---------------- RMSNorm + RoPE for Q -> single fp16 (pre-scaled) + gate ----------------
__global__ __launch_bounds__(256) void qnorm_rope_kernel(
    const float* __restrict__ cosb, const float* __restrict__ sinb,
    const float* __restrict__ gamma)
{
    const int l = blockIdx.x;
    const int h = blockIdx.y;
    const int d = threadIdx.x;
    const float* row = g_qraw + (size_t)l * (ODIM * 2) + h * 512;
    float v  = row[d];
    float gv = row[256 + d];

    float s = v * v;
#pragma unroll
    for (int o = 16; o > 0; o >>= 1) s += __shfl_xor_sync(0xffffffffu, s, o);
    __shared__ float wsum[8];
    __shared__ float sh[256];
    if ((d & 31) == 0) wsum[d >> 5] = s;
    __syncthreads();
    float tot = 0.0f;
#pragma unroll
    for (int w = 0; w < 8; w++) tot += wsum[w];
    float rstd = rsqrtf(tot * (1.0f / 256.0f) + 1e-6f);
    float y = v * rstd * gamma[d];
    sh[d] = y;
    __syncthreads();
    float out = y;
    if (d < ROPED) {
        float rot = (d < ROPED / 2) ? -sh[d + ROPED / 2] : sh[d - ROPED / 2];
        out = y * cosb[(size_t)l * ROPED + d] + rot * sinb[(size_t)l * ROPED + d];
    }
    size_t o = (size_t)l * ODIM + h * HDIM + d;
    g_q16[o]  = __float2half_rn(out * QSCALE);
    g_gate[o] = gv;
}

// ---------------- RMSNorm + RoPE for K + V -> single fp16 ----------------
__global__ __launch_bounds__(256) void knorm_rope_v_kernel(
    const float* __restrict__ cosb, const float* __restrict__ sinb,
    const float* __restrict__ gamma)
{
    const int l = blockIdx.x;
    const int g = blockIdx.y;
    const int d = threadIdx.x;
    float v  = g_kvraw[(size_t)l * 1024 + g * HDIM + d];
    float vv = g_kvraw[(size_t)l * 1024 + 512 + g * HDIM + d];

    float s = v * v;
#pragma unroll
    for (int o = 16; o > 0; o >>= 1) s += __shfl_xor_sync(0xffffffffu, s, o);
    __shared__ float wsum[8];
    __shared__ float sh[256];
    if ((d & 31) == 0) wsum[d >> 5] = s;
    __syncthreads();
    float tot = 0.0f;
#pragma unroll
    for (int w = 0; w < 8; w++) tot += wsum[w];
    float rstd = rsqrtf(tot * (1.0f / 256.0f) + 1e-6f);
    float y = v * rstd * gamma[d];
    sh[d] = y;
    __syncthreads();
    float out = y;
    if (d < ROPED) {
        float rot = (d < ROPED / 2) ? -sh[d + ROPED / 2] : sh[d - ROPED / 2];
        out = y * cosb[(size_t)l * ROPED + d] + rot * sinb[(size_t)l * ROPED + d];
    }
    size_t o = (size_t)l * NKV + g * HDIM + d;
    g_k16[o] = __float2half_rn(out);
    g_v16[o] = __float2half_rn(vv);
}

// ---------------- MMA flash attention (single fp16), BR=BC=64, D=256 ----------------
// Q, K, V, P all single fp16. Pipelined loads: V(i) overlaps S(i)+softmax;
// K(i+1) overlaps P·V(i).
#define AQ  0
#define AK  32768
#define AV  65536
#define ASS 98304
#define SSS 68
#define AP  (ASS + 64*SSS*4)       // 115712
#define AMR (AP + 8192)            // 123904
#define ALR (AMR + 256)
#define ACR (ALR + 256)
#define ATT_SMEM (ACR + 256)       // 124672

__device__ __forceinline__ uint32_t sw512(int row, int g) {
    return (uint32_t)(row * 512 + ((g ^ (row & 7)) << 4));
}
__device__ __forceinline__ uint32_t sw128(int row, int g) {
    return (uint32_t)(row * 128 + ((g ^ (row & 7)) << 4));
}

__global__ __launch_bounds__(256, 1) void attn_mma_kernel()
{
    extern __shared__ char sm[];
    const uint32_t sb = smem_to_u32(sm);
    const int tid  = threadIdx.x;
    const int lane = tid & 31;
    const int wid  = tid >> 5;
    const int qt   = gridDim.x - 1 - blockIdx.x;   // big tiles first
    const int h    = blockIdx.y;
    const int g    = h >> 2;
    const int i0   = qt * 64;

    float* Ss   = reinterpret_cast<float*>(sm + ASS);
    float* mrow = reinterpret_cast<float*>(sm + AMR);
    float* lrow = reinterpret_cast<float*>(sm + ALR);
    float* crow = reinterpret_cast<float*>(sm + ACR);

    auto load_k = [&](int j0) {
        const size_t rbase = ((size_t)j0 * NGROUPS + g) * HDIM;
        const size_t rstr  = (size_t)NGROUPS * HDIM;
#pragma unroll
        for (int i = 0; i < 8; i++) {
            int idx = tid + 256 * i;
            int row = idx >> 5, gr = idx & 31;
            cp_async16(sb + AK + sw512(row, gr),
                       (const char*)g_k16 + (rbase + (size_t)row * rstr) * 2 + gr * 16);
        }
    };
    auto load_v = [&](int j0) {
        const size_t rbase = ((size_t)j0 * NGROUPS + g) * HDIM;
        const size_t rstr  = (size_t)NGROUPS * HDIM;
#pragma unroll
        for (int i = 0; i < 8; i++) {
            int idx = tid + 256 * i;
            int row = idx >> 5, gr = idx & 31;
            cp_async16(sb + AV + sw512(row, gr),
                       (const char*)g_v16 + (rbase + (size_t)row * rstr) * 2 + gr * 16);
        }
    };

    // ---- prolog: Q, K(0), V(0) ----
    {
        const char* q16 = (const char*)(g_q16 + ((size_t)i0 * NHEADS + h) * HDIM);
        const size_t rstr = (size_t)NHEADS * HDIM * 2;
#pragma unroll
        for (int i = 0; i < 8; i++) {
            int idx = tid + 256 * i;
            int row = idx >> 5, gr = idx & 31;
            cp_async16(sb + AQ + sw512(row, gr), q16 + (size_t)row * rstr + gr * 16);
        }
    }
    CP_COMMIT();
    load_k(0); CP_COMMIT();
    if (tid < 64) { mrow[tid] = -INFINITY; lrow[tid] = 0.0f; }
    load_v(0); CP_COMMIT();

    const int wm = wid & 3;
    const int wn = wid >> 2;
    const int er = lane >> 2;
    const int ec = (lane & 3) * 2;
    const int kgl = lane >> 4;

    float oacc[16][4];
#pragma unroll
    for (int t = 0; t < 16; t++)
#pragma unroll
        for (int r = 0; r < 4; r++) oacc[t][r] = 0.0f;

    for (int j0 = 0; j0 <= i0; j0 += 64) {
        CP_WAIT1();                // Q (+K) ready
        __syncthreads();

        // ---- S = Q K^T ----
        float sacc[4][4];
#pragma unroll
        for (int t = 0; t < 4; t++)
#pragma unroll
            for (int r = 0; r < 4; r++) sacc[t][r] = 0.0f;

        const int arow  = wm * 16 + (lane & 15);
        const int brow0 = wn * 32 + (lane & 15);
#pragma unroll 4
        for (int ks = 0; ks < 16; ks++) {
            int kg = ks * 2 + kgl;
            uint32_t a[4], b[2][4];
            ldsm_x4(a, sb + AQ + sw512(arow, kg));
            ldsm_x4(b[0], sb + AK + sw512(brow0, kg));
            ldsm_x4(b[1], sb + AK + sw512(brow0 + 16, kg));
#pragma unroll
            for (int nt = 0; nt < 2; nt++)
#pragma unroll
                for (int sub = 0; sub < 2; sub++)
                    mma16816h(sacc[nt * 2 + sub], a, b[nt][sub], b[nt][2 + sub]);
        }
#pragma unroll
        for (int t = 0; t < 4; t++) {
            int col = wn * 32 + (t >> 1) * 16 + (t & 1) * 8 + ec;
            int r0 = wm * 16 + er;
            Ss[r0 * SSS + col]           = sacc[t][0];
            Ss[r0 * SSS + col + 1]       = sacc[t][1];
            Ss[(r0 + 8) * SSS + col]     = sacc[t][2];
            Ss[(r0 + 8) * SSS + col + 1] = sacc[t][3];
        }
        __syncthreads();

        // ---- online softmax + P fp16 (4 threads / row) ----
        {
            const int row  = tid >> 2;
            const int part = tid & 3;
            int vlim = i0 + row - j0 + 1; if (vlim > 64) vlim = 64;
            float sv[16];
            float mx = -INFINITY;
            const float* srow = &Ss[row * SSS + part * 16];
#pragma unroll
            for (int c = 0; c < 16; c++) {
                int cc = part * 16 + c;
                float v = (cc < vlim) ? srow[c] : -INFINITY;
                sv[c] = v; mx = fmaxf(mx, v);
            }
            mx = fmaxf(mx, __shfl_xor_sync(0xffffffffu, mx, 1));
            mx = fmaxf(mx, __shfl_xor_sync(0xffffffffu, mx, 2));
            float mold = mrow[row];
            float mnew = fmaxf(mold, mx);
            float ls = 0.0f;
#pragma unroll
            for (int c = 0; c < 16; c++) {
                float p = __expf(sv[c] - mnew);
                sv[c] = p; ls += p;
            }
            ls += __shfl_xor_sync(0xffffffffu, ls, 1);
            ls += __shfl_xor_sync(0xffffffffu, ls, 2);
            float corr = __expf(mold - mnew);
            if (part == 0) {
                mrow[row] = mnew;
                lrow[row] = lrow[row] * corr + ls;
                crow[row] = corr;
            }
#pragma unroll
            for (int gs = 0; gs < 2; gs++) {
                uint32_t hw[4];
#pragma unroll
                for (int q = 0; q < 4; q++)
                    hw[q] = pack_h2(__float2half_rn(sv[gs * 8 + q * 2]),
                                    __float2half_rn(sv[gs * 8 + q * 2 + 1]));
                *reinterpret_cast<uint4*>(sm + AP + sw128(row, part * 2 + gs)) =
                    make_uint4(hw[0], hw[1], hw[2], hw[3]);
            }
        }
        __syncthreads();          // K buffer dead; P ready

        if (j0 + 64 <= i0) load_k(j0 + 64);
        CP_COMMIT();
        CP_WAIT1();               // V(j0) ready
        __syncthreads();

        // ---- rescale O, then O += P V ----
        {
            float c0 = crow[wm * 16 + er];
            float c1 = crow[wm * 16 + er + 8];
#pragma unroll
            for (int t = 0; t < 16; t++) {
                oacc[t][0] *= c0; oacc[t][1] *= c0;
                oacc[t][2] *= c1; oacc[t][3] *= c1;
            }
        }
        const int prow = wm * 16 + (lane & 15);
        const int vk   = lane & 15;
        const int vng  = lane >> 4;
#pragma unroll
        for (int ks = 0; ks < 4; ks++) {
            uint32_t a[4];
            ldsm_x4(a, sb + AP + sw128(prow, ks * 2 + kgl));
            int krow = ks * 16 + vk;
#pragma unroll
            for (int ng = 0; ng < 8; ng++) {
                uint32_t vv[4];
                int gv = wn * 16 + ng * 2 + vng;
                ldsm_x4_trans(vv, sb + AV + sw512(krow, gv));
#pragma unroll
                for (int sub = 0; sub < 2; sub++)
                    mma16816h(oacc[ng * 2 + sub], a, vv[2 * sub], vv[2 * sub + 1]);
            }
        }
        __syncthreads();          // V buffer dead

        if (j0 + 64 <= i0) load_v(j0 + 64);
        CP_COMMIT();
    }

    // ---- epilogue: 1/l, sigmoid gate, write single fp16 y ----
    {
        const int r0 = wm * 16 + er;
        const float li0 = 1.0f / lrow[r0];
        const float li1 = 1.0f / lrow[r0 + 8];
        const size_t base0 = (size_t)(i0 + r0) * ODIM + h * HDIM;
        const size_t base1 = (size_t)(i0 + r0 + 8) * ODIM + h * HDIM;
#pragma unroll
        for (int t = 0; t < 16; t++) {
            int col = wn * 128 + (t >> 1) * 16 + (t & 1) * 8 + ec;
            float2 gt0 = *reinterpret_cast<const float2*>(&g_gate[base0 + col]);
            float2 gt1 = *reinterpret_cast<const float2*>(&g_gate[base1 + col]);
            float v00 = oacc[t][0] * li0 * (1.0f / (1.0f + __expf(-gt0.x)));
            float v01 = oacc[t][1] * li0 * (1.0f / (1.0f + __expf(-gt0.y)));
            float v10 = oacc[t][2] * li1 * (1.0f / (1.0f + __expf(-gt1.x)));
            float v11 = oacc[t][3] * li1 * (1.0f / (1.0f + __expf(-gt1.y)));
            *reinterpret_cast<__half2*>(&g_y[base0 + col]) =
                __halves2half2(__float2half_rn(v00), __float2half_rn(v01));
            *reinterpret_cast<__half2*>(&g_y[base1 + col]) =
                __halves2half2(__float2half_rn(v10), __float2half_rn(v11));
        }
    }
}

// ---------------- launch ----------------
extern "C" void kernel_launch(void* const* d_in, const int* in_sizes, int n_in,
                              void* d_out, int out_size)
{
    const float* x    = (const float*)d_in[0];
    const float* cosb = (const float*)d_in[1];
    const float* sinb = (const float*)d_in[2];
    const float* wq   = (const float*)d_in[4];
    const float* wk   = (const float*)d_in[5];
    const float* wv   = (const float*)d_in[6];
    const float* wo   = (const float*)d_in[7];
    const float* qg   = (const float*)d_in[8];
    const float* kg   = (const float*)d_in[9];
    float* out        = (float*)d_out;

    float *p_qraw, *p_kvraw;
    cudaGetSymbolAddress((void**)&p_qraw,  g_qraw);
    cudaGetSymbolAddress((void**)&p_kvraw, g_kvraw);

    __half *p_x16, *p_wqh16, *p_wql16, *p_wkvh16, *p_wkvl16, *p_woh16, *p_wol16, *p_y;
    cudaGetSymbolAddress((void**)&p_x16,    g_x16);
    cudaGetSymbolAddress((void**)&p_wqh16,  g_wqh16);
    cudaGetSymbolAddress((void**)&p_wql16,  g_wql16);
    cudaGetSymbolAddress((void**)&p_wkvh16, g_wkvh16);
    cudaGetSymbolAddress((void**)&p_wkvl16, g_wkvl16);
    cudaGetSymbolAddress((void**)&p_woh16,  g_woh16);
    cudaGetSymbolAddress((void**)&p_wol16,  g_wol16);
    cudaGetSymbolAddress((void**)&p_y,      g_y);

    cudaFuncSetAttribute(mma_gemm2h, cudaFuncAttributeMaxDynamicSharedMemorySize, GEMM2_SMEM);
    cudaFuncSetAttribute(attn_mma_kernel, cudaFuncAttributeMaxDynamicSharedMemorySize, ATT_SMEM);

    // 0) operand prep (all fp16)
    cast_h_kernel<<<1024, 256>>>(x, p_x16, (size_t)L_SEQ * IDIM / 4);
    transpose_split_h_kernel<<<dim3((ODIM*2)/32, IDIM/32), 256>>>(wq, p_wqh16, p_wql16, IDIM, ODIM*2);
    transpose_split_h_kernel<<<dim3(NKV/32, IDIM/32), 256>>>(wk, p_wkvh16, p_wkvl16, IDIM, NKV);
    transpose_split_h_kernel<<<dim3(NKV/32, IDIM/32), 256>>>(
        wv, p_wkvh16 + (size_t)512 * IDIM, p_wkvl16 + (size_t)512 * IDIM, IDIM, NKV);
    transpose_split_h_kernel<<<dim3(IDIM/32, ODIM/32), 256>>>(wo, p_woh16, p_wol16, ODIM, IDIM);

    // 1) projections: Q (N=4096) and fused KV (N=1024), 2-term fp16
    mma_gemm2h<<<dim3((ODIM*2)/128, L_SEQ/128), 256, GEMM2_SMEM>>>(p_x16, p_wqh16, p_wql16, p_qraw, ODIM*2);
    mma_gemm2h<<<dim3(1024/128,     L_SEQ/128), 256, GEMM2_SMEM>>>(p_x16, p_wkvh16, p_wkvl16, p_kvraw, 1024);

    // 2) norms + RoPE -> single fp16
    qnorm_rope_kernel<<<dim3(L_SEQ, NHEADS),  256>>>(cosb, sinb, qg);
    knorm_rope_v_kernel<<<dim3(L_SEQ, NGROUPS), 256>>>(cosb, sinb, kg);

    // 3) MMA flash attention (single fp16) + gating -> fp16 y
    attn_mma_kernel<<<dim3(L_SEQ / 64, NHEADS), 256, ATT_SMEM>>>();

    // 4) output projection: 2-term fp16
    mma_gemm2h<<<dim3(IDIM/128, L_SEQ/128), 256, GEMM2_SMEM>>>(p_y, p_woh16, p_wol16, out, IDIM);
}

// round 11
// speedup vs baseline: 2.2664x; 1.3599x over previous
#include <cuda_runtime.h>
#include <cuda_bf16.h>
#include <cuda_fp16.h>
#include <math.h>
#include <stdint.h>

// ---------------- problem constants ----------------
#define L_SEQ   4096
#define IDIM    2048
#define NHEADS  8
#define NGROUPS 2
#define HDIM    256
#define ROPED   64
#define ODIM    (NHEADS*HDIM)     // 2048
#define NKV     (NGROUPS*HDIM)    // 512
#define QSCALE  0.0625f           // 256^-0.5

// ---------------- warp-MMA helpers (standard PTX, sm_80+) ----------------
__device__ __forceinline__ void ldsm_x4(uint32_t* r, uint32_t addr) {
    asm volatile("ldmatrix.sync.aligned.m8n8.x4.shared.b16 {%0,%1,%2,%3}, [%4];"
        : "=r"(r[0]), "=r"(r[1]), "=r"(r[2]), "=r"(r[3]) : "r"(addr));
}
__device__ __forceinline__ void ldsm_x4_trans(uint32_t* r, uint32_t addr) {
    asm volatile("ldmatrix.sync.aligned.m8n8.x4.trans.shared.b16 {%0,%1,%2,%3}, [%4];"
        : "=r"(r[0]), "=r"(r[1]), "=r"(r[2]), "=r"(r[3]) : "r"(addr));
}
__device__ __forceinline__ void mma16816h(float* d, const uint32_t* a, uint32_t b0, uint32_t b1) {
    asm volatile("mma.sync.aligned.m16n8k16.row.col.f32.f16.f16.f32 "
        "{%0,%1,%2,%3}, {%4,%5,%6,%7}, {%8,%9}, {%0,%1,%2,%3};"
        : "+f"(d[0]), "+f"(d[1]), "+f"(d[2]), "+f"(d[3])
        : "r"(a[0]), "r"(a[1]), "r"(a[2]), "r"(a[3]), "r"(b0), "r"(b1));
}
__device__ __forceinline__ void cp_async16(uint32_t dst, const void* src) {
    asm volatile("cp.async.cg.shared.global [%0], [%1], 16;" :: "r"(dst), "l"(src));
}
#define CP_COMMIT() asm volatile("cp.async.commit_group;" ::: "memory")
#define CP_WAIT1()  asm volatile("cp.async.wait_group 1;" ::: "memory")
#define CP_WAIT0()  asm volatile("cp.async.wait_group 0;" ::: "memory")

__device__ __forceinline__ uint32_t smem_to_u32(const void* p) {
    uint32_t a;
    asm("{ .reg .u64 t; cvta.to.shared.u64 t, %1; cvt.u32.u64 %0, t; }" : "=r"(a) : "l"(p));
    return a;
}
__device__ __forceinline__ uint32_t pack_h2(__half a, __half b) {
    __half2 t = __halves2half2(a, b);
    return *reinterpret_cast<uint32_t*>(&t);
}

// ---------------- scratch (device globals) ----------------
__device__ float g_qraw [(size_t)L_SEQ * (ODIM*2)];
__device__ float g_gate [(size_t)L_SEQ * ODIM];
__device__ float g_kvraw[(size_t)L_SEQ * 1024];     // cols 0-511 = K, 512-1023 = V

// fp16 operands (all GEMMs 1-term fp16)
__device__ __half g_x16  [(size_t)L_SEQ * IDIM];
__device__ __half g_wq16 [(size_t)(ODIM*2) * IDIM];
__device__ __half g_wkv16[(size_t)1024 * IDIM];     // rows 0-511 wk^T, 512-1023 wv^T
__device__ __half g_wo16 [(size_t)IDIM * ODIM];
__device__ __half g_y    [(size_t)L_SEQ * ODIM];
// attention operands (single fp16)
__device__ __half g_q16 [(size_t)L_SEQ * ODIM];     // pre-scaled
__device__ __half g_k16 [(size_t)L_SEQ * NKV];
__device__ __half g_v16 [(size_t)L_SEQ * NKV];

// ---------------- cast kernel: fp32 -> fp16 ----------------
__global__ __launch_bounds__(256) void cast_h_kernel(
    const float* __restrict__ in, __half* __restrict__ out, size_t n4)
{
    size_t i = (size_t)blockIdx.x * blockDim.x + threadIdx.x;
    size_t stride = (size_t)gridDim.x * blockDim.x;
    for (; i < n4; i += stride) {
        float4 v = reinterpret_cast<const float4*>(in)[i];
        __half2 a = __halves2half2(__float2half_rn(v.x), __float2half_rn(v.y));
        __half2 b = __halves2half2(__float2half_rn(v.z), __float2half_rn(v.w));
        reinterpret_cast<__half2*>(out)[i*2]   = a;
        reinterpret_cast<__half2*>(out)[i*2+1] = b;
    }
}

// ---------------- transpose: W[K][N] fp32 -> Wt [N][K] fp16 ----------------
__global__ __launch_bounds__(256) void transpose_h_kernel(
    const float* __restrict__ W, __half* __restrict__ T, int Kdim, int Ndim)
{
    __shared__ float tile[32][33];
    int n0 = blockIdx.x * 32;
    int k0 = blockIdx.y * 32;
    int tx = threadIdx.x & 31;
    int ty = threadIdx.x >> 5;
#pragma unroll
    for (int r = 0; r < 4; r++)
        tile[ty + 8*r][tx] = W[(size_t)(k0 + ty + 8*r) * Ndim + n0 + tx];
    __syncthreads();
#pragma unroll
    for (int r = 0; r < 4; r++) {
        float v = tile[tx][ty + 8*r];
        T[(size_t)(n0 + ty + 8*r) * Kdim + k0 + tx] = __float2half_rn(v);
    }
}

// ---------------- 1-term fp16 GEMM: C = A(fp16) @ B(fp16)^T ----------------
// block 128x128, 8 warps (2M x 4N), warp 64x32, BK=32, 2-stage cp.async.
#define GBK 32
#define NCHUNK (IDIM / GBK)            // 64
#define RS 80                          // smem row stride bytes
#define MAT_BYTES (128 * RS)           // 10240
#define MAT2_STAGE (2 * MAT_BYTES)     // 20480
#define GEMM1_SMEM (2 * MAT2_STAGE)    // 40960

__global__ __launch_bounds__(256) void mma_gemmh(
    const __half* __restrict__ A, const __half* __restrict__ B,
    float* __restrict__ C, int N)
{
    extern __shared__ char smem[];
    const uint32_t sb = smem_to_u32(smem);

    const int tid  = threadIdx.x;
    const int lane = tid & 31;
    const int wid  = tid >> 5;
    const int wm   = wid & 1;
    const int wn   = wid >> 1;
    const int m0   = blockIdx.y * 128;
    const int n0   = blockIdx.x * 128;

    auto issue_loads = [&](int chunk) {
        const int stage = chunk & 1;
        const uint32_t s0 = sb + stage * MAT2_STAGE;
#pragma unroll
        for (int j = 0; j < 4; j++) {
            int idx = tid + 256 * j;          // 0..1023
            int mat = idx >> 9;               // 0=A,1=B
            int wi  = idx & 511;
            int row = wi >> 2;
            int c   = wi & 3;
            const __half* gp = (mat == 0) ? A + (size_t)(m0 + row) * IDIM
                                          : B + (size_t)(n0 + row) * IDIM;
            cp_async16(s0 + mat * MAT_BYTES + row * RS + c * 16,
                       gp + chunk * GBK + c * 8);
        }
    };

    float acc[4][4][4];
#pragma unroll
    for (int mi = 0; mi < 4; mi++)
#pragma unroll
        for (int ni = 0; ni < 4; ni++)
#pragma unroll
            for (int r = 0; r < 4; r++) acc[mi][ni][r] = 0.0f;

    const uint32_t a_row = wm * 64 + (lane & 15);
    const uint32_t b_row = wn * 32 + (lane & 15);
    const uint32_t colb  = (lane >> 4) * 16;

    issue_loads(0); CP_COMMIT();

    for (int i = 0; i < NCHUNK; i++) {
        const int stage = i & 1;
        if (i + 1 < NCHUNK) { issue_loads(i + 1); CP_COMMIT(); CP_WAIT1(); }
        else                { CP_WAIT0(); }
        __syncthreads();

        const uint32_t sA = sb + stage * MAT2_STAGE;
        const uint32_t sB = sA + MAT_BYTES;

#pragma unroll
        for (int ks = 0; ks < 2; ks++) {
            const uint32_t kb = ks * 32 + colb;
            uint32_t a[4][4], b[2][4];
#pragma unroll
            for (int mi = 0; mi < 4; mi++)
                ldsm_x4(a[mi], sA + (a_row + mi * 16) * RS + kb);
#pragma unroll
            for (int nt = 0; nt < 2; nt++)
                ldsm_x4(b[nt], sB + (b_row + nt * 16) * RS + kb);
#pragma unroll
            for (int mi = 0; mi < 4; mi++) {
#pragma unroll
                for (int ni = 0; ni < 4; ni++) {
                    const int nt = ni >> 1, sub = ni & 1;
                    mma16816h(acc[mi][ni], a[mi], b[nt][sub], b[nt][2 + sub]);
                }
            }
        }
        __syncthreads();
    }

    const int er = lane >> 2;
    const int ec = (lane & 3) * 2;
#pragma unroll
    for (int mi = 0; mi < 4; mi++) {
#pragma unroll
        for (int ni = 0; ni < 4; ni++) {
            int row = m0 + wm * 64 + mi * 16 + er;
            int col = n0 + wn * 32 + ni * 8 + ec;
            *reinterpret_cast<float2*>(&C[(size_t)row * N + col]) =
                make_float2(acc[mi][ni][0], acc[mi][ni][1]);
            *reinterpret_cast<float2*>(&C[(size_t)(row + 8) * N + col]) =
                make_float2(acc[mi][ni][2], acc[mi][ni][3]);
        }
    }
}

// ---------------- RMSNorm + RoPE for Q -> single fp16 (pre-scaled) + gate ----------------
__global__ __launch_bounds__(256) void qnorm_rope_kernel(
    const float* __restrict__ cosb, const float* __restrict__ sinb,
    const float* __restrict__ gamma)
{
    const int l = blockIdx.x;
    const int h = blockIdx.y;
    const int d = threadIdx.x;
    const float* row = g_qraw + (size_t)l * (ODIM * 2) + h * 512;
    float v  = row[d];
    float gv = row[256 + d];

    float s = v * v;
#pragma unroll
    for (int o = 16; o > 0; o >>= 1) s += __shfl_xor_sync(0xffffffffu, s, o);
    __shared__ float wsum[8];
    __shared__ float sh[256];
    if ((d & 31) == 0) wsum[d >> 5] = s;
    __syncthreads();
    float tot = 0.0f;
#pragma unroll
    for (int w = 0; w < 8; w++) tot += wsum[w];
    float rstd = rsqrtf(tot * (1.0f / 256.0f) + 1e-6f);
    float y = v * rstd * gamma[d];
    sh[d] = y;
    __syncthreads();
    float out = y;
    if (d < ROPED) {
        float rot = (d < ROPED / 2) ? -sh[d + ROPED / 2] : sh[d - ROPED / 2];
        out = y * cosb[(size_t)l * ROPED + d] + rot * sinb[(size_t)l * ROPED + d];
    }
    size_t o = (size_t)l * ODIM + h * HDIM + d;
    g_q16[o]  = __float2half_rn(out * QSCALE);
    g_gate[o] = gv;
}

// ---------------- RMSNorm + RoPE for K + V -> single fp16 ----------------
__global__ __launch_bounds__(256) void knorm_rope_v_kernel(
    const float* __restrict__ cosb, const float* __restrict__ sinb,
    const float* __restrict__ gamma)
{
    const int l = blockIdx.x;
    const int g = blockIdx.y;
    const int d = threadIdx.x;
    float v  = g_kvraw[(size_t)l * 1024 + g * HDIM + d];
    float vv = g_kvraw[(size_t)l * 1024 + 512 + g * HDIM + d];

    float s = v * v;
#pragma unroll
    for (int o = 16; o > 0; o >>= 1) s += __shfl_xor_sync(0xffffffffu, s, o);
    __shared__ float wsum[8];
    __shared__ float sh[256];
    if ((d & 31) == 0) wsum[d >> 5] = s;
    __syncthreads();
    float tot = 0.0f;
#pragma unroll
    for (int w = 0; w < 8; w++) tot += wsum[w];
    float rstd = rsqrtf(tot * (1.0f / 256.0f) + 1e-6f);
    float y = v * rstd * gamma[d];
    sh[d] = y;
    __syncthreads();
    float out = y;
    if (d < ROPED) {
        float rot = (d < ROPED / 2) ? -sh[d + ROPED / 2] : sh[d - ROPED / 2];
        out = y * cosb[(size_t)l * ROPED + d] + rot * sinb[(size_t)l * ROPED + d];
    }
    size_t o = (size_t)l * NKV + g * HDIM + d;
    g_k16[o] = __float2half_rn(out);
    g_v16[o] = __float2half_rn(vv);
}

// ---------------- MMA flash attention (single fp16), BR=BC=64, D=256 ----------------
#define AQ  0
#define AK  32768
#define AV  65536
#define ASS 98304
#define SSS 68
#define AP  (ASS + 64*SSS*4)       // 115712
#define AMR (AP + 8192)            // 123904
#define ALR (AMR + 256)
#define ACR (ALR + 256)
#define ATT_SMEM (ACR + 256)       // 124672

__device__ __forceinline__ uint32_t sw512(int row, int g) {
    return (uint32_t)(row * 512 + ((g ^ (row & 7)) << 4));
}
__device__ __forceinline__ uint32_t sw128(int row, int g) {
    return (uint32_t)(row * 128 + ((g ^ (row & 7)) << 4));
}

__global__ __launch_bounds__(256, 1) void attn_mma_kernel()
{
    extern __shared__ char sm[];
    const uint32_t sb = smem_to_u32(sm);
    const int tid  = threadIdx.x;
    const int lane = tid & 31;
    const int wid  = tid >> 5;
    const int qt   = gridDim.x - 1 - blockIdx.x;   // big tiles first
    const int h    = blockIdx.y;
    const int g    = h >> 2;
    const int i0   = qt * 64;

    float* Ss   = reinterpret_cast<float*>(sm + ASS);
    float* mrow = reinterpret_cast<float*>(sm + AMR);
    float* lrow = reinterpret_cast<float*>(sm + ALR);
    float* crow = reinterpret_cast<float*>(sm + ACR);

    auto load_k = [&](int j0) {
        const size_t rbase = ((size_t)j0 * NGROUPS + g) * HDIM;
        const size_t rstr  = (size_t)NGROUPS * HDIM;
#pragma unroll
        for (int i = 0; i < 8; i++) {
            int idx = tid + 256 * i;
            int row = idx >> 5, gr = idx & 31;
            cp_async16(sb + AK + sw512(row, gr),
                       (const char*)g_k16 + (rbase + (size_t)row * rstr) * 2 + gr * 16);
        }
    };
    auto load_v = [&](int j0) {
        const size_t rbase = ((size_t)j0 * NGROUPS + g) * HDIM;
        const size_t rstr  = (size_t)NGROUPS * HDIM;
#pragma unroll
        for (int i = 0; i < 8; i++) {
            int idx = tid + 256 * i;
            int row = idx >> 5, gr = idx & 31;
            cp_async16(sb + AV + sw512(row, gr),
                       (const char*)g_v16 + (rbase + (size_t)row * rstr) * 2 + gr * 16);
        }
    };

    // ---- prolog: Q, K(0), V(0) ----
    {
        const char* q16 = (const char*)(g_q16 + ((size_t)i0 * NHEADS + h) * HDIM);
        const size_t rstr = (size_t)NHEADS * HDIM * 2;
#pragma unroll
        for (int i = 0; i < 8; i++) {
            int idx = tid + 256 * i;
            int row = idx >> 5, gr = idx & 31;
            cp_async16(sb + AQ + sw512(row, gr), q16 + (size_t)row * rstr + gr * 16);
        }
    }
    CP_COMMIT();
    load_k(0); CP_COMMIT();
    if (tid < 64) { mrow[tid] = -INFINITY; lrow[tid] = 0.0f; }
    load_v(0); CP_COMMIT();

    const int wm = wid & 3;
    const int wn = wid >> 2;
    const int er = lane >> 2;
    const int ec = (lane & 3) * 2;
    const int kgl = lane >> 4;

    float oacc[16][4];
#pragma unroll
    for (int t = 0; t < 16; t++)
#pragma unroll
        for (int r = 0; r < 4; r++) oacc[t][r] = 0.0f;

    for (int j0 = 0; j0 <= i0; j0 += 64) {
        CP_WAIT1();                // Q (+K) ready
        __syncthreads();

        // ---- S = Q K^T ----
        float sacc[4][4];
#pragma unroll
        for (int t = 0; t < 4; t++)
#pragma unroll
            for (int r = 0; r < 4; r++) sacc[t][r] = 0.0f;

        const int arow  = wm * 16 + (lane & 15);
        const int brow0 = wn * 32 + (lane & 15);
#pragma unroll 4
        for (int ks = 0; ks < 16; ks++) {
            int kg = ks * 2 + kgl;
            uint32_t a[4], b[2][4];
            ldsm_x4(a, sb + AQ + sw512(arow, kg));
            ldsm_x4(b[0], sb + AK + sw512(brow0, kg));
            ldsm_x4(b[1], sb + AK + sw512(brow0 + 16, kg));
#pragma unroll
            for (int nt = 0; nt < 2; nt++)
#pragma unroll
                for (int sub = 0; sub < 2; sub++)
                    mma16816h(sacc[nt * 2 + sub], a, b[nt][sub], b[nt][2 + sub]);
        }
#pragma unroll
        for (int t = 0; t < 4; t++) {
            int col = wn * 32 + (t >> 1) * 16 + (t & 1) * 8 + ec;
            int r0 = wm * 16 + er;
            Ss[r0 * SSS + col]           = sacc[t][0];
            Ss[r0 * SSS + col + 1]       = sacc[t][1];
            Ss[(r0 + 8) * SSS + col]     = sacc[t][2];
            Ss[(r0 + 8) * SSS + col + 1] = sacc[t][3];
        }
        __syncthreads();

        // ---- online softmax + P fp16 (4 threads / row) ----
        {
            const int row  = tid >> 2;
            const int part = tid & 3;
            int vlim = i0 + row - j0 + 1; if (vlim > 64) vlim = 64;
            float sv[16];
            float mx = -INFINITY;
            const float* srow = &Ss[row * SSS + part * 16];
#pragma unroll
            for (int c = 0; c < 16; c++) {
                int cc = part * 16 + c;
                float v = (cc < vlim) ? srow[c] : -INFINITY;
                sv[c] = v; mx = fmaxf(mx, v);
            }
            mx = fmaxf(mx, __shfl_xor_sync(0xffffffffu, mx, 1));
            mx = fmaxf(mx, __shfl_xor_sync(0xffffffffu, mx, 2));
            float mold = mrow[row];
            float mnew = fmaxf(mold, mx);
            float ls = 0.0f;
#pragma unroll
            for (int c = 0; c < 16; c++) {
                float p = __expf(sv[c] - mnew);
                sv[c] = p; ls += p;
            }
            ls += __shfl_xor_sync(0xffffffffu, ls, 1);
            ls += __shfl_xor_sync(0xffffffffu, ls, 2);
            float corr = __expf(mold - mnew);
            if (part == 0) {
                mrow[row] = mnew;
                lrow[row] = lrow[row] * corr + ls;
                crow[row] = corr;
            }
#pragma unroll
            for (int gs = 0; gs < 2; gs++) {
                uint32_t hw[4];
#pragma unroll
                for (int q = 0; q < 4; q++)
                    hw[q] = pack_h2(__float2half_rn(sv[gs * 8 + q * 2]),
                                    __float2half_rn(sv[gs * 8 + q * 2 + 1]));
                *reinterpret_cast<uint4*>(sm + AP + sw128(row, part * 2 + gs)) =
                    make_uint4(hw[0], hw[1], hw[2], hw[3]);
            }
        }
        __syncthreads();          // K buffer dead; P ready

        if (j0 + 64 <= i0) load_k(j0 + 64);
        CP_COMMIT();
        CP_WAIT1();               // V(j0) ready
        __syncthreads();

        // ---- rescale O, then O += P V ----
        {
            float c0 = crow[wm * 16 + er];
            float c1 = crow[wm * 16 + er + 8];
#pragma unroll
            for (int t = 0; t < 16; t++) {
                oacc[t][0] *= c0; oacc[t][1] *= c0;
                oacc[t][2] *= c1; oacc[t][3] *= c1;
            }
        }
        const int prow = wm * 16 + (lane & 15);
        const int vk   = lane & 15;
        const int vng  = lane >> 4;
#pragma unroll
        for (int ks = 0; ks < 4; ks++) {
            uint32_t a[4];
            ldsm_x4(a, sb + AP + sw128(prow, ks * 2 + kgl));
            int krow = ks * 16 + vk;
#pragma unroll
            for (int ng = 0; ng < 8; ng++) {
                uint32_t vv[4];
                int gv = wn * 16 + ng * 2 + vng;
                ldsm_x4_trans(vv, sb + AV + sw512(krow, gv));
#pragma unroll
                for (int sub = 0; sub < 2; sub++)
                    mma16816h(oacc[ng * 2 + sub], a, vv[2 * sub], vv[2 * sub + 1]);
            }
        }
        __syncthreads();          // V buffer dead

        if (j0 + 64 <= i0) load_v(j0 + 64);
        CP_COMMIT();
    }

    // ---- epilogue: 1/l, sigmoid gate, write single fp16 y ----
    {
        const int r0 = wm * 16 + er;
        const float li0 = 1.0f / lrow[r0];
        const float li1 = 1.0f / lrow[r0 + 8];
        const size_t base0 = (size_t)(i0 + r0) * ODIM + h * HDIM;
        const size_t base1 = (size_t)(i0 + r0 + 8) * ODIM + h * HDIM;
#pragma unroll
        for (int t = 0; t < 16; t++) {
            int col = wn * 128 + (t >> 1) * 16 + (t & 1) * 8 + ec;
            float2 gt0 = *reinterpret_cast<const float2*>(&g_gate[base0 + col]);
            float2 gt1 = *reinterpret_cast<const float2*>(&g_gate[base1 + col]);
            float v00 = oacc[t][0] * li0 * (1.0f / (1.0f + __expf(-gt0.x)));
            float v01 = oacc[t][1] * li0 * (1.0f / (1.0f + __expf(-gt0.y)));
            float v10 = oacc[t][2] * li1 * (1.0f / (1.0f + __expf(-gt1.x)));
            float v11 = oacc[t][3] * li1 * (1.0f / (1.0f + __expf(-gt1.y)));
            *reinterpret_cast<__half2*>(&g_y[base0 + col]) =
                __halves2half2(__float2half_rn(v00), __float2half_rn(v01));
            *reinterpret_cast<__half2*>(&g_y[base1 + col]) =
                __halves2half2(__float2half_rn(v10), __float2half_rn(v11));
        }
    }
}

// ---------------- launch ----------------
extern "C" void kernel_launch(void* const* d_in, const int* in_sizes, int n_in,
                              void* d_out, int out_size)
{
    const float* x    = (const float*)d_in[0];
    const float* cosb = (const float*)d_in[1];
    const float* sinb = (const float*)d_in[2];
    const float* wq   = (const float*)d_in[4];
    const float* wk   = (const float*)d_in[5];
    const float* wv   = (const float*)d_in[6];
    const float* wo   = (const float*)d_in[7];
    const float* qg   = (const float*)d_in[8];
    const float* kg   = (const float*)d_in[9];
    float* out        = (float*)d_out;

    float *p_qraw, *p_kvraw;
    cudaGetSymbolAddress((void**)&p_qraw,  g_qraw);
    cudaGetSymbolAddress((void**)&p_kvraw, g_kvraw);

    __half *p_x16, *p_wq16, *p_wkv16, *p_wo16, *p_y;
    cudaGetSymbolAddress((void**)&p_x16,   g_x16);
    cudaGetSymbolAddress((void**)&p_wq16,  g_wq16);
    cudaGetSymbolAddress((void**)&p_wkv16, g_wkv16);
    cudaGetSymbolAddress((void**)&p_wo16,  g_wo16);
    cudaGetSymbolAddress((void**)&p_y,     g_y);

    cudaFuncSetAttribute(mma_gemmh, cudaFuncAttributeMaxDynamicSharedMemorySize, GEMM1_SMEM);
    cudaFuncSetAttribute(attn_mma_kernel, cudaFuncAttributeMaxDynamicSharedMemorySize, ATT_SMEM);

    // 0) operand prep (all fp16, 1-term)
    cast_h_kernel<<<1024, 256>>>(x, p_x16, (size_t)L_SEQ * IDIM / 4);
    transpose_h_kernel<<<dim3((ODIM*2)/32, IDIM/32), 256>>>(wq, p_wq16, IDIM, ODIM*2);
    transpose_h_kernel<<<dim3(NKV/32, IDIM/32), 256>>>(wk, p_wkv16, IDIM, NKV);
    transpose_h_kernel<<<dim3(NKV/32, IDIM/32), 256>>>(
        wv, p_wkv16 + (size_t)512 * IDIM, IDIM, NKV);
    transpose_h_kernel<<<dim3(IDIM/32, ODIM/32), 256>>>(wo, p_wo16, ODIM, IDIM);

    // 1) projections: Q (N=4096) and fused KV (N=1024), 1-term fp16
    mma_gemmh<<<dim3((ODIM*2)/128, L_SEQ/128), 256, GEMM1_SMEM>>>(p_x16, p_wq16, p_qraw, ODIM*2);
    mma_gemmh<<<dim3(1024/128,     L_SEQ/128), 256, GEMM1_SMEM>>>(p_x16, p_wkv16, p_kvraw, 1024);

    // 2) norms + RoPE -> single fp16
    qnorm_rope_kernel<<<dim3(L_SEQ, NHEADS),  256>>>(cosb, sinb, qg);
    knorm_rope_v_kernel<<<dim3(L_SEQ, NGROUPS), 256>>>(cosb, sinb, kg);

    // 3) MMA flash attention (single fp16) + gating -> fp16 y
    attn_mma_kernel<<<dim3(L_SEQ / 64, NHEADS), 256, ATT_SMEM>>>();

    // 4) output projection: 1-term fp16
    mma_gemmh<<<dim3(IDIM/128, L_SEQ/128), 256, GEMM1_SMEM>>>(p_y, p_wo16, out, IDIM);
}

// round 12
// speedup vs baseline: 2.4395x; 1.0764x over previous
#include <cuda_runtime.h>
#include <cuda_bf16.h>
#include <cuda_fp16.h>
#include <math.h>
#include <stdint.h>

// ---------------- problem constants ----------------
#define L_SEQ   4096
#define IDIM    2048
#define NHEADS  8
#define NGROUPS 2
#define HDIM    256
#define ROPED   64
#define ODIM    (NHEADS*HDIM)     // 2048
#define NKV     (NGROUPS*HDIM)    // 512
#define QSCALE  0.0625f           // 256^-0.5

// ---------------- warp-MMA helpers (standard PTX, sm_80+) ----------------
__device__ __forceinline__ void ldsm_x4(uint32_t* r, uint32_t addr) {
    asm volatile("ldmatrix.sync.aligned.m8n8.x4.shared.b16 {%0,%1,%2,%3}, [%4];"
        : "=r"(r[0]), "=r"(r[1]), "=r"(r[2]), "=r"(r[3]) : "r"(addr));
}
__device__ __forceinline__ void ldsm_x4_trans(uint32_t* r, uint32_t addr) {
    asm volatile("ldmatrix.sync.aligned.m8n8.x4.trans.shared.b16 {%0,%1,%2,%3}, [%4];"
        : "=r"(r[0]), "=r"(r[1]), "=r"(r[2]), "=r"(r[3]) : "r"(addr));
}
__device__ __forceinline__ void mma16816h(float* d, const uint32_t* a, uint32_t b0, uint32_t b1) {
    asm volatile("mma.sync.aligned.m16n8k16.row.col.f32.f16.f16.f32 "
        "{%0,%1,%2,%3}, {%4,%5,%6,%7}, {%8,%9}, {%0,%1,%2,%3};"
        : "+f"(d[0]), "+f"(d[1]), "+f"(d[2]), "+f"(d[3])
        : "r"(a[0]), "r"(a[1]), "r"(a[2]), "r"(a[3]), "r"(b0), "r"(b1));
}
__device__ __forceinline__ void cp_async16(uint32_t dst, const void* src) {
    asm volatile("cp.async.cg.shared.global [%0], [%1], 16;" :: "r"(dst), "l"(src));
}
#define CP_COMMIT() asm volatile("cp.async.commit_group;" ::: "memory")
#define CP_WAIT1()  asm volatile("cp.async.wait_group 1;" ::: "memory")
#define CP_WAIT0()  asm volatile("cp.async.wait_group 0;" ::: "memory")

__device__ __forceinline__ uint32_t smem_to_u32(const void* p) {
    uint32_t a;
    asm("{ .reg .u64 t; cvta.to.shared.u64 t, %1; cvt.u32.u64 %0, t; }" : "=r"(a) : "l"(p));
    return a;
}
__device__ __forceinline__ uint32_t pack_h2(__half a, __half b) {
    __half2 t = __halves2half2(a, b);
    return *reinterpret_cast<uint32_t*>(&t);
}

// ---------------- scratch (device globals) ----------------
__device__ float  g_qraw [(size_t)L_SEQ * (ODIM*2)];
__device__ __half g_gate16[(size_t)L_SEQ * ODIM];
__device__ float  g_kvraw[(size_t)L_SEQ * 1024];    // cols 0-511 = K, 512-1023 = V

// fp16 operands (all GEMMs 1-term fp16)
__device__ __half g_x16  [(size_t)L_SEQ * IDIM];
__device__ __half g_wq16 [(size_t)(ODIM*2) * IDIM];
__device__ __half g_wkv16[(size_t)1024 * IDIM];     // rows 0-511 wk^T, 512-1023 wv^T
__device__ __half g_wo16 [(size_t)IDIM * ODIM];
__device__ __half g_y    [(size_t)L_SEQ * ODIM];
// attention operands (single fp16)
__device__ __half g_q16 [(size_t)L_SEQ * ODIM];     // pre-scaled
__device__ __half g_k16 [(size_t)L_SEQ * NKV];
__device__ __half g_v16 [(size_t)L_SEQ * NKV];

// ---------------- cast kernel: fp32 -> fp16 ----------------
__global__ __launch_bounds__(256) void cast_h_kernel(
    const float* __restrict__ in, __half* __restrict__ out, size_t n4)
{
    size_t i = (size_t)blockIdx.x * blockDim.x + threadIdx.x;
    size_t stride = (size_t)gridDim.x * blockDim.x;
    for (; i < n4; i += stride) {
        float4 v = reinterpret_cast<const float4*>(in)[i];
        __half2 a = __halves2half2(__float2half_rn(v.x), __float2half_rn(v.y));
        __half2 b = __halves2half2(__float2half_rn(v.z), __float2half_rn(v.w));
        reinterpret_cast<__half2*>(out)[i*2]   = a;
        reinterpret_cast<__half2*>(out)[i*2+1] = b;
    }
}

// ---------------- transpose: W[K][N] fp32 -> Wt [N][K] fp16 ----------------
__global__ __launch_bounds__(256) void transpose_h_kernel(
    const float* __restrict__ W, __half* __restrict__ T, int Kdim, int Ndim)
{
    __shared__ float tile[32][33];
    int n0 = blockIdx.x * 32;
    int k0 = blockIdx.y * 32;
    int tx = threadIdx.x & 31;
    int ty = threadIdx.x >> 5;
#pragma unroll
    for (int r = 0; r < 4; r++)
        tile[ty + 8*r][tx] = W[(size_t)(k0 + ty + 8*r) * Ndim + n0 + tx];
    __syncthreads();
#pragma unroll
    for (int r = 0; r < 4; r++) {
        float v = tile[tx][ty + 8*r];
        T[(size_t)(n0 + ty + 8*r) * Kdim + k0 + tx] = __float2half_rn(v);
    }
}

// ---------------- 1-term fp16 GEMM: C = A(fp16) @ B(fp16)^T ----------------
#define GBK 32
#define NCHUNK (IDIM / GBK)            // 64
#define RS 80                          // smem row stride bytes
#define MAT_BYTES (128 * RS)           // 10240
#define MAT2_STAGE (2 * MAT_BYTES)     // 20480
#define GEMM1_SMEM (2 * MAT2_STAGE)    // 40960

__global__ __launch_bounds__(256) void mma_gemmh(
    const __half* __restrict__ A, const __half* __restrict__ B,
    float* __restrict__ C, int N)
{
    extern __shared__ char smem[];
    const uint32_t sb = smem_to_u32(smem);

    const int tid  = threadIdx.x;
    const int lane = tid & 31;
    const int wid  = tid >> 5;
    const int wm   = wid & 1;
    const int wn   = wid >> 1;
    const int m0   = blockIdx.y * 128;
    const int n0   = blockIdx.x * 128;

    auto issue_loads = [&](int chunk) {
        const int stage = chunk & 1;
        const uint32_t s0 = sb + stage * MAT2_STAGE;
#pragma unroll
        for (int j = 0; j < 4; j++) {
            int idx = tid + 256 * j;          // 0..1023
            int mat = idx >> 9;               // 0=A,1=B
            int wi  = idx & 511;
            int row = wi >> 2;
            int c   = wi & 3;
            const __half* gp = (mat == 0) ? A + (size_t)(m0 + row) * IDIM
                                          : B + (size_t)(n0 + row) * IDIM;
            cp_async16(s0 + mat * MAT_BYTES + row * RS + c * 16,
                       gp + chunk * GBK + c * 8);
        }
    };

    float acc[4][4][4];
#pragma unroll
    for (int mi = 0; mi < 4; mi++)
#pragma unroll
        for (int ni = 0; ni < 4; ni++)
#pragma unroll
            for (int r = 0; r < 4; r++) acc[mi][ni][r] = 0.0f;

    const uint32_t a_row = wm * 64 + (lane & 15);
    const uint32_t b_row = wn * 32 + (lane & 15);
    const uint32_t colb  = (lane >> 4) * 16;

    issue_loads(0); CP_COMMIT();

    for (int i = 0; i < NCHUNK; i++) {
        const int stage = i & 1;
        if (i + 1 < NCHUNK) { issue_loads(i + 1); CP_COMMIT(); CP_WAIT1(); }
        else                { CP_WAIT0(); }
        __syncthreads();

        const uint32_t sA = sb + stage * MAT2_STAGE;
        const uint32_t sB = sA + MAT_BYTES;

#pragma unroll
        for (int ks = 0; ks < 2; ks++) {
            const uint32_t kb = ks * 32 + colb;
            uint32_t a[4][4], b[2][4];
#pragma unroll
            for (int mi = 0; mi < 4; mi++)
                ldsm_x4(a[mi], sA + (a_row + mi * 16) * RS + kb);
#pragma unroll
            for (int nt = 0; nt < 2; nt++)
                ldsm_x4(b[nt], sB + (b_row + nt * 16) * RS + kb);
#pragma unroll
            for (int mi = 0; mi < 4; mi++) {
#pragma unroll
                for (int ni = 0; ni < 4; ni++) {
                    const int nt = ni >> 1, sub = ni & 1;
                    mma16816h(acc[mi][ni], a[mi], b[nt][sub], b[nt][2 + sub]);
                }
            }
        }
        __syncthreads();
    }

    const int er = lane >> 2;
    const int ec = (lane & 3) * 2;
#pragma unroll
    for (int mi = 0; mi < 4; mi++) {
#pragma unroll
        for (int ni = 0; ni < 4; ni++) {
            int row = m0 + wm * 64 + mi * 16 + er;
            int col = n0 + wn * 32 + ni * 8 + ec;
            *reinterpret_cast<float2*>(&C[(size_t)row * N + col]) =
                make_float2(acc[mi][ni][0], acc[mi][ni][1]);
            *reinterpret_cast<float2*>(&C[(size_t)(row + 8) * N + col]) =
                make_float2(acc[mi][ni][2], acc[mi][ni][3]);
        }
    }
}

// ---------------- RMSNorm + RoPE for Q -> single fp16 (pre-scaled) + gate fp16 ----------------
__global__ __launch_bounds__(256) void qnorm_rope_kernel(
    const float* __restrict__ cosb, const float* __restrict__ sinb,
    const float* __restrict__ gamma)
{
    const int l = blockIdx.x;
    const int h = blockIdx.y;
    const int d = threadIdx.x;
    const float* row = g_qraw + (size_t)l * (ODIM * 2) + h * 512;
    float v  = row[d];
    float gv = row[256 + d];

    float s = v * v;
#pragma unroll
    for (int o = 16; o > 0; o >>= 1) s += __shfl_xor_sync(0xffffffffu, s, o);
    __shared__ float wsum[8];
    __shared__ float sh[256];
    if ((d & 31) == 0) wsum[d >> 5] = s;
    __syncthreads();
    float tot = 0.0f;
#pragma unroll
    for (int w = 0; w < 8; w++) tot += wsum[w];
    float rstd = rsqrtf(tot * (1.0f / 256.0f) + 1e-6f);
    float y = v * rstd * gamma[d];
    sh[d] = y;
    __syncthreads();
    float out = y;
    if (d < ROPED) {
        float rot = (d < ROPED / 2) ? -sh[d + ROPED / 2] : sh[d - ROPED / 2];
        out = y * cosb[(size_t)l * ROPED + d] + rot * sinb[(size_t)l * ROPED + d];
    }
    size_t o = (size_t)l * ODIM + h * HDIM + d;
    g_q16[o]    = __float2half_rn(out * QSCALE);
    g_gate16[o] = __float2half_rn(gv);
}

// ---------------- RMSNorm + RoPE for K + V -> single fp16 ----------------
__global__ __launch_bounds__(256) void knorm_rope_v_kernel(
    const float* __restrict__ cosb, const float* __restrict__ sinb,
    const float* __restrict__ gamma)
{
    const int l = blockIdx.x;
    const int g = blockIdx.y;
    const int d = threadIdx.x;
    float v  = g_kvraw[(size_t)l * 1024 + g * HDIM + d];
    float vv = g_kvraw[(size_t)l * 1024 + 512 + g * HDIM + d];

    float s = v * v;
#pragma unroll
    for (int o = 16; o > 0; o >>= 1) s += __shfl_xor_sync(0xffffffffu, s, o);
    __shared__ float wsum[8];
    __shared__ float sh[256];
    if ((d & 31) == 0) wsum[d >> 5] = s;
    __syncthreads();
    float tot = 0.0f;
#pragma unroll
    for (int w = 0; w < 8; w++) tot += wsum[w];
    float rstd = rsqrtf(tot * (1.0f / 256.0f) + 1e-6f);
    float y = v * rstd * gamma[d];
    sh[d] = y;
    __syncthreads();
    float out = y;
    if (d < ROPED) {
        float rot = (d < ROPED / 2) ? -sh[d + ROPED / 2] : sh[d - ROPED / 2];
        out = y * cosb[(size_t)l * ROPED + d] + rot * sinb[(size_t)l * ROPED + d];
    }
    size_t o = (size_t)l * NKV + g * HDIM + d;
    g_k16[o] = __float2half_rn(out);
    g_v16[o] = __float2half_rn(vv);
}

// ---------------- MMA flash attention (single fp16), BR=BC=64, D=256 ----------------
// Register-resident softmax fused into the S epilogue; P written as fp16
// directly with the sw128 granule pattern. smem ~105.8KB -> 2 CTAs/SM.
#define AQ   0
#define AK   32768
#define AV   65536
#define AP   98304                  // 64 x 128B (fp16 P, swizzled)
#define APM  (AP + 8192)            // partial max: 2 x 64 floats
#define APS  (APM + 512)            // partial sum: 2 x 64 floats
#define AMR  (APS + 512)
#define ALR  (AMR + 256)
#define ACR  (ALR + 256)
#define ATT_SMEM (ACR + 256)        // 108288

__device__ __forceinline__ uint32_t sw512(int row, int g) {
    return (uint32_t)(row * 512 + ((g ^ (row & 7)) << 4));
}
__device__ __forceinline__ uint32_t sw128(int row, int g) {
    return (uint32_t)(row * 128 + ((g ^ (row & 7)) << 4));
}

__global__ __launch_bounds__(256, 2) void attn_mma_kernel()
{
    extern __shared__ char sm[];
    const uint32_t sb = smem_to_u32(sm);
    const int tid  = threadIdx.x;
    const int lane = tid & 31;
    const int wid  = tid >> 5;
    const int qt   = gridDim.x - 1 - blockIdx.x;   // big tiles first
    const int h    = blockIdx.y;
    const int g    = h >> 2;
    const int i0   = qt * 64;

    float* pmax = reinterpret_cast<float*>(sm + APM);
    float* psum = reinterpret_cast<float*>(sm + APS);
    float* mrow = reinterpret_cast<float*>(sm + AMR);
    float* lrow = reinterpret_cast<float*>(sm + ALR);
    float* crow = reinterpret_cast<float*>(sm + ACR);

    auto load_k = [&](int j0) {
        const size_t rbase = ((size_t)j0 * NGROUPS + g) * HDIM;
        const size_t rstr  = (size_t)NGROUPS * HDIM;
#pragma unroll
        for (int i = 0; i < 8; i++) {
            int idx = tid + 256 * i;
            int row = idx >> 5, gr = idx & 31;
            cp_async16(sb + AK + sw512(row, gr),
                       (const char*)g_k16 + (rbase + (size_t)row * rstr) * 2 + gr * 16);
        }
    };
    auto load_v = [&](int j0) {
        const size_t rbase = ((size_t)j0 * NGROUPS + g) * HDIM;
        const size_t rstr  = (size_t)NGROUPS * HDIM;
#pragma unroll
        for (int i = 0; i < 8; i++) {
            int idx = tid + 256 * i;
            int row = idx >> 5, gr = idx & 31;
            cp_async16(sb + AV + sw512(row, gr),
                       (const char*)g_v16 + (rbase + (size_t)row * rstr) * 2 + gr * 16);
        }
    };

    // ---- prolog: Q, K(0), V(0) ----
    {
        const char* q16 = (const char*)(g_q16 + ((size_t)i0 * NHEADS + h) * HDIM);
        const size_t rstr = (size_t)NHEADS * HDIM * 2;
#pragma unroll
        for (int i = 0; i < 8; i++) {
            int idx = tid + 256 * i;
            int row = idx >> 5, gr = idx & 31;
            cp_async16(sb + AQ + sw512(row, gr), q16 + (size_t)row * rstr + gr * 16);
        }
    }
    CP_COMMIT();
    load_k(0); CP_COMMIT();
    if (tid < 64) { mrow[tid] = -INFINITY; lrow[tid] = 0.0f; }
    load_v(0); CP_COMMIT();

    const int wm = wid & 3;
    const int wn = wid >> 2;
    const int er = lane >> 2;
    const int ec = (lane & 3) * 2;
    const int kgl = lane >> 4;

    float oacc[16][4];
#pragma unroll
    for (int t = 0; t < 16; t++)
#pragma unroll
        for (int r = 0; r < 4; r++) oacc[t][r] = 0.0f;

    for (int j0 = 0; j0 <= i0; j0 += 64) {
        CP_WAIT1();                // Q (+K) ready
        __syncthreads();

        // ---- S = Q K^T ----
        float sacc[4][4];
#pragma unroll
        for (int t = 0; t < 4; t++)
#pragma unroll
            for (int r = 0; r < 4; r++) sacc[t][r] = 0.0f;

        const int arow  = wm * 16 + (lane & 15);
        const int brow0 = wn * 32 + (lane & 15);
#pragma unroll 4
        for (int ks = 0; ks < 16; ks++) {
            int kg = ks * 2 + kgl;
            uint32_t a[4], b[2][4];
            ldsm_x4(a, sb + AQ + sw512(arow, kg));
            ldsm_x4(b[0], sb + AK + sw512(brow0, kg));
            ldsm_x4(b[1], sb + AK + sw512(brow0 + 16, kg));
#pragma unroll
            for (int nt = 0; nt < 2; nt++)
#pragma unroll
                for (int sub = 0; sub < 2; sub++)
                    mma16816h(sacc[nt * 2 + sub], a, b[nt][sub], b[nt][2 + sub]);
        }

        // ---- fused softmax (register-resident) ----
        const int r0 = wm * 16 + er;
        const int r1 = r0 + 8;
        {
            const int lim0 = i0 + r0 - j0;       // max allowed col
            const int lim1 = lim0 + 8;
            float m0 = -INFINITY, m1 = -INFINITY;
#pragma unroll
            for (int t = 0; t < 4; t++) {
                int col = wn * 32 + (t >> 1) * 16 + (t & 1) * 8 + ec;
                if (col > lim0)     sacc[t][0] = -INFINITY;
                if (col + 1 > lim0) sacc[t][1] = -INFINITY;
                if (col > lim1)     sacc[t][2] = -INFINITY;
                if (col + 1 > lim1) sacc[t][3] = -INFINITY;
                m0 = fmaxf(m0, fmaxf(sacc[t][0], sacc[t][1]));
                m1 = fmaxf(m1, fmaxf(sacc[t][2], sacc[t][3]));
            }
            m0 = fmaxf(m0, __shfl_xor_sync(0xffffffffu, m0, 1));
            m0 = fmaxf(m0, __shfl_xor_sync(0xffffffffu, m0, 2));
            m1 = fmaxf(m1, __shfl_xor_sync(0xffffffffu, m1, 1));
            m1 = fmaxf(m1, __shfl_xor_sync(0xffffffffu, m1, 2));
            if ((lane & 3) == 0) { pmax[wn * 64 + r0] = m0; pmax[wn * 64 + r1] = m1; }
            __syncthreads();

            float mn0 = fmaxf(fmaxf(pmax[r0], pmax[64 + r0]), mrow[r0]);
            float mn1 = fmaxf(fmaxf(pmax[r1], pmax[64 + r1]), mrow[r1]);
            float s0 = 0.0f, s1 = 0.0f;
            uint32_t pw0[4], pw1[4];
#pragma unroll
            for (int t = 0; t < 4; t++) {
                float p00 = __expf(sacc[t][0] - mn0);
                float p01 = __expf(sacc[t][1] - mn0);
                float p10 = __expf(sacc[t][2] - mn1);
                float p11 = __expf(sacc[t][3] - mn1);
                s0 += p00 + p01; s1 += p10 + p11;
                pw0[t] = pack_h2(__float2half_rn(p00), __float2half_rn(p01));
                pw1[t] = pack_h2(__float2half_rn(p10), __float2half_rn(p11));
            }
            s0 += __shfl_xor_sync(0xffffffffu, s0, 1);
            s0 += __shfl_xor_sync(0xffffffffu, s0, 2);
            s1 += __shfl_xor_sync(0xffffffffu, s1, 1);
            s1 += __shfl_xor_sync(0xffffffffu, s1, 2);
#pragma unroll
            for (int t = 0; t < 4; t++) {
                int gidx = wn * 4 + (t >> 1) * 2 + (t & 1);
                *reinterpret_cast<uint32_t*>(sm + AP + sw128(r0, gidx) + (lane & 3) * 4) = pw0[t];
                *reinterpret_cast<uint32_t*>(sm + AP + sw128(r1, gidx) + (lane & 3) * 4) = pw1[t];
            }
            if ((lane & 3) == 0) { psum[wn * 64 + r0] = s0; psum[wn * 64 + r1] = s1; }
            __syncthreads();

            if (tid < 64) {
                float mold = mrow[tid];
                float mnew = fmaxf(fmaxf(pmax[tid], pmax[64 + tid]), mold);
                float corr = __expf(mold - mnew);
                lrow[tid] = lrow[tid] * corr + psum[tid] + psum[64 + tid];
                mrow[tid] = mnew;
                crow[tid] = corr;
            }
        }

        if (j0 + 64 <= i0) load_k(j0 + 64);
        CP_COMMIT();
        CP_WAIT1();               // V(j0) ready
        __syncthreads();          // also publishes crow/lrow updates

        // ---- rescale O, then O += P V ----
        {
            float c0 = crow[r0];
            float c1 = crow[r1];
#pragma unroll
            for (int t = 0; t < 16; t++) {
                oacc[t][0] *= c0; oacc[t][1] *= c0;
                oacc[t][2] *= c1; oacc[t][3] *= c1;
            }
        }
        const int prow = wm * 16 + (lane & 15);
        const int vk   = lane & 15;
        const int vng  = lane >> 4;
#pragma unroll
        for (int ks = 0; ks < 4; ks++) {
            uint32_t a[4];
            ldsm_x4(a, sb + AP + sw128(prow, ks * 2 + kgl));
            int krow = ks * 16 + vk;
#pragma unroll
            for (int ng = 0; ng < 8; ng++) {
                uint32_t vv[4];
                int gv = wn * 16 + ng * 2 + vng;
                ldsm_x4_trans(vv, sb + AV + sw512(krow, gv));
#pragma unroll
                for (int sub = 0; sub < 2; sub++)
                    mma16816h(oacc[ng * 2 + sub], a, vv[2 * sub], vv[2 * sub + 1]);
            }
        }
        __syncthreads();          // V buffer dead

        if (j0 + 64 <= i0) load_v(j0 + 64);
        CP_COMMIT();
    }

    // ---- epilogue: 1/l, sigmoid gate (fp16), write single fp16 y ----
    {
        const int r0 = wm * 16 + er;
        const float li0 = 1.0f / lrow[r0];
        const float li1 = 1.0f / lrow[r0 + 8];
        const size_t base0 = (size_t)(i0 + r0) * ODIM + h * HDIM;
        const size_t base1 = (size_t)(i0 + r0 + 8) * ODIM + h * HDIM;
#pragma unroll
        for (int t = 0; t < 16; t++) {
            int col = wn * 128 + (t >> 1) * 16 + (t & 1) * 8 + ec;
            __half2 gh0 = *reinterpret_cast<const __half2*>(&g_gate16[base0 + col]);
            __half2 gh1 = *reinterpret_cast<const __half2*>(&g_gate16[base1 + col]);
            float2 gt0 = __half22float2(gh0);
            float2 gt1 = __half22float2(gh1);
            float v00 = oacc[t][0] * li0 * (1.0f / (1.0f + __expf(-gt0.x)));
            float v01 = oacc[t][1] * li0 * (1.0f / (1.0f + __expf(-gt0.y)));
            float v10 = oacc[t][2] * li1 * (1.0f / (1.0f + __expf(-gt1.x)));
            float v11 = oacc[t][3] * li1 * (1.0f / (1.0f + __expf(-gt1.y)));
            *reinterpret_cast<__half2*>(&g_y[base0 + col]) =
                __halves2half2(__float2half_rn(v00), __float2half_rn(v01));
            *reinterpret_cast<__half2*>(&g_y[base1 + col]) =
                __halves2half2(__float2half_rn(v10), __float2half_rn(v11));
        }
    }
}

// ---------------- launch ----------------
extern "C" void kernel_launch(void* const* d_in, const int* in_sizes, int n_in,
                              void* d_out, int out_size)
{
    const float* x    = (const float*)d_in[0];
    const float* cosb = (const float*)d_in[1];
    const float* sinb = (const float*)d_in[2];
    const float* wq   = (const float*)d_in[4];
    const float* wk   = (const float*)d_in[5];
    const float* wv   = (const float*)d_in[6];
    const float* wo   = (const float*)d_in[7];
    const float* qg   = (const float*)d_in[8];
    const float* kg   = (const float*)d_in[9];
    float* out        = (float*)d_out;

    float *p_qraw, *p_kvraw;
    cudaGetSymbolAddress((void**)&p_qraw,  g_qraw);
    cudaGetSymbolAddress((void**)&p_kvraw, g_kvraw);

    __half *p_x16, *p_wq16, *p_wkv16, *p_wo16, *p_y;
    cudaGetSymbolAddress((void**)&p_x16,   g_x16);
    cudaGetSymbolAddress((void**)&p_wq16,  g_wq16);
    cudaGetSymbolAddress((void**)&p_wkv16, g_wkv16);
    cudaGetSymbolAddress((void**)&p_wo16,  g_wo16);
    cudaGetSymbolAddress((void**)&p_y,     g_y);

    cudaFuncSetAttribute(mma_gemmh, cudaFuncAttributeMaxDynamicSharedMemorySize, GEMM1_SMEM);
    cudaFuncSetAttribute(attn_mma_kernel, cudaFuncAttributeMaxDynamicSharedMemorySize, ATT_SMEM);

    // 0) operand prep (all fp16, 1-term)
    cast_h_kernel<<<1024, 256>>>(x, p_x16, (size_t)L_SEQ * IDIM / 4);
    transpose_h_kernel<<<dim3((ODIM*2)/32, IDIM/32), 256>>>(wq, p_wq16, IDIM, ODIM*2);
    transpose_h_kernel<<<dim3(NKV/32, IDIM/32), 256>>>(wk, p_wkv16, IDIM, NKV);
    transpose_h_kernel<<<dim3(NKV/32, IDIM/32), 256>>>(
        wv, p_wkv16 + (size_t)512 * IDIM, IDIM, NKV);
    transpose_h_kernel<<<dim3(IDIM/32, ODIM/32), 256>>>(wo, p_wo16, ODIM, IDIM);

    // 1) projections: Q (N=4096) and fused KV (N=1024), 1-term fp16
    mma_gemmh<<<dim3((ODIM*2)/128, L_SEQ/128), 256, GEMM1_SMEM>>>(p_x16, p_wq16, p_qraw, ODIM*2);
    mma_gemmh<<<dim3(1024/128,     L_SEQ/128), 256, GEMM1_SMEM>>>(p_x16, p_wkv16, p_kvraw, 1024);

    // 2) norms + RoPE -> single fp16
    qnorm_rope_kernel<<<dim3(L_SEQ, NHEADS),  256>>>(cosb, sinb, qg);
    knorm_rope_v_kernel<<<dim3(L_SEQ, NGROUPS), 256>>>(cosb, sinb, kg);

    // 3) MMA flash attention (fused register softmax, 2 CTAs/SM) -> fp16 y
    attn_mma_kernel<<<dim3(L_SEQ / 64, NHEADS), 256, ATT_SMEM>>>();

    // 4) output projection: 1-term fp16
    mma_gemmh<<<dim3(IDIM/128, L_SEQ/128), 256, GEMM1_SMEM>>>(p_y, p_wo16, out, IDIM);
}